// round 1
// baseline (speedup 1.0000x reference)
#include <cuda_runtime.h>
#include <cuda_bf16.h>
#include <cstdint>

// Problem constants
#define Bb 8
#define Tt 1024
#define Cc 2048
#define Hh 32
#define Nn 64
#define BT (Bb*Tt)                 // 8192
#define BTC ((size_t)BT*Cc)        // 16,777,216
#define D_DECAY 96
#define D_AAA 96
#define D_MV 64
#define D_GATE 128
#define LN_EPS (1e-5f*64.0f)

// ------------------------- scratch (device globals, no allocation) ----------
__device__ float g_xr[BTC], g_xw[BTC], g_xk[BTC], g_xv[BTC], g_xa[BTC], g_xg[BTC];
__device__ float g_r[BTC], g_k[BTC], g_v[BTC];
__device__ float g_wdec[BTC], g_asig[BTC], g_g[BTC], g_kk[BTC], g_y[BTC];
__device__ float g_t2[BTC];
__device__ float g_tsmall[(size_t)BT*128];

// ------------------------- prep: mask + time-shift mix ----------------------
__global__ void prep_kernel(const float* __restrict__ x, const float* __restrict__ mask,
                            const float* __restrict__ mr, const float* __restrict__ mw,
                            const float* __restrict__ mk, const float* __restrict__ mv,
                            const float* __restrict__ ma, const float* __restrict__ mg)
{
    size_t idx = (size_t)blockIdx.x * blockDim.x + threadIdx.x;
    if (idx >= BTC) return;
    int c = (int)(idx % Cc);
    size_t bt = idx / Cc;
    int t = (int)(bt % Tt);
    float m  = mask[bt];
    float xm = x[idx] * m;
    float xprev = 0.f;
    if (t > 0) xprev = x[idx - Cc] * mask[bt - 1];
    float xx = xprev - xm;
    g_xr[idx] = xm + xx * mr[c];
    g_xw[idx] = xm + xx * mw[c];
    g_xk[idx] = xm + xx * mk[c];
    g_xv[idx] = xm + xx * mv[c];
    g_xa[idx] = xm + xx * ma[c];
    g_xg[idx] = xm + xx * mg[c];
}

// ------------------------- SGEMM ---------------------------------------------
// TB=true : C[m,n] = sum_k A[m,k] * B[n,k]   (B row-major [Nc,K])
// TB=false: C[m,n] = sum_k A[m,k] * B[k,n]   (B row-major [K,Nc])
// ACT: 0=none, 1=tanh, 2=sigmoid (applied to output)
#define GBM 128
#define GBN 128
#define GBK 16
template<int ACT, bool TB>
__global__ __launch_bounds__(256)
void sgemm_kernel(const float* __restrict__ A, const float* __restrict__ B,
                  float* __restrict__ C, int M, int Nc, int K)
{
    __shared__ float As[GBK][GBM];
    __shared__ float Bs[GBK][GBN];
    int tid = threadIdx.x;
    int m0 = blockIdx.y * GBM;
    int n0 = blockIdx.x * GBN;
    int tx = tid & 15;     // 0..15 -> n
    int ty = tid >> 4;     // 0..15 -> m
    float acc[8][8];
#pragma unroll
    for (int i = 0; i < 8; i++)
#pragma unroll
        for (int j = 0; j < 8; j++) acc[i][j] = 0.f;

    for (int k0 = 0; k0 < K; k0 += GBK) {
        // A tile: 128 rows x 16 k -> float4 along k
#pragma unroll
        for (int l = 0; l < 2; l++) {
            int t = tid + l * 256;
            int row = t >> 2;
            int kq = (t & 3) * 4;
            float4 va = *reinterpret_cast<const float4*>(&A[(size_t)(m0 + row) * K + k0 + kq]);
            As[kq + 0][row] = va.x; As[kq + 1][row] = va.y;
            As[kq + 2][row] = va.z; As[kq + 3][row] = va.w;
        }
        if (TB) {
#pragma unroll
            for (int l = 0; l < 2; l++) {
                int t = tid + l * 256;
                int row = t >> 2;
                int kq = (t & 3) * 4;
                float4 vb = make_float4(0.f, 0.f, 0.f, 0.f);
                if (n0 + row < Nc)
                    vb = *reinterpret_cast<const float4*>(&B[(size_t)(n0 + row) * K + k0 + kq]);
                Bs[kq + 0][row] = vb.x; Bs[kq + 1][row] = vb.y;
                Bs[kq + 2][row] = vb.z; Bs[kq + 3][row] = vb.w;
            }
        } else {
#pragma unroll
            for (int l = 0; l < 2; l++) {
                int t = tid + l * 256;
                int kr = t >> 5;          // 0..15
                int nc = (t & 31) * 4;    // 0..124
                float4 vb = make_float4(0.f, 0.f, 0.f, 0.f);
                if (n0 + nc < Nc)
                    vb = *reinterpret_cast<const float4*>(&B[(size_t)(k0 + kr) * Nc + n0 + nc]);
                Bs[kr][nc + 0] = vb.x; Bs[kr][nc + 1] = vb.y;
                Bs[kr][nc + 2] = vb.z; Bs[kr][nc + 3] = vb.w;
            }
        }
        __syncthreads();
#pragma unroll
        for (int kk2 = 0; kk2 < GBK; kk2++) {
            float ra[8], rb[8];
#pragma unroll
            for (int i = 0; i < 8; i++) ra[i] = As[kk2][ty * 8 + i];
#pragma unroll
            for (int i = 0; i < 8; i++) rb[i] = Bs[kk2][tx * 8 + i];
#pragma unroll
            for (int i = 0; i < 8; i++)
#pragma unroll
                for (int j = 0; j < 8; j++) acc[i][j] += ra[i] * rb[j];
        }
        __syncthreads();
    }
#pragma unroll
    for (int i = 0; i < 8; i++) {
        int m = m0 + ty * 8 + i;
#pragma unroll
        for (int j = 0; j < 8; j++) {
            int n = n0 + tx * 8 + j;
            if (n < Nc) {
                float v = acc[i][j];
                if (ACT == 1) v = tanhf(v);
                else if (ACT == 2) v = 1.f / (1.f + expf(-v));
                C[(size_t)m * Nc + n] = v;
            }
        }
    }
}

// ------------------------- elementwise fixups -------------------------------
__global__ void wdec_kernel(const float* __restrict__ w0, const float* __restrict__ t2,
                            float* __restrict__ wdec)
{
    size_t idx = (size_t)blockIdx.x * blockDim.x + threadIdx.x;
    if (idx >= BTC) return;
    int c = (int)(idx % Cc);
    float z = w0[c] + t2[idx];
    // softplus(-z), numerically stable
    float nz = -z;
    float sp = (nz > 20.f) ? nz : log1pf(expf(nz));
    float w = -sp - 0.5f;
    wdec[idx] = expf(-expf(w));
}

__global__ void asig_kernel(const float* __restrict__ a0, const float* __restrict__ t2,
                            float* __restrict__ asig)
{
    size_t idx = (size_t)blockIdx.x * blockDim.x + threadIdx.x;
    if (idx >= BTC) return;
    int c = (int)(idx % Cc);
    float z = a0[c] + t2[idx];
    asig[idx] = 1.f / (1.f + expf(-z));
}

__global__ void vupd_kernel(const float* __restrict__ v0, const float* __restrict__ t2,
                            const float* __restrict__ v_first, const float* __restrict__ mask,
                            float* __restrict__ v)
{
    size_t idx = (size_t)blockIdx.x * blockDim.x + threadIdx.x;
    if (idx >= BTC) return;
    int c = (int)(idx % Cc);
    size_t bt = idx / Cc;
    float z = v0[c] + t2[idx];
    float s = 1.f / (1.f + expf(-z));
    float vv = v[idx];
    vv = vv + (v_first[idx] - vv) * s;
    v[idx] = vv * mask[bt];
}

// kk = normalize(k*k_k) per head; k <- k*(1+(a-1)*k_a). One warp per head-group.
__global__ void kk_kernel(const float* __restrict__ kkp, const float* __restrict__ kap,
                          const float* __restrict__ asig,
                          float* __restrict__ k, float* __restrict__ kk)
{
    int gid = blockIdx.x * 8 + (threadIdx.x >> 5);   // group id in [0, BT*H)
    int lane = threadIdx.x & 31;
    int h = gid % Hh;
    size_t bt = gid / Hh;
    size_t base = bt * Cc + (size_t)h * Nn;
    int c0 = h * Nn + lane, c1 = c0 + 32;
    float k0v = k[base + lane], k1v = k[base + lane + 32];
    float kk0 = k0v * kkp[c0], kk1 = k1v * kkp[c1];
    float ss = kk0 * kk0 + kk1 * kk1;
#pragma unroll
    for (int o = 16; o > 0; o >>= 1) ss += __shfl_xor_sync(0xffffffffu, ss, o);
    float nrm = sqrtf(ss);
    nrm = fmaxf(nrm, 1e-12f);
    float inv = 1.f / nrm;
    kk[base + lane]      = kk0 * inv;
    kk[base + lane + 32] = kk1 * inv;
    float a0v = asig[base + lane], a1v = asig[base + lane + 32];
    k[base + lane]      = k0v * (1.f + (a0v - 1.f) * kap[c0]);
    k[base + lane + 32] = k1v * (1.f + (a1v - 1.f) * kap[c1]);
}

// ------------------------- RWKV-7 scan --------------------------------------
// One block per (b,h). 64 threads; thread j owns state row S[j][0..63].
__global__ __launch_bounds__(64)
void scan_kernel(const float* __restrict__ r, const float* __restrict__ wdec,
                 const float* __restrict__ k, const float* __restrict__ v,
                 const float* __restrict__ kk, const float* __restrict__ asig,
                 float* __restrict__ y)
{
    int bh = blockIdx.x;
    int b = bh / Hh, h = bh % Hh;
    int j = threadIdx.x;
    __shared__ float sr[Nn], sw[Nn], sk[Nn], sa[Nn], sb[Nn];
    float S[Nn];
#pragma unroll
    for (int i = 0; i < Nn; i++) S[i] = 0.f;
    size_t base0 = ((size_t)b * Tt) * Cc + (size_t)h * Nn;
    for (int t = 0; t < Tt; t++) {
        size_t base = base0 + (size_t)t * Cc;
        float kkj = kk[base + j];
        sr[j] = r[base + j];
        sw[j] = wdec[base + j];
        sk[j] = k[base + j];
        sa[j] = -kkj;
        sb[j] = kkj * asig[base + j];
        float vj = v[base + j];
        __syncthreads();
        float sacc = 0.f;
#pragma unroll
        for (int i = 0; i < Nn; i++) sacc += S[i] * sa[i];
        float yj = 0.f;
#pragma unroll
        for (int i = 0; i < Nn; i++) {
            float s = S[i] * sw[i] + sacc * sb[i] + vj * sk[i];
            S[i] = s;
            yj += s * sr[i];
        }
        y[base + j] = yj;
        __syncthreads();
    }
}

// ------------------------- groupnorm + rk*v + gate --------------------------
__global__ void post_kernel(const float* __restrict__ y, const float* __restrict__ r,
                            const float* __restrict__ k, const float* __restrict__ v,
                            const float* __restrict__ g, const float* __restrict__ r_k,
                            const float* __restrict__ ln_w, const float* __restrict__ ln_b,
                            float* __restrict__ out)
{
    int gid = blockIdx.x * 8 + (threadIdx.x >> 5);
    int lane = threadIdx.x & 31;
    int h = gid % Hh;
    size_t bt = gid / Hh;
    size_t base = bt * Cc + (size_t)h * Nn;
    int c0 = h * Nn + lane, c1 = c0 + 32;
    float y0 = y[base + lane], y1 = y[base + lane + 32];
    float sum = y0 + y1;
#pragma unroll
    for (int o = 16; o > 0; o >>= 1) sum += __shfl_xor_sync(0xffffffffu, sum, o);
    float mean = sum * (1.f / 64.f);
    float d0 = y0 - mean, d1 = y1 - mean;
    float var = d0 * d0 + d1 * d1;
#pragma unroll
    for (int o = 16; o > 0; o >>= 1) var += __shfl_xor_sync(0xffffffffu, var, o);
    var *= (1.f / 64.f);
    float inv = rsqrtf(var + LN_EPS);
    float yn0 = d0 * inv * ln_w[c0] + ln_b[c0];
    float yn1 = d1 * inv * ln_w[c1] + ln_b[c1];
    float r0 = r[base + lane], r1 = r[base + lane + 32];
    float k0v = k[base + lane], k1v = k[base + lane + 32];
    float rk = r0 * k0v * r_k[c0] + r1 * k1v * r_k[c1];
#pragma unroll
    for (int o = 16; o > 0; o >>= 1) rk += __shfl_xor_sync(0xffffffffu, rk, o);
    float o0 = (yn0 + rk * v[base + lane]) * g[base + lane];
    float o1 = (yn1 + rk * v[base + lane + 32]) * g[base + lane + 32];
    out[base + lane] = o0;
    out[base + lane + 32] = o1;
}

// ------------------------- launch -------------------------------------------
extern "C" void kernel_launch(void* const* d_in, const int* in_sizes, int n_in,
                              void* d_out, int out_size)
{
    const float* x        = (const float*)d_in[0];
    const float* mask     = (const float*)d_in[1];
    const float* v_first  = (const float*)d_in[2];
    const float* x_r      = (const float*)d_in[3];
    const float* x_w      = (const float*)d_in[4];
    const float* x_k      = (const float*)d_in[5];
    const float* x_v      = (const float*)d_in[6];
    const float* x_a      = (const float*)d_in[7];
    const float* x_g      = (const float*)d_in[8];
    const float* w0       = (const float*)d_in[9];
    const float* w1       = (const float*)d_in[10];
    const float* w2       = (const float*)d_in[11];
    const float* a0       = (const float*)d_in[12];
    const float* a1       = (const float*)d_in[13];
    const float* a2       = (const float*)d_in[14];
    const float* v0       = (const float*)d_in[15];
    const float* v1       = (const float*)d_in[16];
    const float* v2       = (const float*)d_in[17];
    const float* g1       = (const float*)d_in[18];
    const float* g2       = (const float*)d_in[19];
    const float* k_k      = (const float*)d_in[20];
    const float* k_a      = (const float*)d_in[21];
    const float* r_k      = (const float*)d_in[22];
    const float* W_r      = (const float*)d_in[23];
    const float* W_k      = (const float*)d_in[24];
    const float* W_v      = (const float*)d_in[25];
    const float* W_o      = (const float*)d_in[26];
    const float* ln_w     = (const float*)d_in[27];
    const float* ln_b     = (const float*)d_in[28];
    float* out = (float*)d_out;

    float *xr, *xw, *xk, *xv, *xa, *xg, *rr, *kb, *vb, *wd, *as, *gg, *kkb, *yb, *t2, *ts;
    cudaGetSymbolAddress((void**)&xr,  g_xr);
    cudaGetSymbolAddress((void**)&xw,  g_xw);
    cudaGetSymbolAddress((void**)&xk,  g_xk);
    cudaGetSymbolAddress((void**)&xv,  g_xv);
    cudaGetSymbolAddress((void**)&xa,  g_xa);
    cudaGetSymbolAddress((void**)&xg,  g_xg);
    cudaGetSymbolAddress((void**)&rr,  g_r);
    cudaGetSymbolAddress((void**)&kb,  g_k);
    cudaGetSymbolAddress((void**)&vb,  g_v);
    cudaGetSymbolAddress((void**)&wd,  g_wdec);
    cudaGetSymbolAddress((void**)&as,  g_asig);
    cudaGetSymbolAddress((void**)&gg,  g_g);
    cudaGetSymbolAddress((void**)&kkb, g_kk);
    cudaGetSymbolAddress((void**)&yb,  g_y);
    cudaGetSymbolAddress((void**)&t2,  g_t2);
    cudaGetSymbolAddress((void**)&ts,  g_tsmall);

    int nEl = (int)((BTC + 255) / 256);
    prep_kernel<<<nEl, 256>>>(x, mask, x_r, x_w, x_k, x_v, x_a, x_g);

    dim3 gBig(Cc / GBN, BT / GBM);   // 16 x 64
    // big projections
    sgemm_kernel<0, true><<<gBig, 256>>>(xr, W_r, rr, BT, Cc, Cc);
    sgemm_kernel<0, true><<<gBig, 256>>>(xk, W_k, kb, BT, Cc, Cc);
    sgemm_kernel<0, true><<<gBig, 256>>>(xv, W_v, vb, BT, Cc, Cc);

    // w path: tanh(xw@w1)@w2
    sgemm_kernel<1, false><<<dim3(1, BT / GBM), 256>>>(xw, w1, ts, BT, D_DECAY, Cc);
    sgemm_kernel<0, false><<<gBig, 256>>>(ts, w2, t2, BT, Cc, D_DECAY);
    wdec_kernel<<<nEl, 256>>>(w0, t2, wd);

    // a path
    sgemm_kernel<0, false><<<dim3(1, BT / GBM), 256>>>(xa, a1, ts, BT, D_AAA, Cc);
    sgemm_kernel<0, false><<<gBig, 256>>>(ts, a2, t2, BT, Cc, D_AAA);
    asig_kernel<<<nEl, 256>>>(a0, t2, as);

    // v path
    sgemm_kernel<0, false><<<dim3(1, BT / GBM), 256>>>(xv, v1, ts, BT, D_MV, Cc);
    sgemm_kernel<0, false><<<gBig, 256>>>(ts, v2, t2, BT, Cc, D_MV);
    vupd_kernel<<<nEl, 256>>>(v0, t2, v_first, mask, vb);

    // g path
    sgemm_kernel<2, false><<<dim3(1, BT / GBM), 256>>>(xg, g1, ts, BT, D_GATE, Cc);
    sgemm_kernel<0, false><<<gBig, 256>>>(ts, g2, gg, BT, Cc, D_GATE);

    // kk normalize + k rescale
    kk_kernel<<<(BT * Hh) / 8, 256>>>(k_k, k_a, as, kb, kkb);

    // sequential scan
    scan_kernel<<<Bb * Hh, 64>>>(rr, wd, kb, vb, kkb, as, yb);

    // groupnorm + rk*v + gate -> t2
    post_kernel<<<(BT * Hh) / 8, 256>>>(yb, rr, kb, vb, gg, r_k, ln_w, ln_b, t2);

    // output projection
    sgemm_kernel<0, true><<<gBig, 256>>>(t2, W_o, out, BT, Cc, Cc);

    // second output: v_first passthrough
    if ((size_t)out_size >= 2 * BTC) {
        cudaMemcpyAsync(out + BTC, v_first, BTC * sizeof(float),
                        cudaMemcpyDeviceToDevice);
    }
}

// round 4
// speedup vs baseline: 2.4518x; 2.4518x over previous
#include <cuda_runtime.h>
#include <cuda_bf16.h>
#include <cstdint>

// ---------------- problem constants ----------------
#define Bb 8
#define Tt 1024
#define Cc 2048
#define Hh 32
#define Nn 64
#define BT (Bb*Tt)                  // 8192
#define BTC ((size_t)BT*Cc)         // 16.7M
#define D_DECAY 96
#define D_AAA 96
#define D_MV 64
#define D_GATE 128
#define LORA_PAD 128
#define LN_EPS (1e-5f*64.0f)

// ---------------- scratch (device globals) ----------------
__device__ float g_r[BTC], g_k[BTC], g_v[BTC];
__device__ float g_wdec[BTC], g_asig[BTC], g_g[BTC], g_kk[BTC], g_y[BTC], g_t2[BTC];

// bf16 split inputs for GEMMs
__device__ uint16_t g_xrh[BTC], g_xrl[BTC], g_xwh[BTC], g_xwl[BTC];
__device__ uint16_t g_xkh[BTC], g_xkl[BTC], g_xvh[BTC], g_xvl[BTC];
__device__ uint16_t g_xah[BTC], g_xal[BTC], g_xgh[BTC], g_xgl[BTC];
__device__ uint16_t g_ygh[BTC], g_ygl[BTC];
// big weights split
__device__ uint16_t g_Wrh[Cc*Cc], g_Wrl[Cc*Cc], g_Wkh[Cc*Cc], g_Wkl[Cc*Cc];
__device__ uint16_t g_Wvh[Cc*Cc], g_Wvl[Cc*Cc], g_Woh[Cc*Cc], g_Wol[Cc*Cc];
// LoRA weights (transposed + zero-padded to 128)
__device__ uint16_t g_w1h[LORA_PAD*Cc], g_w1l[LORA_PAD*Cc], g_w2h[Cc*LORA_PAD], g_w2l[Cc*LORA_PAD];
__device__ uint16_t g_a1h[LORA_PAD*Cc], g_a1l[LORA_PAD*Cc], g_a2h[Cc*LORA_PAD], g_a2l[Cc*LORA_PAD];
__device__ uint16_t g_v1h[LORA_PAD*Cc], g_v1l[LORA_PAD*Cc], g_v2h[Cc*LORA_PAD], g_v2l[Cc*LORA_PAD];
__device__ uint16_t g_g1h[LORA_PAD*Cc], g_g1l[LORA_PAD*Cc], g_g2h[Cc*LORA_PAD], g_g2l[Cc*LORA_PAD];
// LoRA stage-1 output (split, 128 cols)
__device__ uint16_t g_tsh[(size_t)BT*LORA_PAD], g_tsl[(size_t)BT*LORA_PAD];

// ---------------- helpers ----------------
__device__ __forceinline__ void split_store(float v, uint16_t* hi, uint16_t* lo, size_t i) {
    __nv_bfloat16 h = __float2bfloat16(v);
    float hf = __bfloat162float(h);
    __nv_bfloat16 l = __float2bfloat16(v - hf);
    reinterpret_cast<__nv_bfloat16*>(hi)[i] = h;
    reinterpret_cast<__nv_bfloat16*>(lo)[i] = l;
}

__device__ __forceinline__ uint32_t smem_u32(const void* p) {
    uint32_t a;
    asm("{ .reg .u64 t; cvta.to.shared.u64 t, %1; cvt.u32.u64 %0, t; }" : "=r"(a) : "l"(p));
    return a;
}
#define SWZ128(o) ((o) ^ (((o) >> 3) & 0x70))

__device__ __forceinline__ void cpa16(uint32_t daddr, const void* g)
{
    asm volatile("cp.async.cg.shared.global [%0], [%1], 16;"
                 :: "r"(daddr), "l"(__cvta_generic_to_global(g)) : "memory");
}

__device__ __forceinline__ void ldsm4(uint32_t& r0, uint32_t& r1, uint32_t& r2, uint32_t& r3,
                                      uint32_t addr)
{
    asm volatile("ldmatrix.sync.aligned.m8n8.x4.shared.b16 {%0,%1,%2,%3}, [%4];"
                 : "=r"(r0), "=r"(r1), "=r"(r2), "=r"(r3) : "r"(addr));
}

__device__ __forceinline__ void mma16816(float* c, const uint32_t* a, const uint32_t* b)
{
    asm volatile("mma.sync.aligned.m16n8k16.row.col.f32.bf16.bf16.f32 "
                 "{%0,%1,%2,%3}, {%4,%5,%6,%7}, {%8,%9}, {%0,%1,%2,%3};"
                 : "+f"(c[0]), "+f"(c[1]), "+f"(c[2]), "+f"(c[3])
                 : "r"(a[0]), "r"(a[1]), "r"(a[2]), "r"(a[3]), "r"(b[0]), "r"(b[1]));
}

template<int ACT> __device__ __forceinline__ float actf(float v) {
    if (ACT == 1) return tanhf(v);
    if (ACT == 2) return 1.f / (1.f + expf(-v));
    return v;
}

// ---------------- prep: mask + time-shift mixes -> split bf16 ----------------
__global__ void prep_kernel(const float* __restrict__ x, const float* __restrict__ mask,
                            const float* __restrict__ mr, const float* __restrict__ mw,
                            const float* __restrict__ mk, const float* __restrict__ mv,
                            const float* __restrict__ ma, const float* __restrict__ mg)
{
    size_t idx = (size_t)blockIdx.x * blockDim.x + threadIdx.x;
    if (idx >= BTC) return;
    int c = (int)(idx % Cc);
    size_t bt = idx / Cc;
    int t = (int)(bt % Tt);
    float m  = mask[bt];
    float xm = x[idx] * m;
    float xprev = 0.f;
    if (t > 0) xprev = x[idx - Cc] * mask[bt - 1];
    float xx = xprev - xm;
    split_store(xm + xx * mr[c], g_xrh, g_xrl, idx);
    split_store(xm + xx * mw[c], g_xwh, g_xwl, idx);
    split_store(xm + xx * mk[c], g_xkh, g_xkl, idx);
    split_store(xm + xx * mv[c], g_xvh, g_xvl, idx);
    split_store(xm + xx * ma[c], g_xah, g_xal, idx);
    split_store(xm + xx * mg[c], g_xgh, g_xgl, idx);
}

__global__ void split_kernel(const float* __restrict__ src, uint16_t* hi, uint16_t* lo, int n)
{
    int i = blockIdx.x * blockDim.x + threadIdx.x;
    if (i >= n) return;
    split_store(src[i], hi, lo, i);
}

// stage-1 LoRA weight: src [K=2048, D] -> dst [128, 2048] (row n, col k), zero-pad n>=D
__global__ void lora1_kernel(const float* __restrict__ src, uint16_t* hi, uint16_t* lo, int D)
{
    int i = blockIdx.x * blockDim.x + threadIdx.x;
    if (i >= LORA_PAD * Cc) return;
    int n = i / Cc, k = i % Cc;
    float v = (n < D) ? src[(size_t)k * D + n] : 0.f;
    split_store(v, hi, lo, i);
}

// stage-2 LoRA weight: src [D, 2048] -> dst [2048, 128] (row n, col k), zero-pad k>=D
__global__ void lora2_kernel(const float* __restrict__ src, uint16_t* hi, uint16_t* lo, int D)
{
    int i = blockIdx.x * blockDim.x + threadIdx.x;
    if (i >= Cc * LORA_PAD) return;
    int n = i / LORA_PAD, k = i % LORA_PAD;
    float v = (k < D) ? src[(size_t)k * Cc + n] : 0.f;
    split_store(v, hi, lo, i);
}

// ---------------- mma.sync GEMM (3-term bf16 split via virtual K) ----------------
// C[M,Nc] = sum_k A[m,k]*B[n,k] in ~fp32 precision.
// Virtual chunks: phase 0 = Ahi*Bhi, 1 = Ahi*Blo, 2 = Alo*Bhi.
// Tile 128x128, BK=64, 3-stage cp.async, 8 warps (4x2), warp tile 32x64 m16n8k16.
#define STAGES 3
#define ATILE_B 16384               // 128 rows x 128B
#define STAGE_B (2*ATILE_B)
#define GEMM_SMEM (STAGES*STAGE_B)  // 98304

template<int ACT, bool SPLIT>
__global__ __launch_bounds__(256, 2)
void mma_gemm(const uint16_t* __restrict__ Ahi, const uint16_t* __restrict__ Alo,
              const uint16_t* __restrict__ Bhi, const uint16_t* __restrict__ Blo,
              float* __restrict__ Cf, uint16_t* __restrict__ Chi, uint16_t* __restrict__ Clo,
              int Nc, int K, int ldo)
{
    extern __shared__ char smem[];
    const uint32_t sb = smem_u32(smem);
    const int tid = threadIdx.x;
    const int lane = tid & 31, warp = tid >> 5;
    const int warpM = warp >> 1, warpN = warp & 1;          // 4 x 2
    const int m0 = blockIdx.y * 128, n0 = blockIdx.x * 128;
    const int kc = K >> 6;
    const int nCh = 3 * kc;

    float acc[2][8][4];
#pragma unroll
    for (int mt = 0; mt < 2; mt++)
#pragma unroll
        for (int nt = 0; nt < 8; nt++)
#pragma unroll
            for (int e = 0; e < 4; e++) acc[mt][nt][e] = 0.f;

    auto load_chunk = [&](int c) {
        const int phase = (c >= 2 * kc) ? 2 : ((c >= kc) ? 1 : 0);
        const int k0 = (c - phase * kc) << 6;
        const uint16_t* sA = (phase == 2) ? Alo : Ahi;
        const uint16_t* sB = (phase == 1) ? Blo : Bhi;
        const uint32_t stb = sb + (uint32_t)(c % STAGES) * STAGE_B;
#pragma unroll
        for (int j = 0; j < 4; j++) {
            int T = tid + j * 256;
            int row = T >> 3, seg = T & 7;
            cpa16(stb + SWZ128(row * 128 + seg * 16),
                  sA + (size_t)(m0 + row) * K + k0 + seg * 8);
        }
#pragma unroll
        for (int j = 0; j < 4; j++) {
            int T = tid + j * 256;
            int row = T >> 3, seg = T & 7;
            cpa16(stb + ATILE_B + SWZ128(row * 128 + seg * 16),
                  sB + (size_t)(n0 + row) * K + k0 + seg * 8);
        }
    };

    // prologue: 2 chunks in flight
    load_chunk(0);
    asm volatile("cp.async.commit_group;" ::: "memory");
    load_chunk(1);
    asm volatile("cp.async.commit_group;" ::: "memory");

    for (int c = 0; c < nCh; c++) {
        asm volatile("cp.async.wait_group 1;" ::: "memory");
        __syncthreads();
        if (c + 2 < nCh) load_chunk(c + 2);
        asm volatile("cp.async.commit_group;" ::: "memory");

        const uint32_t sAa = sb + (uint32_t)(c % STAGES) * STAGE_B;
        const uint32_t sBb = sAa + ATILE_B;
#pragma unroll
        for (int s = 0; s < 4; s++) {
            uint32_t a[2][4];
#pragma unroll
            for (int mt = 0; mt < 2; mt++) {
                int row = warpM * 32 + mt * 16 + (lane & 15);
                int kb = s * 32 + ((lane >> 4) << 4);
                ldsm4(a[mt][0], a[mt][1], a[mt][2], a[mt][3], sAa + SWZ128(row * 128 + kb));
            }
            uint32_t b[8][2];
#pragma unroll
            for (int p = 0; p < 4; p++) {
                int nr = warpN * 64 + p * 16 + (lane & 7) + ((lane >> 1) & 8);
                int kb = s * 32 + ((lane >> 3) & 1) * 16;
                uint32_t r0, r1, r2, r3;
                ldsm4(r0, r1, r2, r3, sBb + SWZ128(nr * 128 + kb));
                b[p * 2][0] = r0;     b[p * 2][1] = r1;
                b[p * 2 + 1][0] = r2; b[p * 2 + 1][1] = r3;
            }
#pragma unroll
            for (int mt = 0; mt < 2; mt++)
#pragma unroll
                for (int nt = 0; nt < 8; nt++)
                    mma16816(acc[mt][nt], a[mt], b[nt]);
        }
    }

    // epilogue
    const int row0 = m0 + warpM * 32 + (lane >> 2);
    const int col0 = n0 + warpN * 64 + (lane & 3) * 2;
#pragma unroll
    for (int mt = 0; mt < 2; mt++) {
#pragma unroll
        for (int nt = 0; nt < 8; nt++) {
            int r1 = row0 + mt * 16;
            int c1 = col0 + nt * 8;
            float v0 = actf<ACT>(acc[mt][nt][0]);
            float v1 = actf<ACT>(acc[mt][nt][1]);
            float v2 = actf<ACT>(acc[mt][nt][2]);
            float v3 = actf<ACT>(acc[mt][nt][3]);
            if (SPLIT) {
                split_store(v0, Chi, Clo, (size_t)r1 * ldo + c1);
                split_store(v1, Chi, Clo, (size_t)r1 * ldo + c1 + 1);
                split_store(v2, Chi, Clo, (size_t)(r1 + 8) * ldo + c1);
                split_store(v3, Chi, Clo, (size_t)(r1 + 8) * ldo + c1 + 1);
            } else {
                *reinterpret_cast<float2*>(&Cf[(size_t)r1 * ldo + c1]) = make_float2(v0, v1);
                *reinterpret_cast<float2*>(&Cf[(size_t)(r1 + 8) * ldo + c1]) = make_float2(v2, v3);
            }
        }
    }
}

// ---------------- elementwise fixups ----------------
__global__ void wdec_kernel(const float* __restrict__ w0, const float* __restrict__ t2,
                            float* __restrict__ wdec)
{
    size_t idx = (size_t)blockIdx.x * blockDim.x + threadIdx.x;
    if (idx >= BTC) return;
    int c = (int)(idx % Cc);
    float z = w0[c] + t2[idx];
    float nz = -z;
    float sp = (nz > 20.f) ? nz : log1pf(expf(nz));
    float w = -sp - 0.5f;
    wdec[idx] = expf(-expf(w));
}

__global__ void asig_kernel(const float* __restrict__ a0, const float* __restrict__ t2,
                            float* __restrict__ asig)
{
    size_t idx = (size_t)blockIdx.x * blockDim.x + threadIdx.x;
    if (idx >= BTC) return;
    int c = (int)(idx % Cc);
    float z = a0[c] + t2[idx];
    asig[idx] = 1.f / (1.f + expf(-z));
}

__global__ void vupd_kernel(const float* __restrict__ v0, const float* __restrict__ t2,
                            const float* __restrict__ v_first, const float* __restrict__ mask,
                            float* __restrict__ v)
{
    size_t idx = (size_t)blockIdx.x * blockDim.x + threadIdx.x;
    if (idx >= BTC) return;
    int c = (int)(idx % Cc);
    size_t bt = idx / Cc;
    float z = v0[c] + t2[idx];
    float s = 1.f / (1.f + expf(-z));
    float vv = v[idx];
    vv = vv + (v_first[idx] - vv) * s;
    v[idx] = vv * mask[bt];
}

__global__ void kk_kernel(const float* __restrict__ kkp, const float* __restrict__ kap,
                          const float* __restrict__ asig,
                          float* __restrict__ k, float* __restrict__ kk)
{
    int gid = blockIdx.x * 8 + (threadIdx.x >> 5);
    int lane = threadIdx.x & 31;
    int h = gid % Hh;
    size_t bt = gid / Hh;
    size_t base = bt * Cc + (size_t)h * Nn;
    int c0 = h * Nn + lane, c1 = c0 + 32;
    float k0v = k[base + lane], k1v = k[base + lane + 32];
    float kk0 = k0v * kkp[c0], kk1 = k1v * kkp[c1];
    float ss = kk0 * kk0 + kk1 * kk1;
#pragma unroll
    for (int o = 16; o > 0; o >>= 1) ss += __shfl_xor_sync(0xffffffffu, ss, o);
    float inv = 1.f / fmaxf(sqrtf(ss), 1e-12f);
    kk[base + lane]      = kk0 * inv;
    kk[base + lane + 32] = kk1 * inv;
    float a0v = asig[base + lane], a1v = asig[base + lane + 32];
    k[base + lane]      = k0v * (1.f + (a0v - 1.f) * kap[c0]);
    k[base + lane + 32] = k1v * (1.f + (a1v - 1.f) * kap[c1]);
}

// ---------------- RWKV-7 scan ----------------
__global__ __launch_bounds__(64)
void scan_kernel(const float* __restrict__ r, const float* __restrict__ wdec,
                 const float* __restrict__ k, const float* __restrict__ v,
                 const float* __restrict__ kk, const float* __restrict__ asig,
                 float* __restrict__ y)
{
    int bh = blockIdx.x;
    int b = bh / Hh, h = bh % Hh;
    int j = threadIdx.x;
    __shared__ float4 bufQ[2][Nn];   // (w, b, k, r)
    __shared__ float  bufA[2][Nn];   // a = -kk
    float S[Nn];
#pragma unroll
    for (int i = 0; i < Nn; i++) S[i] = 0.f;
    size_t base0 = ((size_t)b * Tt) * Cc + (size_t)h * Nn;
    for (int t = 0; t < Tt; t++) {
        int pb = t & 1;
        size_t base = base0 + (size_t)t * Cc;
        float kkj = kk[base + j];
        bufQ[pb][j] = make_float4(wdec[base + j], kkj * asig[base + j], k[base + j], r[base + j]);
        bufA[pb][j] = -kkj;
        float vj = v[base + j];
        __syncthreads();
        float sacc = 0.f;
#pragma unroll
        for (int i = 0; i < Nn; i++) sacc += S[i] * bufA[pb][i];
        float yj = 0.f;
#pragma unroll
        for (int i = 0; i < Nn; i++) {
            float4 q = bufQ[pb][i];
            float s = fmaf(S[i], q.x, fmaf(sacc, q.y, vj * q.z));
            S[i] = s;
            yj = fmaf(s, q.w, yj);
        }
        y[base + j] = yj;
    }
}

// ---------------- groupnorm + rk*v + gate -> split bf16 ----------------
__global__ void post_kernel(const float* __restrict__ y, const float* __restrict__ r,
                            const float* __restrict__ k, const float* __restrict__ v,
                            const float* __restrict__ g, const float* __restrict__ r_k,
                            const float* __restrict__ ln_w, const float* __restrict__ ln_b,
                            uint16_t* __restrict__ oh, uint16_t* __restrict__ ol)
{
    int gid = blockIdx.x * 8 + (threadIdx.x >> 5);
    int lane = threadIdx.x & 31;
    int h = gid % Hh;
    size_t bt = gid / Hh;
    size_t base = bt * Cc + (size_t)h * Nn;
    int c0 = h * Nn + lane, c1 = c0 + 32;
    float y0 = y[base + lane], y1 = y[base + lane + 32];
    float sum = y0 + y1;
#pragma unroll
    for (int o = 16; o > 0; o >>= 1) sum += __shfl_xor_sync(0xffffffffu, sum, o);
    float mean = sum * (1.f / 64.f);
    float d0 = y0 - mean, d1 = y1 - mean;
    float var = d0 * d0 + d1 * d1;
#pragma unroll
    for (int o = 16; o > 0; o >>= 1) var += __shfl_xor_sync(0xffffffffu, var, o);
    var *= (1.f / 64.f);
    float inv = rsqrtf(var + LN_EPS);
    float yn0 = d0 * inv * ln_w[c0] + ln_b[c0];
    float yn1 = d1 * inv * ln_w[c1] + ln_b[c1];
    float rk = r[base + lane] * k[base + lane] * r_k[c0]
             + r[base + lane + 32] * k[base + lane + 32] * r_k[c1];
#pragma unroll
    for (int o = 16; o > 0; o >>= 1) rk += __shfl_xor_sync(0xffffffffu, rk, o);
    float o0 = (yn0 + rk * v[base + lane]) * g[base + lane];
    float o1 = (yn1 + rk * v[base + lane + 32]) * g[base + lane + 32];
    split_store(o0, oh, ol, base + lane);
    split_store(o1, oh, ol, base + lane + 32);
}

// ---------------- launch ----------------
#define GETSYM(var, sym) do { void* _p; cudaGetSymbolAddress(&_p, sym); var = (decltype(var))_p; } while (0)

extern "C" void kernel_launch(void* const* d_in, const int* in_sizes, int n_in,
                              void* d_out, int out_size)
{
    const float* x       = (const float*)d_in[0];
    const float* mask    = (const float*)d_in[1];
    const float* v_first = (const float*)d_in[2];
    const float* x_r = (const float*)d_in[3];
    const float* x_w = (const float*)d_in[4];
    const float* x_k = (const float*)d_in[5];
    const float* x_v = (const float*)d_in[6];
    const float* x_a = (const float*)d_in[7];
    const float* x_g = (const float*)d_in[8];
    const float* w0 = (const float*)d_in[9];
    const float* w1 = (const float*)d_in[10];
    const float* w2 = (const float*)d_in[11];
    const float* a0 = (const float*)d_in[12];
    const float* a1 = (const float*)d_in[13];
    const float* a2 = (const float*)d_in[14];
    const float* v0 = (const float*)d_in[15];
    const float* v1 = (const float*)d_in[16];
    const float* v2 = (const float*)d_in[17];
    const float* g1 = (const float*)d_in[18];
    const float* g2 = (const float*)d_in[19];
    const float* k_k = (const float*)d_in[20];
    const float* k_a = (const float*)d_in[21];
    const float* r_k = (const float*)d_in[22];
    const float* W_r = (const float*)d_in[23];
    const float* W_k = (const float*)d_in[24];
    const float* W_v = (const float*)d_in[25];
    const float* W_o = (const float*)d_in[26];
    const float* ln_w = (const float*)d_in[27];
    const float* ln_b = (const float*)d_in[28];
    float* out = (float*)d_out;

    float *rr, *kb, *vb, *wd, *as, *gg, *kkb, *yb, *t2;
    GETSYM(rr, g_r); GETSYM(kb, g_k); GETSYM(vb, g_v);
    GETSYM(wd, g_wdec); GETSYM(as, g_asig); GETSYM(gg, g_g);
    GETSYM(kkb, g_kk); GETSYM(yb, g_y); GETSYM(t2, g_t2);
    uint16_t *xrh,*xrl,*xwh,*xwl,*xkh,*xkl,*xvh,*xvl,*xah,*xal,*xgh,*xgl,*ygh,*ygl;
    GETSYM(xrh, g_xrh); GETSYM(xrl, g_xrl); GETSYM(xwh, g_xwh); GETSYM(xwl, g_xwl);
    GETSYM(xkh, g_xkh); GETSYM(xkl, g_xkl); GETSYM(xvh, g_xvh); GETSYM(xvl, g_xvl);
    GETSYM(xah, g_xah); GETSYM(xal, g_xal); GETSYM(xgh, g_xgh); GETSYM(xgl, g_xgl);
    GETSYM(ygh, g_ygh); GETSYM(ygl, g_ygl);
    uint16_t *Wrh,*Wrl,*Wkh,*Wkl,*Wvh,*Wvl,*Woh,*Wol;
    GETSYM(Wrh, g_Wrh); GETSYM(Wrl, g_Wrl); GETSYM(Wkh, g_Wkh); GETSYM(Wkl, g_Wkl);
    GETSYM(Wvh, g_Wvh); GETSYM(Wvl, g_Wvl); GETSYM(Woh, g_Woh); GETSYM(Wol, g_Wol);
    uint16_t *w1h,*w1l,*w2h,*w2l,*a1h,*a1l,*a2h,*a2l,*v1h,*v1l,*v2h,*v2l,*g1h,*g1l,*g2h,*g2l;
    GETSYM(w1h, g_w1h); GETSYM(w1l, g_w1l); GETSYM(w2h, g_w2h); GETSYM(w2l, g_w2l);
    GETSYM(a1h, g_a1h); GETSYM(a1l, g_a1l); GETSYM(a2h, g_a2h); GETSYM(a2l, g_a2l);
    GETSYM(v1h, g_v1h); GETSYM(v1l, g_v1l); GETSYM(v2h, g_v2h); GETSYM(v2l, g_v2l);
    GETSYM(g1h, g_g1h); GETSYM(g1l, g_g1l); GETSYM(g2h, g_g2h); GETSYM(g2l, g_g2l);
    uint16_t *tsh, *tsl;
    GETSYM(tsh, g_tsh); GETSYM(tsl, g_tsl);

    cudaFuncSetAttribute(mma_gemm<0,false>, cudaFuncAttributeMaxDynamicSharedMemorySize, GEMM_SMEM);
    cudaFuncSetAttribute(mma_gemm<0,true>,  cudaFuncAttributeMaxDynamicSharedMemorySize, GEMM_SMEM);
    cudaFuncSetAttribute(mma_gemm<1,true>,  cudaFuncAttributeMaxDynamicSharedMemorySize, GEMM_SMEM);
    cudaFuncSetAttribute(mma_gemm<2,true>,  cudaFuncAttributeMaxDynamicSharedMemorySize, GEMM_SMEM);

    const int nEl = (int)((BTC + 255) / 256);
    prep_kernel<<<nEl, 256>>>(x, mask, x_r, x_w, x_k, x_v, x_a, x_g);

    const int nW = Cc * Cc;
    split_kernel<<<(nW + 255) / 256, 256>>>(W_r, Wrh, Wrl, nW);
    split_kernel<<<(nW + 255) / 256, 256>>>(W_k, Wkh, Wkl, nW);
    split_kernel<<<(nW + 255) / 256, 256>>>(W_v, Wvh, Wvl, nW);
    split_kernel<<<(nW + 255) / 256, 256>>>(W_o, Woh, Wol, nW);
    const int nL = LORA_PAD * Cc;
    lora1_kernel<<<(nL + 255) / 256, 256>>>(w1, w1h, w1l, D_DECAY);
    lora2_kernel<<<(nL + 255) / 256, 256>>>(w2, w2h, w2l, D_DECAY);
    lora1_kernel<<<(nL + 255) / 256, 256>>>(a1, a1h, a1l, D_AAA);
    lora2_kernel<<<(nL + 255) / 256, 256>>>(a2, a2h, a2l, D_AAA);
    lora1_kernel<<<(nL + 255) / 256, 256>>>(v1, v1h, v1l, D_MV);
    lora2_kernel<<<(nL + 255) / 256, 256>>>(v2, v2h, v2l, D_MV);
    lora1_kernel<<<(nL + 255) / 256, 256>>>(g1, g1h, g1l, D_GATE);
    lora2_kernel<<<(nL + 255) / 256, 256>>>(g2, g2h, g2l, D_GATE);

    const dim3 gBig(Cc / 128, BT / 128);   // (16, 64)
    const dim3 gS1(1, BT / 128);           // (1, 64)

    // big projections: r, k, v
    mma_gemm<0,false><<<gBig, 256, GEMM_SMEM>>>(xrh, xrl, Wrh, Wrl, rr, nullptr, nullptr, Cc, Cc, Cc);
    mma_gemm<0,false><<<gBig, 256, GEMM_SMEM>>>(xkh, xkl, Wkh, Wkl, kb, nullptr, nullptr, Cc, Cc, Cc);
    mma_gemm<0,false><<<gBig, 256, GEMM_SMEM>>>(xvh, xvl, Wvh, Wvl, vb, nullptr, nullptr, Cc, Cc, Cc);

    // w path: tanh(xw@w1)@w2
    mma_gemm<1,true><<<gS1, 256, GEMM_SMEM>>>(xwh, xwl, w1h, w1l, nullptr, tsh, tsl, LORA_PAD, Cc, LORA_PAD);
    mma_gemm<0,false><<<gBig, 256, GEMM_SMEM>>>(tsh, tsl, w2h, w2l, t2, nullptr, nullptr, Cc, LORA_PAD, Cc);
    wdec_kernel<<<nEl, 256>>>(w0, t2, wd);

    // a path
    mma_gemm<0,true><<<gS1, 256, GEMM_SMEM>>>(xah, xal, a1h, a1l, nullptr, tsh, tsl, LORA_PAD, Cc, LORA_PAD);
    mma_gemm<0,false><<<gBig, 256, GEMM_SMEM>>>(tsh, tsl, a2h, a2l, t2, nullptr, nullptr, Cc, LORA_PAD, Cc);
    asig_kernel<<<nEl, 256>>>(a0, t2, as);

    // v path
    mma_gemm<0,true><<<gS1, 256, GEMM_SMEM>>>(xvh, xvl, v1h, v1l, nullptr, tsh, tsl, LORA_PAD, Cc, LORA_PAD);
    mma_gemm<0,false><<<gBig, 256, GEMM_SMEM>>>(tsh, tsl, v2h, v2l, t2, nullptr, nullptr, Cc, LORA_PAD, Cc);
    vupd_kernel<<<nEl, 256>>>(v0, t2, v_first, mask, vb);

    // g path: sigmoid(xg@g1)@g2
    mma_gemm<2,true><<<gS1, 256, GEMM_SMEM>>>(xgh, xgl, g1h, g1l, nullptr, tsh, tsl, LORA_PAD, Cc, LORA_PAD);
    mma_gemm<0,false><<<gBig, 256, GEMM_SMEM>>>(tsh, tsl, g2h, g2l, gg, nullptr, nullptr, Cc, LORA_PAD, Cc);

    kk_kernel<<<(BT * Hh) / 8, 256>>>(k_k, k_a, as, kb, kkb);
    scan_kernel<<<Bb * Hh, 64>>>(rr, wd, kb, vb, kkb, as, yb);
    post_kernel<<<(BT * Hh) / 8, 256>>>(yb, rr, kb, vb, gg, r_k, ln_w, ln_b, ygh, ygl);

    // output projection
    mma_gemm<0,false><<<gBig, 256, GEMM_SMEM>>>(ygh, ygl, Woh, Wol, out, nullptr, nullptr, Cc, Cc, Cc);

    if ((size_t)out_size >= 2 * BTC) {
        cudaMemcpyAsync(out + BTC, v_first, BTC * sizeof(float), cudaMemcpyDeviceToDevice);
    }
}

// round 6
// speedup vs baseline: 2.4954x; 1.0178x over previous
#include <cuda_runtime.h>
#include <cuda_bf16.h>
#include <cstdint>

// ---------------- problem constants ----------------
#define Bb 8
#define Tt 1024
#define Cc 2048
#define Hh 32
#define Nn 64
#define BT (Bb*Tt)                  // 8192
#define BTC ((size_t)BT*Cc)         // 16.7M
#define LORA_PAD 128
#define LN_EPS (1e-5f*64.0f)

// ---------------- scratch (device globals) ----------------
__device__ float g_r[BTC], g_k[BTC], g_v[BTC];
__device__ float g_wdec[BTC], g_asig[BTC], g_g[BTC], g_kk[BTC], g_y[BTC];

__device__ uint16_t g_xrh[BTC], g_xrl[BTC], g_xwh[BTC], g_xwl[BTC];
__device__ uint16_t g_xkh[BTC], g_xkl[BTC], g_xvh[BTC], g_xvl[BTC];
__device__ uint16_t g_xah[BTC], g_xal[BTC], g_xgh[BTC], g_xgl[BTC];
__device__ uint16_t g_ygh[BTC], g_ygl[BTC];
__device__ uint16_t g_Wrh[Cc*Cc], g_Wrl[Cc*Cc], g_Wkh[Cc*Cc], g_Wkl[Cc*Cc];
__device__ uint16_t g_Wvh[Cc*Cc], g_Wvl[Cc*Cc], g_Woh[Cc*Cc], g_Wol[Cc*Cc];
// LoRA weights: stage1 [4][128 x 2048], stage2 [4][2048 x 128]
__device__ uint16_t g_l1h[4][LORA_PAD*Cc], g_l1l[4][LORA_PAD*Cc];
__device__ uint16_t g_l2h[4][Cc*LORA_PAD], g_l2l[4][Cc*LORA_PAD];
// LoRA stage-1 outputs [4][8192 x 128]
__device__ uint16_t g_tsh[4][(size_t)BT*LORA_PAD], g_tsl[4][(size_t)BT*LORA_PAD];

// ---------------- helpers ----------------
__device__ __forceinline__ void split_store(float v, uint16_t* hi, uint16_t* lo, size_t i) {
    __nv_bfloat16 h = __float2bfloat16(v);
    float hf = __bfloat162float(h);
    __nv_bfloat16 l = __float2bfloat16(v - hf);
    reinterpret_cast<__nv_bfloat16*>(hi)[i] = h;
    reinterpret_cast<__nv_bfloat16*>(lo)[i] = l;
}

__device__ __forceinline__ void split4(float4 v, uint16_t* hi, uint16_t* lo, size_t i) {
    __nv_bfloat162 h0 = __floats2bfloat162_rn(v.x, v.y);
    __nv_bfloat162 h1 = __floats2bfloat162_rn(v.z, v.w);
    float2 f0 = __bfloat1622float2(h0), f1 = __bfloat1622float2(h1);
    __nv_bfloat162 l0 = __floats2bfloat162_rn(v.x - f0.x, v.y - f0.y);
    __nv_bfloat162 l1 = __floats2bfloat162_rn(v.z - f1.x, v.w - f1.y);
    *reinterpret_cast<uint2*>(hi + i) =
        make_uint2(*reinterpret_cast<uint32_t*>(&h0), *reinterpret_cast<uint32_t*>(&h1));
    *reinterpret_cast<uint2*>(lo + i) =
        make_uint2(*reinterpret_cast<uint32_t*>(&l0), *reinterpret_cast<uint32_t*>(&l1));
}

__device__ __forceinline__ uint32_t smem_u32(const void* p) {
    uint32_t a;
    asm("{ .reg .u64 t; cvta.to.shared.u64 t, %1; cvt.u32.u64 %0, t; }" : "=r"(a) : "l"(p));
    return a;
}
#define SWZ128(o) ((o) ^ (((o) >> 3) & 0x70))

__device__ __forceinline__ void cpa16(uint32_t daddr, const void* g)
{
    asm volatile("cp.async.cg.shared.global [%0], [%1], 16;"
                 :: "r"(daddr), "l"(__cvta_generic_to_global(g)) : "memory");
}

__device__ __forceinline__ void ldsm4(uint32_t& r0, uint32_t& r1, uint32_t& r2, uint32_t& r3,
                                      uint32_t addr)
{
    asm volatile("ldmatrix.sync.aligned.m8n8.x4.shared.b16 {%0,%1,%2,%3}, [%4];"
                 : "=r"(r0), "=r"(r1), "=r"(r2), "=r"(r3) : "r"(addr));
}

__device__ __forceinline__ void mma16816(float* c, const uint32_t* a, const uint32_t* b)
{
    asm volatile("mma.sync.aligned.m16n8k16.row.col.f32.bf16.bf16.f32 "
                 "{%0,%1,%2,%3}, {%4,%5,%6,%7}, {%8,%9}, {%0,%1,%2,%3};"
                 : "+f"(c[0]), "+f"(c[1]), "+f"(c[2]), "+f"(c[3])
                 : "r"(a[0]), "r"(a[1]), "r"(a[2]), "r"(a[3]), "r"(b[0]), "r"(b[1]));
}

// packed f32x2 (sm_100+)
typedef unsigned long long u64t;
__device__ __forceinline__ u64t pk2(float x, float y){ u64t d; asm("mov.b64 %0, {%1,%2};" : "=l"(d) : "f"(x), "f"(y)); return d; }
__device__ __forceinline__ void upk2(u64t d, float& x, float& y){ asm("mov.b64 {%0,%1}, %2;" : "=f"(x), "=f"(y) : "l"(d)); }
__device__ __forceinline__ u64t fma2(u64t a, u64t b, u64t c){ u64t d; asm("fma.rn.f32x2 %0, %1, %2, %3;" : "=l"(d) : "l"(a), "l"(b), "l"(c)); return d; }
__device__ __forceinline__ u64t mul2(u64t a, u64t b){ u64t d; asm("mul.rn.f32x2 %0, %1, %2;" : "=l"(d) : "l"(a), "l"(b)); return d; }

// ---------------- prep: mask + time-shift mixes -> split bf16 ----------------
// grid (BT, 2), block 256: thread handles 4 channels
__global__ void prep_kernel(const float* __restrict__ x, const float* __restrict__ mask,
                            const float* __restrict__ mr, const float* __restrict__ mw,
                            const float* __restrict__ mk, const float* __restrict__ mv,
                            const float* __restrict__ ma, const float* __restrict__ mg)
{
    int bt = blockIdx.x;
    int c  = blockIdx.y * 1024 + threadIdx.x * 4;
    int t  = bt & (Tt - 1);
    float m  = mask[bt];
    float mp = (t > 0) ? mask[bt - 1] : 0.f;
    size_t idx = (size_t)bt * Cc + c;
    float4 xv = *reinterpret_cast<const float4*>(&x[idx]);
    float4 xp = make_float4(0.f, 0.f, 0.f, 0.f);
    if (t > 0) xp = *reinterpret_cast<const float4*>(&x[idx - Cc]);
    float4 xm = make_float4(xv.x*m, xv.y*m, xv.z*m, xv.w*m);
    float4 xx = make_float4(xp.x*mp - xm.x, xp.y*mp - xm.y, xp.z*mp - xm.z, xp.w*mp - xm.w);
#define MIX(MM, HH, LL) { \
    float4 mm = *reinterpret_cast<const float4*>(&MM[c]); \
    float4 vv = make_float4(xm.x + xx.x*mm.x, xm.y + xx.y*mm.y, xm.z + xx.z*mm.z, xm.w + xx.w*mm.w); \
    split4(vv, HH, LL, idx); }
    MIX(mr, g_xrh, g_xrl); MIX(mw, g_xwh, g_xwl); MIX(mk, g_xkh, g_xkl);
    MIX(mv, g_xvh, g_xvl); MIX(ma, g_xah, g_xal); MIX(mg, g_xgh, g_xgl);
#undef MIX
}

// big weights: 4 at once, float4 per thread per matrix
__global__ void wsplit_kernel(const float* __restrict__ Wr, const float* __restrict__ Wk,
                              const float* __restrict__ Wv, const float* __restrict__ Wo)
{
    size_t i = ((size_t)blockIdx.x * 256 + threadIdx.x) * 4;
    split4(*reinterpret_cast<const float4*>(&Wr[i]), g_Wrh, g_Wrl, i);
    split4(*reinterpret_cast<const float4*>(&Wk[i]), g_Wkh, g_Wkl, i);
    split4(*reinterpret_cast<const float4*>(&Wv[i]), g_Wvh, g_Wvl, i);
    split4(*reinterpret_cast<const float4*>(&Wo[i]), g_Woh, g_Wol, i);
}

struct LoraSrc { const float* s1[4]; const float* s2[4]; };
__constant__ int c_D[4] = {96, 96, 64, 128};

// grid (1024, 8): y<4 -> stage1 [128,2048] from [2048,D]; y>=4 -> stage2 [2048,128] from [D,2048]
__global__ void lsplit_kernel(LoraSrc ls)
{
    int id = blockIdx.y;
    int i = blockIdx.x * 256 + threadIdx.x;   // < 262144
    if (id < 4) {
        int D = c_D[id];
        int n = i >> 11, kcol = i & 2047;
        float v = (n < D) ? ls.s1[id][(size_t)kcol * D + n] : 0.f;
        split_store(v, g_l1h[id], g_l1l[id], i);
    } else {
        int p = id - 4;
        int D = c_D[p];
        int n = i >> 7, kcol = i & 127;
        float v = (kcol < D) ? ls.s2[p][(size_t)kcol * Cc + n] : 0.f;
        split_store(v, g_l2h[p], g_l2l[p], i);
    }
}

// ---------------- GEMM: 3-term bf16 split, 4 resident tiles, 3 phases/chunk ------
// MODE 0: plain, C=Cf [*,2048].  MODE 1: batched LoRA stage1 (grid 4x64), split out [*,128],
// act tanh(path0)/sigmoid(path3).  MODE 2: batched stage2 (grid 64x64), fused elementwise out.
#define ATILE_B 16384
#define STAGE4_B (4*ATILE_B)        // 64KB
#define GEMM_SMEM (3*STAGE4_B)      // 192KB

struct GemmB {
    const uint16_t *Ah[4], *Al[4], *Bh[4], *Bl[4];
    uint16_t *Oh[4], *Ol[4];
    float *Of[4];
    const float *bias[4];
    const float *vf; const float *mask;
};

template<int MODE>
__global__ __launch_bounds__(256, 1)
void mma_gemm(const uint16_t* __restrict__ Ahi_, const uint16_t* __restrict__ Alo_,
              const uint16_t* __restrict__ Bhi_, const uint16_t* __restrict__ Blo_,
              float* __restrict__ Cf, GemmB bp, int K)
{
    extern __shared__ char smem[];
    const uint32_t sb = smem_u32(smem);
    const int tid = threadIdx.x, lane = tid & 31, warp = tid >> 5;
    const int warpM = warp >> 1, warpN = warp & 1;
    const int m0 = blockIdx.y * 128;
    int n0, path = 0;
    const uint16_t *Ahi, *Alo, *Bhi, *Blo;
    if (MODE == 0) { n0 = blockIdx.x * 128; Ahi = Ahi_; Alo = Alo_; Bhi = Bhi_; Blo = Blo_; }
    else if (MODE == 1) {
        path = blockIdx.x; n0 = 0;
        Ahi = bp.Ah[path]; Alo = bp.Al[path]; Bhi = bp.Bh[path]; Blo = bp.Bl[path];
    } else {
        path = blockIdx.x >> 4; n0 = (blockIdx.x & 15) * 128;
        Ahi = bp.Ah[path]; Alo = bp.Al[path]; Bhi = bp.Bh[path]; Blo = bp.Bl[path];
    }
    const int kc = K >> 6;

    float acc[2][8][4];
#pragma unroll
    for (int mt = 0; mt < 2; mt++)
#pragma unroll
        for (int nt = 0; nt < 8; nt++)
#pragma unroll
            for (int e = 0; e < 4; e++) acc[mt][nt][e] = 0.f;

    auto load_chunk = [&](int c) {
        const uint32_t stb = sb + (uint32_t)(c % 3) * STAGE4_B;
        const int k0 = c << 6;
        const uint16_t* srcs[4] = {Ahi, Alo, Bhi, Blo};
#pragma unroll
        for (int a4 = 0; a4 < 4; a4++) {
            const uint16_t* src = srcs[a4];
            const int rb = (a4 < 2) ? m0 : n0;
            const uint32_t ab = stb + a4 * ATILE_B;
#pragma unroll
            for (int jj = 0; jj < 4; jj++) {
                int T = tid + jj * 256;
                int row = T >> 3, seg = T & 7;
                cpa16(ab + SWZ128(row * 128 + seg * 16),
                      src + (size_t)(rb + row) * K + k0 + seg * 8);
            }
        }
    };

    load_chunk(0);
    asm volatile("cp.async.commit_group;" ::: "memory");
    load_chunk(1);
    asm volatile("cp.async.commit_group;" ::: "memory");

    for (int c = 0; c < kc; c++) {
        asm volatile("cp.async.wait_group 1;" ::: "memory");
        __syncthreads();
        if (c + 2 < kc) load_chunk(c + 2);
        asm volatile("cp.async.commit_group;" ::: "memory");

        const uint32_t stb = sb + (uint32_t)(c % 3) * STAGE4_B;
#pragma unroll
        for (int ph = 0; ph < 3; ph++) {
            const uint32_t sAa = stb + ((ph == 2) ? ATILE_B : 0u);
            const uint32_t sBb = stb + 2u * ATILE_B + ((ph == 1) ? ATILE_B : 0u);
#pragma unroll
            for (int s = 0; s < 4; s++) {
                uint32_t a[2][4];
#pragma unroll
                for (int mt = 0; mt < 2; mt++) {
                    int row = warpM * 32 + mt * 16 + (lane & 15);
                    int kb = s * 32 + ((lane >> 4) << 4);
                    ldsm4(a[mt][0], a[mt][1], a[mt][2], a[mt][3], sAa + SWZ128(row * 128 + kb));
                }
                uint32_t b[8][2];
#pragma unroll
                for (int p = 0; p < 4; p++) {
                    int nr = warpN * 64 + p * 16 + (lane & 7) + ((lane >> 1) & 8);
                    int kb = s * 32 + ((lane >> 3) & 1) * 16;
                    uint32_t r0, r1, r2, r3;
                    ldsm4(r0, r1, r2, r3, sBb + SWZ128(nr * 128 + kb));
                    b[p * 2][0] = r0;     b[p * 2][1] = r1;
                    b[p * 2 + 1][0] = r2; b[p * 2 + 1][1] = r3;
                }
#pragma unroll
                for (int mt = 0; mt < 2; mt++)
#pragma unroll
                    for (int nt = 0; nt < 8; nt++)
                        mma16816(acc[mt][nt], a[mt], b[nt]);
            }
        }
    }

    // epilogue
    const int row0 = m0 + warpM * 32 + (lane >> 2);
    const int col0 = n0 + warpN * 64 + (lane & 3) * 2;
#pragma unroll
    for (int mt = 0; mt < 2; mt++) {
#pragma unroll
        for (int nt = 0; nt < 8; nt++) {
            int r1 = row0 + mt * 16;
            int c1 = col0 + nt * 8;
            float v0 = acc[mt][nt][0], v1 = acc[mt][nt][1];
            float v2 = acc[mt][nt][2], v3 = acc[mt][nt][3];
            if (MODE == 0) {
                *reinterpret_cast<float2*>(&Cf[(size_t)r1 * Cc + c1]) = make_float2(v0, v1);
                *reinterpret_cast<float2*>(&Cf[(size_t)(r1 + 8) * Cc + c1]) = make_float2(v2, v3);
            } else if (MODE == 1) {
                if (path == 0) { v0 = tanhf(v0); v1 = tanhf(v1); v2 = tanhf(v2); v3 = tanhf(v3); }
                else if (path == 3) {
                    v0 = 1.f/(1.f+expf(-v0)); v1 = 1.f/(1.f+expf(-v1));
                    v2 = 1.f/(1.f+expf(-v2)); v3 = 1.f/(1.f+expf(-v3));
                }
                uint16_t* oh = bp.Oh[path]; uint16_t* ol = bp.Ol[path];
                split_store(v0, oh, ol, (size_t)r1 * LORA_PAD + c1);
                split_store(v1, oh, ol, (size_t)r1 * LORA_PAD + c1 + 1);
                split_store(v2, oh, ol, (size_t)(r1 + 8) * LORA_PAD + c1);
                split_store(v3, oh, ol, (size_t)(r1 + 8) * LORA_PAD + c1 + 1);
            } else {
                auto ep = [&](float z, int rr_, int cc_) {
                    size_t idx = (size_t)rr_ * Cc + cc_;
                    if (path == 0) {
                        float zz = bp.bias[0][cc_] + z;
                        float nz = -zz;
                        float sp = (nz > 20.f) ? nz : log1pf(expf(nz));
                        bp.Of[0][idx] = expf(-expf(-sp - 0.5f));
                    } else if (path == 1) {
                        bp.Of[1][idx] = 1.f / (1.f + expf(-(bp.bias[1][cc_] + z)));
                    } else if (path == 2) {
                        float s = 1.f / (1.f + expf(-(bp.bias[2][cc_] + z)));
                        float vv = bp.Of[2][idx];
                        bp.Of[2][idx] = (vv + (bp.vf[idx] - vv) * s) * bp.mask[rr_];
                    } else {
                        bp.Of[3][idx] = z;
                    }
                };
                ep(v0, r1, c1); ep(v1, r1, c1 + 1);
                ep(v2, r1 + 8, c1); ep(v3, r1 + 8, c1 + 1);
            }
        }
    }
}

// ---------------- kk normalize + k rescale ----------------
__global__ void kk_kernel(const float* __restrict__ kkp, const float* __restrict__ kap,
                          const float* __restrict__ asig,
                          float* __restrict__ k, float* __restrict__ kk)
{
    int gid = blockIdx.x * 8 + (threadIdx.x >> 5);
    int lane = threadIdx.x & 31;
    int h = gid % Hh;
    size_t bt = gid / Hh;
    size_t base = bt * Cc + (size_t)h * Nn;
    int c0 = h * Nn + lane, c1 = c0 + 32;
    float k0v = k[base + lane], k1v = k[base + lane + 32];
    float kk0 = k0v * kkp[c0], kk1 = k1v * kkp[c1];
    float ss = kk0 * kk0 + kk1 * kk1;
#pragma unroll
    for (int o = 16; o > 0; o >>= 1) ss += __shfl_xor_sync(0xffffffffu, ss, o);
    float inv = 1.f / fmaxf(sqrtf(ss), 1e-12f);
    kk[base + lane]      = kk0 * inv;
    kk[base + lane + 32] = kk1 * inv;
    float a0v = asig[base + lane], a1v = asig[base + lane + 32];
    k[base + lane]      = k0v * (1.f + (a0v - 1.f) * kap[c0]);
    k[base + lane + 32] = k1v * (1.f + (a1v - 1.f) * kap[c1]);
}

// ---------------- RWKV-7 scan: 128 threads/block, f32x2, prefetch ----------------
__global__ __launch_bounds__(128)
void scan_kernel(const float* __restrict__ r, const float* __restrict__ wdec,
                 const float* __restrict__ k, const float* __restrict__ v,
                 const float* __restrict__ kk, const float* __restrict__ asig,
                 float* __restrict__ y)
{
    int bh = blockIdx.x;
    int b = bh >> 5, h = bh & 31;
    int tid = threadIdx.x;
    int j = tid >> 1, half = tid & 1;
    __shared__ float4 sWB[2][32];   // (w_i, w_i+1, b_i, b_i+1)
    __shared__ float4 sKR[2][32];   // (k_i, k_i+1, r_i, r_i+1)
    __shared__ float2 sA2[2][32];
    u64t S[16];
#pragma unroll
    for (int i = 0; i < 16; i++) S[i] = 0ull;
    size_t base0 = ((size_t)b * Tt) * Cc + (size_t)h * Nn;

    float pw = 0.f, pb = 0.f, pkv = 0.f, prv = 0.f, pa = 0.f;
    if (tid < 64) {
        size_t ba = base0 + tid;
        float kkv = kk[ba];
        pw = wdec[ba]; pb = kkv * asig[ba]; pkv = k[ba]; prv = r[ba]; pa = -kkv;
    }
    float pvj = v[base0 + j];

    for (int t = 0; t < Tt; t++) {
        int buf = t & 1;
        if (tid < 64) {
            int hi_ = tid >> 1, par = tid & 1;
            float* pWB = reinterpret_cast<float*>(&sWB[buf][hi_]);
            pWB[par] = pw; pWB[2 + par] = pb;
            float* pKR = reinterpret_cast<float*>(&sKR[buf][hi_]);
            pKR[par] = pkv; pKR[2 + par] = prv;
            reinterpret_cast<float*>(&sA2[buf][hi_])[par] = pa;
        }
        float vj = pvj;
        __syncthreads();
        if (t + 1 < Tt) {
            if (tid < 64) {
                size_t ba = base0 + (size_t)(t + 1) * Cc + tid;
                float kkv = kk[ba];
                pw = wdec[ba]; pb = kkv * asig[ba]; pkv = k[ba]; prv = r[ba]; pa = -kkv;
            }
            pvj = v[base0 + (size_t)(t + 1) * Cc + j];
        }
        int i0 = half * 16;
        // pass 1: sacc (4-way split chains)
        u64t a0 = 0ull, a1 = 0ull, a2 = 0ull, a3 = 0ull;
#pragma unroll
        for (int ii = 0; ii < 16; ii += 4) {
            a0 = fma2(S[ii + 0], *reinterpret_cast<u64t*>(&sA2[buf][i0 + ii + 0]), a0);
            a1 = fma2(S[ii + 1], *reinterpret_cast<u64t*>(&sA2[buf][i0 + ii + 1]), a1);
            a2 = fma2(S[ii + 2], *reinterpret_cast<u64t*>(&sA2[buf][i0 + ii + 2]), a2);
            a3 = fma2(S[ii + 3], *reinterpret_cast<u64t*>(&sA2[buf][i0 + ii + 3]), a3);
        }
        float ax, ay, bx, by, cx, cy, dx, dy;
        upk2(a0, ax, ay); upk2(a1, bx, by); upk2(a2, cx, cy); upk2(a3, dx, dy);
        float sacc = ((ax + ay) + (bx + by)) + ((cx + cy) + (dx + dy));
        sacc += __shfl_xor_sync(0xffffffffu, sacc, 1);
        u64t sacc2 = pk2(sacc, sacc);
        u64t vj2 = pk2(vj, vj);
        // pass 2: update + y (2-way y chains)
        u64t ya = 0ull, yb = 0ull;
#pragma unroll
        for (int ii = 0; ii < 16; ii += 2) {
            float4 wb0 = sWB[buf][i0 + ii], kr0 = sKR[buf][i0 + ii];
            u64t s0 = fma2(S[ii], pk2(wb0.x, wb0.y),
                           fma2(sacc2, pk2(wb0.z, wb0.w), mul2(vj2, pk2(kr0.x, kr0.y))));
            S[ii] = s0;
            ya = fma2(s0, pk2(kr0.z, kr0.w), ya);
            float4 wb1 = sWB[buf][i0 + ii + 1], kr1 = sKR[buf][i0 + ii + 1];
            u64t s1 = fma2(S[ii + 1], pk2(wb1.x, wb1.y),
                           fma2(sacc2, pk2(wb1.z, wb1.w), mul2(vj2, pk2(kr1.x, kr1.y))));
            S[ii + 1] = s1;
            yb = fma2(s1, pk2(kr1.z, kr1.w), yb);
        }
        float y0x, y0y, y1x, y1y;
        upk2(ya, y0x, y0y); upk2(yb, y1x, y1y);
        float yv = (y0x + y0y) + (y1x + y1y);
        yv += __shfl_xor_sync(0xffffffffu, yv, 1);
        if (half == 0) y[base0 + (size_t)t * Cc + j] = yv;
    }
}

// ---------------- groupnorm + rk*v + gate -> split bf16 ----------------
__global__ void post_kernel(const float* __restrict__ y, const float* __restrict__ r,
                            const float* __restrict__ k, const float* __restrict__ v,
                            const float* __restrict__ g, const float* __restrict__ r_k,
                            const float* __restrict__ ln_w, const float* __restrict__ ln_b,
                            uint16_t* __restrict__ oh, uint16_t* __restrict__ ol)
{
    int gid = blockIdx.x * 8 + (threadIdx.x >> 5);
    int lane = threadIdx.x & 31;
    int h = gid % Hh;
    size_t bt = gid / Hh;
    size_t base = bt * Cc + (size_t)h * Nn;
    int c0 = h * Nn + lane, c1 = c0 + 32;
    float y0 = y[base + lane], y1 = y[base + lane + 32];
    float sum = y0 + y1;
#pragma unroll
    for (int o = 16; o > 0; o >>= 1) sum += __shfl_xor_sync(0xffffffffu, sum, o);
    float mean = sum * (1.f / 64.f);
    float d0 = y0 - mean, d1 = y1 - mean;
    float var = d0 * d0 + d1 * d1;
#pragma unroll
    for (int o = 16; o > 0; o >>= 1) var += __shfl_xor_sync(0xffffffffu, var, o);
    var *= (1.f / 64.f);
    float inv = rsqrtf(var + LN_EPS);
    float yn0 = d0 * inv * ln_w[c0] + ln_b[c0];
    float yn1 = d1 * inv * ln_w[c1] + ln_b[c1];
    float rk = r[base + lane] * k[base + lane] * r_k[c0]
             + r[base + lane + 32] * k[base + lane + 32] * r_k[c1];
#pragma unroll
    for (int o = 16; o > 0; o >>= 1) rk += __shfl_xor_sync(0xffffffffu, rk, o);
    float o0 = (yn0 + rk * v[base + lane]) * g[base + lane];
    float o1 = (yn1 + rk * v[base + lane + 32]) * g[base + lane + 32];
    split_store(o0, oh, ol, base + lane);
    split_store(o1, oh, ol, base + lane + 32);
}

// ---------------- launch ----------------
#define GETSYM(var, sym) do { void* _p; cudaGetSymbolAddress(&_p, sym); var = (decltype(var))_p; } while (0)

extern "C" void kernel_launch(void* const* d_in, const int* in_sizes, int n_in,
                              void* d_out, int out_size)
{
    const float* x       = (const float*)d_in[0];
    const float* mask    = (const float*)d_in[1];
    const float* v_first = (const float*)d_in[2];
    const float* x_r = (const float*)d_in[3];
    const float* x_w = (const float*)d_in[4];
    const float* x_k = (const float*)d_in[5];
    const float* x_v = (const float*)d_in[6];
    const float* x_a = (const float*)d_in[7];
    const float* x_g = (const float*)d_in[8];
    const float* w0 = (const float*)d_in[9];
    const float* w1 = (const float*)d_in[10];
    const float* w2 = (const float*)d_in[11];
    const float* a0 = (const float*)d_in[12];
    const float* a1 = (const float*)d_in[13];
    const float* a2 = (const float*)d_in[14];
    const float* v0 = (const float*)d_in[15];
    const float* v1 = (const float*)d_in[16];
    const float* v2 = (const float*)d_in[17];
    const float* g1 = (const float*)d_in[18];
    const float* g2 = (const float*)d_in[19];
    const float* k_k = (const float*)d_in[20];
    const float* k_a = (const float*)d_in[21];
    const float* r_k = (const float*)d_in[22];
    const float* W_r = (const float*)d_in[23];
    const float* W_k = (const float*)d_in[24];
    const float* W_v = (const float*)d_in[25];
    const float* W_o = (const float*)d_in[26];
    const float* ln_w = (const float*)d_in[27];
    const float* ln_b = (const float*)d_in[28];
    float* out = (float*)d_out;

    float *rr, *kb, *vb, *wd, *as, *gg, *kkb, *yb;
    GETSYM(rr, g_r); GETSYM(kb, g_k); GETSYM(vb, g_v);
    GETSYM(wd, g_wdec); GETSYM(as, g_asig); GETSYM(gg, g_g);
    GETSYM(kkb, g_kk); GETSYM(yb, g_y);
    uint16_t *xrh,*xrl,*xwh,*xwl,*xkh,*xkl,*xvh,*xvl,*xah,*xal,*xgh,*xgl,*ygh,*ygl;
    GETSYM(xrh, g_xrh); GETSYM(xrl, g_xrl); GETSYM(xwh, g_xwh); GETSYM(xwl, g_xwl);
    GETSYM(xkh, g_xkh); GETSYM(xkl, g_xkl); GETSYM(xvh, g_xvh); GETSYM(xvl, g_xvl);
    GETSYM(xah, g_xah); GETSYM(xal, g_xal); GETSYM(xgh, g_xgh); GETSYM(xgl, g_xgl);
    GETSYM(ygh, g_ygh); GETSYM(ygl, g_ygl);
    uint16_t *Wrh,*Wrl,*Wkh,*Wkl,*Wvh,*Wvl,*Woh,*Wol;
    GETSYM(Wrh, g_Wrh); GETSYM(Wrl, g_Wrl); GETSYM(Wkh, g_Wkh); GETSYM(Wkl, g_Wkl);
    GETSYM(Wvh, g_Wvh); GETSYM(Wvl, g_Wvl); GETSYM(Woh, g_Woh); GETSYM(Wol, g_Wol);
    uint16_t *l1h, *l1l, *l2h, *l2l, *tsh, *tsl;
    GETSYM(l1h, g_l1h); GETSYM(l1l, g_l1l); GETSYM(l2h, g_l2h); GETSYM(l2l, g_l2l);
    GETSYM(tsh, g_tsh); GETSYM(tsl, g_tsl);

    cudaFuncSetAttribute(mma_gemm<0>, cudaFuncAttributeMaxDynamicSharedMemorySize, GEMM_SMEM);
    cudaFuncSetAttribute(mma_gemm<1>, cudaFuncAttributeMaxDynamicSharedMemorySize, GEMM_SMEM);
    cudaFuncSetAttribute(mma_gemm<2>, cudaFuncAttributeMaxDynamicSharedMemorySize, GEMM_SMEM);

    // 1: prep
    prep_kernel<<<dim3(BT, 2), 256>>>(x, mask, x_r, x_w, x_k, x_v, x_a, x_g);
    // 2: big weight splits
    wsplit_kernel<<<(Cc * Cc) / 1024, 256>>>(W_r, W_k, W_v, W_o);
    // 3: LoRA weight splits
    LoraSrc ls;
    ls.s1[0] = w1; ls.s1[1] = a1; ls.s1[2] = v1; ls.s1[3] = g1;
    ls.s2[0] = w2; ls.s2[1] = a2; ls.s2[2] = v2; ls.s2[3] = g2;
    lsplit_kernel<<<dim3(1024, 8), 256>>>(ls);

    GemmB be = {};   // empty for MODE 0
    const dim3 gBig(16, 64);
    // 4,5,6: r, k, v projections  (#6 lands in the ncu capture window)
    mma_gemm<0><<<gBig, 256, GEMM_SMEM>>>(xrh, xrl, Wrh, Wrl, rr, be, Cc);
    mma_gemm<0><<<gBig, 256, GEMM_SMEM>>>(xkh, xkl, Wkh, Wkl, kb, be, Cc);
    mma_gemm<0><<<gBig, 256, GEMM_SMEM>>>(xvh, xvl, Wvh, Wvl, vb, be, Cc);

    // 7: batched LoRA stage 1 (w,a,v,g)
    GemmB b1 = {};
    const size_t L1 = (size_t)LORA_PAD * Cc, L2 = (size_t)Cc * LORA_PAD;
    const size_t TS = (size_t)BT * LORA_PAD;
    b1.Ah[0] = xwh; b1.Al[0] = xwl; b1.Ah[1] = xah; b1.Al[1] = xal;
    b1.Ah[2] = xvh; b1.Al[2] = xvl; b1.Ah[3] = xgh; b1.Al[3] = xgl;
    for (int p = 0; p < 4; p++) {
        b1.Bh[p] = l1h + p * L1; b1.Bl[p] = l1l + p * L1;
        b1.Oh[p] = tsh + p * TS; b1.Ol[p] = tsl + p * TS;
    }
    mma_gemm<1><<<dim3(4, 64), 256, GEMM_SMEM>>>(nullptr, nullptr, nullptr, nullptr, nullptr, b1, Cc);

    // 8: batched LoRA stage 2 with fused elementwise epilogues
    GemmB b2 = {};
    for (int p = 0; p < 4; p++) {
        b2.Ah[p] = tsh + p * TS; b2.Al[p] = tsl + p * TS;
        b2.Bh[p] = l2h + p * L2; b2.Bl[p] = l2l + p * L2;
    }
    b2.Of[0] = wd; b2.Of[1] = as; b2.Of[2] = vb; b2.Of[3] = gg;
    b2.bias[0] = w0; b2.bias[1] = a0; b2.bias[2] = v0; b2.bias[3] = w0;
    b2.vf = v_first; b2.mask = mask;
    mma_gemm<2><<<dim3(64, 64), 256, GEMM_SMEM>>>(nullptr, nullptr, nullptr, nullptr, nullptr, b2, LORA_PAD);

    // 9-11: kk, scan, post
    kk_kernel<<<(BT * Hh) / 8, 256>>>(k_k, k_a, as, kb, kkb);
    scan_kernel<<<Bb * Hh, 128>>>(rr, wd, kb, vb, kkb, as, yb);
    post_kernel<<<(BT * Hh) / 8, 256>>>(yb, rr, kb, vb, gg, r_k, ln_w, ln_b, ygh, ygl);

    // 12: output projection
    mma_gemm<0><<<gBig, 256, GEMM_SMEM>>>(ygh, ygl, Woh, Wol, out, be, Cc);

    // 13: v_first passthrough
    if ((size_t)out_size >= 2 * BTC) {
        cudaMemcpyAsync(out + BTC, v_first, BTC * sizeof(float), cudaMemcpyDeviceToDevice);
    }
}

// round 7
// speedup vs baseline: 2.5719x; 1.0307x over previous
#include <cuda_runtime.h>
#include <cuda_bf16.h>
#include <cstdint>

// ---------------- problem constants ----------------
#define Bb 8
#define Tt 1024
#define Cc 2048
#define Hh 32
#define Nn 64
#define BT (Bb*Tt)                  // 8192
#define BTC ((size_t)BT*Cc)         // 16.7M
#define LORA_PAD 128
#define LN_EPS (1e-5f*64.0f)

// ---------------- scratch (device globals) ----------------
__device__ float g_r[BTC], g_k[BTC], g_v[BTC];
__device__ float g_wdec[BTC], g_asig[BTC], g_g[BTC], g_kk[BTC], g_y[BTC];

__device__ uint16_t g_xrh[BTC], g_xrl[BTC], g_xwh[BTC], g_xwl[BTC];
__device__ uint16_t g_xkh[BTC], g_xkl[BTC], g_xvh[BTC], g_xvl[BTC];
__device__ uint16_t g_xah[BTC], g_xal[BTC], g_xgh[BTC], g_xgl[BTC];
__device__ uint16_t g_ygh[BTC], g_ygl[BTC];
__device__ uint16_t g_Wrh[Cc*Cc], g_Wrl[Cc*Cc], g_Wkh[Cc*Cc], g_Wkl[Cc*Cc];
__device__ uint16_t g_Wvh[Cc*Cc], g_Wvl[Cc*Cc], g_Woh[Cc*Cc], g_Wol[Cc*Cc];
// LoRA weights: stage1 [4][128 x 2048], stage2 [4][2048 x 128]
__device__ uint16_t g_l1h[4][LORA_PAD*Cc], g_l1l[4][LORA_PAD*Cc];
__device__ uint16_t g_l2h[4][Cc*LORA_PAD], g_l2l[4][Cc*LORA_PAD];
// LoRA stage-1 outputs [4][8192 x 128]
__device__ uint16_t g_tsh[4][(size_t)BT*LORA_PAD], g_tsl[4][(size_t)BT*LORA_PAD];

// ---------------- helpers ----------------
__device__ __forceinline__ void split_store(float v, uint16_t* hi, uint16_t* lo, size_t i) {
    __nv_bfloat16 h = __float2bfloat16(v);
    float hf = __bfloat162float(h);
    __nv_bfloat16 l = __float2bfloat16(v - hf);
    reinterpret_cast<__nv_bfloat16*>(hi)[i] = h;
    reinterpret_cast<__nv_bfloat16*>(lo)[i] = l;
}

__device__ __forceinline__ void split4(float4 v, uint16_t* hi, uint16_t* lo, size_t i) {
    __nv_bfloat162 h0 = __floats2bfloat162_rn(v.x, v.y);
    __nv_bfloat162 h1 = __floats2bfloat162_rn(v.z, v.w);
    float2 f0 = __bfloat1622float2(h0), f1 = __bfloat1622float2(h1);
    __nv_bfloat162 l0 = __floats2bfloat162_rn(v.x - f0.x, v.y - f0.y);
    __nv_bfloat162 l1 = __floats2bfloat162_rn(v.z - f1.x, v.w - f1.y);
    *reinterpret_cast<uint2*>(hi + i) =
        make_uint2(*reinterpret_cast<uint32_t*>(&h0), *reinterpret_cast<uint32_t*>(&h1));
    *reinterpret_cast<uint2*>(lo + i) =
        make_uint2(*reinterpret_cast<uint32_t*>(&l0), *reinterpret_cast<uint32_t*>(&l1));
}

__device__ __forceinline__ uint32_t smem_u32(const void* p) {
    uint32_t a;
    asm("{ .reg .u64 t; cvta.to.shared.u64 t, %1; cvt.u32.u64 %0, t; }" : "=r"(a) : "l"(p));
    return a;
}
#define SWZ128(o) ((o) ^ (((o) >> 3) & 0x70))

__device__ __forceinline__ void cpa16(uint32_t daddr, const void* g)
{
    asm volatile("cp.async.cg.shared.global [%0], [%1], 16;"
                 :: "r"(daddr), "l"(__cvta_generic_to_global(g)) : "memory");
}

__device__ __forceinline__ void ldsm4(uint32_t& r0, uint32_t& r1, uint32_t& r2, uint32_t& r3,
                                      uint32_t addr)
{
    asm volatile("ldmatrix.sync.aligned.m8n8.x4.shared.b16 {%0,%1,%2,%3}, [%4];"
                 : "=r"(r0), "=r"(r1), "=r"(r2), "=r"(r3) : "r"(addr));
}

__device__ __forceinline__ void mma16816(float* c, const uint32_t* a, const uint32_t* b)
{
    asm volatile("mma.sync.aligned.m16n8k16.row.col.f32.bf16.bf16.f32 "
                 "{%0,%1,%2,%3}, {%4,%5,%6,%7}, {%8,%9}, {%0,%1,%2,%3};"
                 : "+f"(c[0]), "+f"(c[1]), "+f"(c[2]), "+f"(c[3])
                 : "r"(a[0]), "r"(a[1]), "r"(a[2]), "r"(a[3]), "r"(b[0]), "r"(b[1]));
}

// packed f32x2 (sm_100+)
typedef unsigned long long u64t;
__device__ __forceinline__ u64t pk2(float x, float y){ u64t d; asm("mov.b64 %0, {%1,%2};" : "=l"(d) : "f"(x), "f"(y)); return d; }
__device__ __forceinline__ void upk2(u64t d, float& x, float& y){ asm("mov.b64 {%0,%1}, %2;" : "=f"(x), "=f"(y) : "l"(d)); }
__device__ __forceinline__ u64t fma2(u64t a, u64t b, u64t c){ u64t d; asm("fma.rn.f32x2 %0, %1, %2, %3;" : "=l"(d) : "l"(a), "l"(b), "l"(c)); return d; }
__device__ __forceinline__ u64t mul2(u64t a, u64t b){ u64t d; asm("mul.rn.f32x2 %0, %1, %2;" : "=l"(d) : "l"(a), "l"(b)); return d; }

// ---------------- prep: mask + time-shift mixes -> split bf16 ----------------
__global__ void prep_kernel(const float* __restrict__ x, const float* __restrict__ mask,
                            const float* __restrict__ mr, const float* __restrict__ mw,
                            const float* __restrict__ mk, const float* __restrict__ mv,
                            const float* __restrict__ ma, const float* __restrict__ mg)
{
    int bt = blockIdx.x;
    int c  = blockIdx.y * 1024 + threadIdx.x * 4;
    int t  = bt & (Tt - 1);
    float m  = mask[bt];
    float mp = (t > 0) ? mask[bt - 1] : 0.f;
    size_t idx = (size_t)bt * Cc + c;
    float4 xv = *reinterpret_cast<const float4*>(&x[idx]);
    float4 xp = make_float4(0.f, 0.f, 0.f, 0.f);
    if (t > 0) xp = *reinterpret_cast<const float4*>(&x[idx - Cc]);
    float4 xm = make_float4(xv.x*m, xv.y*m, xv.z*m, xv.w*m);
    float4 xx = make_float4(xp.x*mp - xm.x, xp.y*mp - xm.y, xp.z*mp - xm.z, xp.w*mp - xm.w);
#define MIX(MM, HH, LL) { \
    float4 mm = *reinterpret_cast<const float4*>(&MM[c]); \
    float4 vv = make_float4(xm.x + xx.x*mm.x, xm.y + xx.y*mm.y, xm.z + xx.z*mm.z, xm.w + xx.w*mm.w); \
    split4(vv, HH, LL, idx); }
    MIX(mr, g_xrh, g_xrl); MIX(mw, g_xwh, g_xwl); MIX(mk, g_xkh, g_xkl);
    MIX(mv, g_xvh, g_xvl); MIX(ma, g_xah, g_xal); MIX(mg, g_xgh, g_xgl);
#undef MIX
}

__global__ void wsplit_kernel(const float* __restrict__ Wr, const float* __restrict__ Wk,
                              const float* __restrict__ Wv, const float* __restrict__ Wo)
{
    size_t i = ((size_t)blockIdx.x * 256 + threadIdx.x) * 4;
    split4(*reinterpret_cast<const float4*>(&Wr[i]), g_Wrh, g_Wrl, i);
    split4(*reinterpret_cast<const float4*>(&Wk[i]), g_Wkh, g_Wkl, i);
    split4(*reinterpret_cast<const float4*>(&Wv[i]), g_Wvh, g_Wvl, i);
    split4(*reinterpret_cast<const float4*>(&Wo[i]), g_Woh, g_Wol, i);
}

struct LoraSrc { const float* s1[4]; const float* s2[4]; };
__constant__ int c_D[4] = {96, 96, 64, 128};

__global__ void lsplit_kernel(LoraSrc ls)
{
    int id = blockIdx.y;
    int i = blockIdx.x * 256 + threadIdx.x;
    if (id < 4) {
        int D = c_D[id];
        int n = i >> 11, kcol = i & 2047;
        float v = (n < D) ? ls.s1[id][(size_t)kcol * D + n] : 0.f;
        split_store(v, g_l1h[id], g_l1l[id], i);
    } else {
        int p = id - 4;
        int D = c_D[p];
        int n = i >> 7, kcol = i & 127;
        float v = (kcol < D) ? ls.s2[p][(size_t)kcol * Cc + n] : 0.f;
        split_store(v, g_l2h[p], g_l2l[p], i);
    }
}

// ---------------- GEMM: 3-term bf16 split, fragment-reuse inner loop ----------------
// MODE 0: batched plain fp32 out [*,2048] (grid (16*P, 64), path=x>>4).
// MODE 1: batched LoRA stage1 (grid (4,64)), split bf16 out [*,128], tanh/sigmoid.
// MODE 2: batched LoRA stage2 (grid (64,64)), fused elementwise epilogues.
#define ATILE_B 16384
#define STAGE4_B (4*ATILE_B)        // 64KB
#define GEMM_SMEM (3*STAGE4_B)      // 192KB

struct GemmB {
    const uint16_t *Ah[4], *Al[4], *Bh[4], *Bl[4];
    uint16_t *Oh[4], *Ol[4];
    float *Of[4];
    const float *bias[4];
    const float *vf; const float *mask;
};

template<int MODE>
__global__ __launch_bounds__(256, 1)
void mma_gemm(GemmB bp, int K)
{
    extern __shared__ char smem[];
    const uint32_t sb = smem_u32(smem);
    const int tid = threadIdx.x, lane = tid & 31, warp = tid >> 5;
    const int warpM = warp >> 1, warpN = warp & 1;
    const int m0 = blockIdx.y * 128;
    int n0, path;
    if (MODE == 0)      { path = blockIdx.x >> 4; n0 = (blockIdx.x & 15) * 128; }
    else if (MODE == 1) { path = blockIdx.x;      n0 = 0; }
    else                { path = blockIdx.x >> 4; n0 = (blockIdx.x & 15) * 128; }
    const uint16_t* Ahi = bp.Ah[path]; const uint16_t* Alo = bp.Al[path];
    const uint16_t* Bhi = bp.Bh[path]; const uint16_t* Blo = bp.Bl[path];
    const int kc = K >> 6;

    float acc[2][8][4];
#pragma unroll
    for (int mt = 0; mt < 2; mt++)
#pragma unroll
        for (int nt = 0; nt < 8; nt++)
#pragma unroll
            for (int e = 0; e < 4; e++) acc[mt][nt][e] = 0.f;

    auto load_chunk = [&](int c) {
        const uint32_t stb = sb + (uint32_t)(c % 3) * STAGE4_B;
        const int k0 = c << 6;
        const uint16_t* srcs[4] = {Ahi, Alo, Bhi, Blo};
#pragma unroll
        for (int a4 = 0; a4 < 4; a4++) {
            const uint16_t* src = srcs[a4];
            const int rb = (a4 < 2) ? m0 : n0;
            const uint32_t ab = stb + a4 * ATILE_B;
#pragma unroll
            for (int jj = 0; jj < 4; jj++) {
                int T = tid + jj * 256;
                int row = T >> 3, seg = T & 7;
                cpa16(ab + SWZ128(row * 128 + seg * 16),
                      src + (size_t)(rb + row) * K + k0 + seg * 8);
            }
        }
    };

    load_chunk(0);
    asm volatile("cp.async.commit_group;" ::: "memory");
    load_chunk(1);
    asm volatile("cp.async.commit_group;" ::: "memory");

    // precomputed intra-tile ldsm offsets
    const int aRowOff = warpM * 32 + (lane & 15);
    const int aKbase  = (lane >> 4) << 4;                 // bytes
    const int bRowOff = warpN * 64 + (lane & 7) + ((lane >> 1) & 8);
    const int bKbase  = ((lane >> 3) & 1) * 16;           // bytes

    for (int c = 0; c < kc; c++) {
        asm volatile("cp.async.wait_group 1;" ::: "memory");
        __syncthreads();
        if (c + 2 < kc) load_chunk(c + 2);
        asm volatile("cp.async.commit_group;" ::: "memory");

        const uint32_t stb = sb + (uint32_t)(c % 3) * STAGE4_B;
        const uint32_t sAh = stb, sAl = stb + ATILE_B;
        const uint32_t sBh = stb + 2u * ATILE_B, sBl = stb + 3u * ATILE_B;
#pragma unroll
        for (int s = 0; s < 4; s++) {
            const int akb = s * 32 + aKbase;
            const int bkb = s * 32 + bKbase;
            uint32_t ah[2][4], al[2][4];
#pragma unroll
            for (int mt = 0; mt < 2; mt++) {
                int ro = (aRowOff + mt * 16) * 128;
                ldsm4(ah[mt][0], ah[mt][1], ah[mt][2], ah[mt][3], sAh + SWZ128(ro + akb));
                ldsm4(al[mt][0], al[mt][1], al[mt][2], al[mt][3], sAl + SWZ128(ro + akb));
            }
            uint32_t bh[8][2], bl[8][2];
#pragma unroll
            for (int p = 0; p < 4; p++) {
                int ro = (bRowOff + p * 16) * 128;
                uint32_t r0, r1, r2, r3;
                ldsm4(r0, r1, r2, r3, sBh + SWZ128(ro + bkb));
                bh[p*2][0] = r0; bh[p*2][1] = r1; bh[p*2+1][0] = r2; bh[p*2+1][1] = r3;
                ldsm4(r0, r1, r2, r3, sBl + SWZ128(ro + bkb));
                bl[p*2][0] = r0; bl[p*2][1] = r1; bl[p*2+1][0] = r2; bl[p*2+1][1] = r3;
            }
            // 3 split phases on resident fragments
#pragma unroll
            for (int mt = 0; mt < 2; mt++)
#pragma unroll
                for (int nt = 0; nt < 8; nt++)
                    mma16816(acc[mt][nt], ah[mt], bh[nt]);
#pragma unroll
            for (int mt = 0; mt < 2; mt++)
#pragma unroll
                for (int nt = 0; nt < 8; nt++)
                    mma16816(acc[mt][nt], ah[mt], bl[nt]);
#pragma unroll
            for (int mt = 0; mt < 2; mt++)
#pragma unroll
                for (int nt = 0; nt < 8; nt++)
                    mma16816(acc[mt][nt], al[mt], bh[nt]);
        }
    }

    // epilogue
    const int row0 = m0 + warpM * 32 + (lane >> 2);
    const int col0 = n0 + warpN * 64 + (lane & 3) * 2;
#pragma unroll
    for (int mt = 0; mt < 2; mt++) {
#pragma unroll
        for (int nt = 0; nt < 8; nt++) {
            int r1 = row0 + mt * 16;
            int c1 = col0 + nt * 8;
            float v0 = acc[mt][nt][0], v1 = acc[mt][nt][1];
            float v2 = acc[mt][nt][2], v3 = acc[mt][nt][3];
            if (MODE == 0) {
                float* Cf = bp.Of[path];
                *reinterpret_cast<float2*>(&Cf[(size_t)r1 * Cc + c1]) = make_float2(v0, v1);
                *reinterpret_cast<float2*>(&Cf[(size_t)(r1 + 8) * Cc + c1]) = make_float2(v2, v3);
            } else if (MODE == 1) {
                if (path == 0) { v0 = tanhf(v0); v1 = tanhf(v1); v2 = tanhf(v2); v3 = tanhf(v3); }
                else if (path == 3) {
                    v0 = 1.f/(1.f+expf(-v0)); v1 = 1.f/(1.f+expf(-v1));
                    v2 = 1.f/(1.f+expf(-v2)); v3 = 1.f/(1.f+expf(-v3));
                }
                uint16_t* oh = bp.Oh[path]; uint16_t* ol = bp.Ol[path];
                split_store(v0, oh, ol, (size_t)r1 * LORA_PAD + c1);
                split_store(v1, oh, ol, (size_t)r1 * LORA_PAD + c1 + 1);
                split_store(v2, oh, ol, (size_t)(r1 + 8) * LORA_PAD + c1);
                split_store(v3, oh, ol, (size_t)(r1 + 8) * LORA_PAD + c1 + 1);
            } else {
                auto ep = [&](float z, int rr_, int cc_) {
                    size_t idx = (size_t)rr_ * Cc + cc_;
                    if (path == 0) {
                        float zz = bp.bias[0][cc_] + z;
                        float nz = -zz;
                        float sp = (nz > 20.f) ? nz : log1pf(expf(nz));
                        bp.Of[0][idx] = expf(-expf(-sp - 0.5f));
                    } else if (path == 1) {
                        bp.Of[1][idx] = 1.f / (1.f + expf(-(bp.bias[1][cc_] + z)));
                    } else if (path == 2) {
                        float s = 1.f / (1.f + expf(-(bp.bias[2][cc_] + z)));
                        float vv = bp.Of[2][idx];
                        bp.Of[2][idx] = (vv + (bp.vf[idx] - vv) * s) * bp.mask[rr_];
                    } else {
                        bp.Of[3][idx] = z;
                    }
                };
                ep(v0, r1, c1); ep(v1, r1, c1 + 1);
                ep(v2, r1 + 8, c1); ep(v3, r1 + 8, c1 + 1);
            }
        }
    }
}

// ---------------- kk normalize + k rescale ----------------
__global__ void kk_kernel(const float* __restrict__ kkp, const float* __restrict__ kap,
                          const float* __restrict__ asig,
                          float* __restrict__ k, float* __restrict__ kk)
{
    int gid = blockIdx.x * 8 + (threadIdx.x >> 5);
    int lane = threadIdx.x & 31;
    int h = gid % Hh;
    size_t bt = gid / Hh;
    size_t base = bt * Cc + (size_t)h * Nn;
    int c0 = h * Nn + lane, c1 = c0 + 32;
    float k0v = k[base + lane], k1v = k[base + lane + 32];
    float kk0 = k0v * kkp[c0], kk1 = k1v * kkp[c1];
    float ss = kk0 * kk0 + kk1 * kk1;
#pragma unroll
    for (int o = 16; o > 0; o >>= 1) ss += __shfl_xor_sync(0xffffffffu, ss, o);
    float inv = 1.f / fmaxf(sqrtf(ss), 1e-12f);
    kk[base + lane]      = kk0 * inv;
    kk[base + lane + 32] = kk1 * inv;
    float a0v = asig[base + lane], a1v = asig[base + lane + 32];
    k[base + lane]      = k0v * (1.f + (a0v - 1.f) * kap[c0]);
    k[base + lane + 32] = k1v * (1.f + (a1v - 1.f) * kap[c1]);
}

// ---------------- RWKV-7 scan ----------------
__global__ __launch_bounds__(128)
void scan_kernel(const float* __restrict__ r, const float* __restrict__ wdec,
                 const float* __restrict__ k, const float* __restrict__ v,
                 const float* __restrict__ kk, const float* __restrict__ asig,
                 float* __restrict__ y)
{
    int bh = blockIdx.x;
    int b = bh >> 5, h = bh & 31;
    int tid = threadIdx.x;
    int j = tid >> 1, half = tid & 1;
    __shared__ float4 sWB[2][32];
    __shared__ float4 sKR[2][32];
    __shared__ float2 sA2[2][32];
    u64t S[16];
#pragma unroll
    for (int i = 0; i < 16; i++) S[i] = 0ull;
    size_t base0 = ((size_t)b * Tt) * Cc + (size_t)h * Nn;

    float pw = 0.f, pb = 0.f, pkv = 0.f, prv = 0.f, pa = 0.f;
    if (tid < 64) {
        size_t ba = base0 + tid;
        float kkv = kk[ba];
        pw = wdec[ba]; pb = kkv * asig[ba]; pkv = k[ba]; prv = r[ba]; pa = -kkv;
    }
    float pvj = v[base0 + j];

    for (int t = 0; t < Tt; t++) {
        int buf = t & 1;
        if (tid < 64) {
            int hi_ = tid >> 1, par = tid & 1;
            float* pWB = reinterpret_cast<float*>(&sWB[buf][hi_]);
            pWB[par] = pw; pWB[2 + par] = pb;
            float* pKR = reinterpret_cast<float*>(&sKR[buf][hi_]);
            pKR[par] = pkv; pKR[2 + par] = prv;
            reinterpret_cast<float*>(&sA2[buf][hi_])[par] = pa;
        }
        float vj = pvj;
        __syncthreads();
        if (t + 1 < Tt) {
            if (tid < 64) {
                size_t ba = base0 + (size_t)(t + 1) * Cc + tid;
                float kkv = kk[ba];
                pw = wdec[ba]; pb = kkv * asig[ba]; pkv = k[ba]; prv = r[ba]; pa = -kkv;
            }
            pvj = v[base0 + (size_t)(t + 1) * Cc + j];
        }
        int i0 = half * 16;
        u64t a0 = 0ull, a1 = 0ull, a2 = 0ull, a3 = 0ull;
#pragma unroll
        for (int ii = 0; ii < 16; ii += 4) {
            a0 = fma2(S[ii + 0], *reinterpret_cast<u64t*>(&sA2[buf][i0 + ii + 0]), a0);
            a1 = fma2(S[ii + 1], *reinterpret_cast<u64t*>(&sA2[buf][i0 + ii + 1]), a1);
            a2 = fma2(S[ii + 2], *reinterpret_cast<u64t*>(&sA2[buf][i0 + ii + 2]), a2);
            a3 = fma2(S[ii + 3], *reinterpret_cast<u64t*>(&sA2[buf][i0 + ii + 3]), a3);
        }
        float ax, ay, bx, by, cx, cy, dx, dy;
        upk2(a0, ax, ay); upk2(a1, bx, by); upk2(a2, cx, cy); upk2(a3, dx, dy);
        float sacc = ((ax + ay) + (bx + by)) + ((cx + cy) + (dx + dy));
        sacc += __shfl_xor_sync(0xffffffffu, sacc, 1);
        u64t sacc2 = pk2(sacc, sacc);
        u64t vj2 = pk2(vj, vj);
        u64t ya = 0ull, yb = 0ull;
#pragma unroll
        for (int ii = 0; ii < 16; ii += 2) {
            float4 wb0 = sWB[buf][i0 + ii], kr0 = sKR[buf][i0 + ii];
            u64t s0 = fma2(S[ii], pk2(wb0.x, wb0.y),
                           fma2(sacc2, pk2(wb0.z, wb0.w), mul2(vj2, pk2(kr0.x, kr0.y))));
            S[ii] = s0;
            ya = fma2(s0, pk2(kr0.z, kr0.w), ya);
            float4 wb1 = sWB[buf][i0 + ii + 1], kr1 = sKR[buf][i0 + ii + 1];
            u64t s1 = fma2(S[ii + 1], pk2(wb1.x, wb1.y),
                           fma2(sacc2, pk2(wb1.z, wb1.w), mul2(vj2, pk2(kr1.x, kr1.y))));
            S[ii + 1] = s1;
            yb = fma2(s1, pk2(kr1.z, kr1.w), yb);
        }
        float y0x, y0y, y1x, y1y;
        upk2(ya, y0x, y0y); upk2(yb, y1x, y1y);
        float yv = (y0x + y0y) + (y1x + y1y);
        yv += __shfl_xor_sync(0xffffffffu, yv, 1);
        if (half == 0) y[base0 + (size_t)t * Cc + j] = yv;
    }
}

// ---------------- groupnorm + rk*v + gate -> split bf16 ----------------
__global__ void post_kernel(const float* __restrict__ y, const float* __restrict__ r,
                            const float* __restrict__ k, const float* __restrict__ v,
                            const float* __restrict__ g, const float* __restrict__ r_k,
                            const float* __restrict__ ln_w, const float* __restrict__ ln_b,
                            uint16_t* __restrict__ oh, uint16_t* __restrict__ ol)
{
    int gid = blockIdx.x * 8 + (threadIdx.x >> 5);
    int lane = threadIdx.x & 31;
    int h = gid % Hh;
    size_t bt = gid / Hh;
    size_t base = bt * Cc + (size_t)h * Nn;
    int c0 = h * Nn + lane, c1 = c0 + 32;
    float y0 = y[base + lane], y1 = y[base + lane + 32];
    float sum = y0 + y1;
#pragma unroll
    for (int o = 16; o > 0; o >>= 1) sum += __shfl_xor_sync(0xffffffffu, sum, o);
    float mean = sum * (1.f / 64.f);
    float d0 = y0 - mean, d1 = y1 - mean;
    float var = d0 * d0 + d1 * d1;
#pragma unroll
    for (int o = 16; o > 0; o >>= 1) var += __shfl_xor_sync(0xffffffffu, var, o);
    var *= (1.f / 64.f);
    float inv = rsqrtf(var + LN_EPS);
    float yn0 = d0 * inv * ln_w[c0] + ln_b[c0];
    float yn1 = d1 * inv * ln_w[c1] + ln_b[c1];
    float rk = r[base + lane] * k[base + lane] * r_k[c0]
             + r[base + lane + 32] * k[base + lane + 32] * r_k[c1];
#pragma unroll
    for (int o = 16; o > 0; o >>= 1) rk += __shfl_xor_sync(0xffffffffu, rk, o);
    float o0 = (yn0 + rk * v[base + lane]) * g[base + lane];
    float o1 = (yn1 + rk * v[base + lane + 32]) * g[base + lane + 32];
    split_store(o0, oh, ol, base + lane);
    split_store(o1, oh, ol, base + lane + 32);
}

// ---------------- launch ----------------
#define GETSYM(var, sym) do { void* _p; cudaGetSymbolAddress(&_p, sym); var = (decltype(var))_p; } while (0)

extern "C" void kernel_launch(void* const* d_in, const int* in_sizes, int n_in,
                              void* d_out, int out_size)
{
    const float* x       = (const float*)d_in[0];
    const float* mask    = (const float*)d_in[1];
    const float* v_first = (const float*)d_in[2];
    const float* x_r = (const float*)d_in[3];
    const float* x_w = (const float*)d_in[4];
    const float* x_k = (const float*)d_in[5];
    const float* x_v = (const float*)d_in[6];
    const float* x_a = (const float*)d_in[7];
    const float* x_g = (const float*)d_in[8];
    const float* w0 = (const float*)d_in[9];
    const float* w1 = (const float*)d_in[10];
    const float* w2 = (const float*)d_in[11];
    const float* a0 = (const float*)d_in[12];
    const float* a1 = (const float*)d_in[13];
    const float* a2 = (const float*)d_in[14];
    const float* v0 = (const float*)d_in[15];
    const float* v1 = (const float*)d_in[16];
    const float* v2 = (const float*)d_in[17];
    const float* g1 = (const float*)d_in[18];
    const float* g2 = (const float*)d_in[19];
    const float* k_k = (const float*)d_in[20];
    const float* k_a = (const float*)d_in[21];
    const float* r_k = (const float*)d_in[22];
    const float* W_r = (const float*)d_in[23];
    const float* W_k = (const float*)d_in[24];
    const float* W_v = (const float*)d_in[25];
    const float* W_o = (const float*)d_in[26];
    const float* ln_w = (const float*)d_in[27];
    const float* ln_b = (const float*)d_in[28];
    float* out = (float*)d_out;

    float *rr, *kb, *vb, *wd, *as, *gg, *kkb, *yb;
    GETSYM(rr, g_r); GETSYM(kb, g_k); GETSYM(vb, g_v);
    GETSYM(wd, g_wdec); GETSYM(as, g_asig); GETSYM(gg, g_g);
    GETSYM(kkb, g_kk); GETSYM(yb, g_y);
    uint16_t *xrh,*xrl,*xwh,*xwl,*xkh,*xkl,*xvh,*xvl,*xah,*xal,*xgh,*xgl,*ygh,*ygl;
    GETSYM(xrh, g_xrh); GETSYM(xrl, g_xrl); GETSYM(xwh, g_xwh); GETSYM(xwl, g_xwl);
    GETSYM(xkh, g_xkh); GETSYM(xkl, g_xkl); GETSYM(xvh, g_xvh); GETSYM(xvl, g_xvl);
    GETSYM(xah, g_xah); GETSYM(xal, g_xal); GETSYM(xgh, g_xgh); GETSYM(xgl, g_xgl);
    GETSYM(ygh, g_ygh); GETSYM(ygl, g_ygl);
    uint16_t *Wrh,*Wrl,*Wkh,*Wkl,*Wvh,*Wvl,*Woh,*Wol;
    GETSYM(Wrh, g_Wrh); GETSYM(Wrl, g_Wrl); GETSYM(Wkh, g_Wkh); GETSYM(Wkl, g_Wkl);
    GETSYM(Wvh, g_Wvh); GETSYM(Wvl, g_Wvl); GETSYM(Woh, g_Woh); GETSYM(Wol, g_Wol);
    uint16_t *l1h, *l1l, *l2h, *l2l, *tsh, *tsl;
    GETSYM(l1h, g_l1h); GETSYM(l1l, g_l1l); GETSYM(l2h, g_l2h); GETSYM(l2l, g_l2l);
    GETSYM(tsh, g_tsh); GETSYM(tsl, g_tsl);

    cudaFuncSetAttribute(mma_gemm<0>, cudaFuncAttributeMaxDynamicSharedMemorySize, GEMM_SMEM);
    cudaFuncSetAttribute(mma_gemm<1>, cudaFuncAttributeMaxDynamicSharedMemorySize, GEMM_SMEM);
    cudaFuncSetAttribute(mma_gemm<2>, cudaFuncAttributeMaxDynamicSharedMemorySize, GEMM_SMEM);

    // 1: prep
    prep_kernel<<<dim3(BT, 2), 256>>>(x, mask, x_r, x_w, x_k, x_v, x_a, x_g);
    // 2: big weight splits
    wsplit_kernel<<<(Cc * Cc) / 1024, 256>>>(W_r, W_k, W_v, W_o);
    // 3: LoRA weight splits
    LoraSrc ls;
    ls.s1[0] = w1; ls.s1[1] = a1; ls.s1[2] = v1; ls.s1[3] = g1;
    ls.s2[0] = w2; ls.s2[1] = a2; ls.s2[2] = v2; ls.s2[3] = g2;
    lsplit_kernel<<<dim3(1024, 8), 256>>>(ls);

    // 4: batched r,k,v projections (one launch, 3072 CTAs)
    GemmB b0 = {};
    b0.Ah[0] = xrh; b0.Al[0] = xrl; b0.Bh[0] = Wrh; b0.Bl[0] = Wrl; b0.Of[0] = rr;
    b0.Ah[1] = xkh; b0.Al[1] = xkl; b0.Bh[1] = Wkh; b0.Bl[1] = Wkl; b0.Of[1] = kb;
    b0.Ah[2] = xvh; b0.Al[2] = xvl; b0.Bh[2] = Wvh; b0.Bl[2] = Wvl; b0.Of[2] = vb;
    mma_gemm<0><<<dim3(48, 64), 256, GEMM_SMEM>>>(b0, Cc);

    // 5: batched LoRA stage 1 (w,a,v,g)
    GemmB b1 = {};
    const size_t L1 = (size_t)LORA_PAD * Cc, L2 = (size_t)Cc * LORA_PAD;
    const size_t TS = (size_t)BT * LORA_PAD;
    b1.Ah[0] = xwh; b1.Al[0] = xwl; b1.Ah[1] = xah; b1.Al[1] = xal;
    b1.Ah[2] = xvh; b1.Al[2] = xvl; b1.Ah[3] = xgh; b1.Al[3] = xgl;
    for (int p = 0; p < 4; p++) {
        b1.Bh[p] = l1h + p * L1; b1.Bl[p] = l1l + p * L1;
        b1.Oh[p] = tsh + p * TS; b1.Ol[p] = tsl + p * TS;
    }
    mma_gemm<1><<<dim3(4, 64), 256, GEMM_SMEM>>>(b1, Cc);

    // 6: batched LoRA stage 2 with fused elementwise epilogues
    GemmB b2 = {};
    for (int p = 0; p < 4; p++) {
        b2.Ah[p] = tsh + p * TS; b2.Al[p] = tsl + p * TS;
        b2.Bh[p] = l2h + p * L2; b2.Bl[p] = l2l + p * L2;
    }
    b2.Of[0] = wd; b2.Of[1] = as; b2.Of[2] = vb; b2.Of[3] = gg;
    b2.bias[0] = w0; b2.bias[1] = a0; b2.bias[2] = v0; b2.bias[3] = w0;
    b2.vf = v_first; b2.mask = mask;
    mma_gemm<2><<<dim3(64, 64), 256, GEMM_SMEM>>>(b2, LORA_PAD);

    // 7-9: kk, scan, post
    kk_kernel<<<(BT * Hh) / 8, 256>>>(k_k, k_a, as, kb, kkb);
    scan_kernel<<<Bb * Hh, 128>>>(rr, wd, kb, vb, kkb, as, yb);
    post_kernel<<<(BT * Hh) / 8, 256>>>(yb, rr, kb, vb, gg, r_k, ln_w, ln_b, ygh, ygl);

    // 10: output projection
    GemmB bo = {};
    bo.Ah[0] = ygh; bo.Al[0] = ygl; bo.Bh[0] = Woh; bo.Bl[0] = Wol; bo.Of[0] = out;
    mma_gemm<0><<<dim3(16, 64), 256, GEMM_SMEM>>>(bo, Cc);

    // 11: v_first passthrough
    if ((size_t)out_size >= 2 * BTC) {
        cudaMemcpyAsync(out + BTC, v_first, BTC * sizeof(float), cudaMemcpyDeviceToDevice);
    }
}

// round 8
// speedup vs baseline: 3.3435x; 1.3000x over previous
#include <cuda_runtime.h>
#include <cuda_bf16.h>
#include <cuda_fp16.h>
#include <cstdint>

// ---------------- problem constants ----------------
#define Bb 8
#define Tt 1024
#define Cc 2048
#define Hh 32
#define Nn 64
#define BT (Bb*Tt)                  // 8192
#define BTC ((size_t)BT*Cc)         // 16.7M
#define LORA_PAD 128
#define LN_EPS (1e-5f*64.0f)

// ---------------- scratch (device globals) ----------------
__device__ float g_r[BTC], g_k[BTC], g_v[BTC];
__device__ float g_wdec[BTC], g_asig[BTC], g_g[BTC], g_kk[BTC], g_y[BTC];

// fp16 activations (A operands)
__device__ uint16_t g_xr[BTC], g_xw[BTC], g_xk[BTC], g_xv[BTC], g_xa[BTC], g_xg[BTC];
__device__ uint16_t g_yg[BTC];
// fp16 split weights (B operands)
__device__ uint16_t g_Wrh[Cc*Cc], g_Wrl[Cc*Cc], g_Wkh[Cc*Cc], g_Wkl[Cc*Cc];
__device__ uint16_t g_Wvh[Cc*Cc], g_Wvl[Cc*Cc], g_Woh[Cc*Cc], g_Wol[Cc*Cc];
// LoRA weights: stage1 [4][128 x 2048], stage2 [4][2048 x 128]
__device__ uint16_t g_l1h[4][LORA_PAD*Cc], g_l1l[4][LORA_PAD*Cc];
__device__ uint16_t g_l2h[4][Cc*LORA_PAD], g_l2l[4][Cc*LORA_PAD];
// LoRA stage-1 outputs (fp16 single) [4][8192 x 128]
__device__ uint16_t g_ts[4][(size_t)BT*LORA_PAD];

// ---------------- helpers ----------------
__device__ __forceinline__ void h1store(float v, uint16_t* dst, size_t i) {
    reinterpret_cast<__half*>(dst)[i] = __float2half_rn(v);
}
__device__ __forceinline__ void h4store(float4 v, uint16_t* dst, size_t i) {
    __half2 a = __floats2half2_rn(v.x, v.y);
    __half2 b = __floats2half2_rn(v.z, v.w);
    *reinterpret_cast<uint2*>(dst + i) =
        make_uint2(*reinterpret_cast<uint32_t*>(&a), *reinterpret_cast<uint32_t*>(&b));
}
__device__ __forceinline__ void hsplit1(float v, uint16_t* hi, uint16_t* lo, size_t i) {
    __half h = __float2half_rn(v);
    float hf = __half2float(h);
    __half l = __float2half_rn(v - hf);
    reinterpret_cast<__half*>(hi)[i] = h;
    reinterpret_cast<__half*>(lo)[i] = l;
}
__device__ __forceinline__ void hsplit4(float4 v, uint16_t* hi, uint16_t* lo, size_t i) {
    __half2 h0 = __floats2half2_rn(v.x, v.y), h1 = __floats2half2_rn(v.z, v.w);
    float2 f0 = __half22float2(h0), f1 = __half22float2(h1);
    __half2 l0 = __floats2half2_rn(v.x - f0.x, v.y - f0.y);
    __half2 l1 = __floats2half2_rn(v.z - f1.x, v.w - f1.y);
    *reinterpret_cast<uint2*>(hi + i) =
        make_uint2(*reinterpret_cast<uint32_t*>(&h0), *reinterpret_cast<uint32_t*>(&h1));
    *reinterpret_cast<uint2*>(lo + i) =
        make_uint2(*reinterpret_cast<uint32_t*>(&l0), *reinterpret_cast<uint32_t*>(&l1));
}

__device__ __forceinline__ uint32_t smem_u32(const void* p) {
    uint32_t a;
    asm("{ .reg .u64 t; cvta.to.shared.u64 t, %1; cvt.u32.u64 %0, t; }" : "=r"(a) : "l"(p));
    return a;
}
#define SWZ128(o) ((o) ^ (((o) >> 3) & 0x70))

__device__ __forceinline__ void cpa16(uint32_t daddr, const void* g)
{
    asm volatile("cp.async.cg.shared.global [%0], [%1], 16;"
                 :: "r"(daddr), "l"(__cvta_generic_to_global(g)) : "memory");
}

__device__ __forceinline__ void ldsm4(uint32_t& r0, uint32_t& r1, uint32_t& r2, uint32_t& r3,
                                      uint32_t addr)
{
    asm volatile("ldmatrix.sync.aligned.m8n8.x4.shared.b16 {%0,%1,%2,%3}, [%4];"
                 : "=r"(r0), "=r"(r1), "=r"(r2), "=r"(r3) : "r"(addr));
}

__device__ __forceinline__ void mma16816(float* c, const uint32_t* a, const uint32_t* b)
{
    asm volatile("mma.sync.aligned.m16n8k16.row.col.f32.f16.f16.f32 "
                 "{%0,%1,%2,%3}, {%4,%5,%6,%7}, {%8,%9}, {%0,%1,%2,%3};"
                 : "+f"(c[0]), "+f"(c[1]), "+f"(c[2]), "+f"(c[3])
                 : "r"(a[0]), "r"(a[1]), "r"(a[2]), "r"(a[3]), "r"(b[0]), "r"(b[1]));
}

// packed f32x2 (sm_100+)
typedef unsigned long long u64t;
__device__ __forceinline__ u64t pk2(float x, float y){ u64t d; asm("mov.b64 %0, {%1,%2};" : "=l"(d) : "f"(x), "f"(y)); return d; }
__device__ __forceinline__ void upk2(u64t d, float& x, float& y){ asm("mov.b64 {%0,%1}, %2;" : "=f"(x), "=f"(y) : "l"(d)); }
__device__ __forceinline__ u64t fma2(u64t a, u64t b, u64t c){ u64t d; asm("fma.rn.f32x2 %0, %1, %2, %3;" : "=l"(d) : "l"(a), "l"(b), "l"(c)); return d; }
__device__ __forceinline__ u64t mul2(u64t a, u64t b){ u64t d; asm("mul.rn.f32x2 %0, %1, %2;" : "=l"(d) : "l"(a), "l"(b)); return d; }

// ---------------- prep: mask + time-shift mixes -> fp16 ----------------
__global__ void prep_kernel(const float* __restrict__ x, const float* __restrict__ mask,
                            const float* __restrict__ mr, const float* __restrict__ mw,
                            const float* __restrict__ mk, const float* __restrict__ mv,
                            const float* __restrict__ ma, const float* __restrict__ mg)
{
    int bt = blockIdx.x;
    int c  = blockIdx.y * 1024 + threadIdx.x * 4;
    int t  = bt & (Tt - 1);
    float m  = mask[bt];
    float mp = (t > 0) ? mask[bt - 1] : 0.f;
    size_t idx = (size_t)bt * Cc + c;
    float4 xv = *reinterpret_cast<const float4*>(&x[idx]);
    float4 xp = make_float4(0.f, 0.f, 0.f, 0.f);
    if (t > 0) xp = *reinterpret_cast<const float4*>(&x[idx - Cc]);
    float4 xm = make_float4(xv.x*m, xv.y*m, xv.z*m, xv.w*m);
    float4 xx = make_float4(xp.x*mp - xm.x, xp.y*mp - xm.y, xp.z*mp - xm.z, xp.w*mp - xm.w);
#define MIX(MM, DD) { \
    float4 mm = *reinterpret_cast<const float4*>(&MM[c]); \
    float4 vv = make_float4(xm.x + xx.x*mm.x, xm.y + xx.y*mm.y, xm.z + xx.z*mm.z, xm.w + xx.w*mm.w); \
    h4store(vv, DD, idx); }
    MIX(mr, g_xr); MIX(mw, g_xw); MIX(mk, g_xk);
    MIX(mv, g_xv); MIX(ma, g_xa); MIX(mg, g_xg);
#undef MIX
}

__global__ void wsplit_kernel(const float* __restrict__ Wr, const float* __restrict__ Wk,
                              const float* __restrict__ Wv, const float* __restrict__ Wo)
{
    size_t i = ((size_t)blockIdx.x * 256 + threadIdx.x) * 4;
    hsplit4(*reinterpret_cast<const float4*>(&Wr[i]), g_Wrh, g_Wrl, i);
    hsplit4(*reinterpret_cast<const float4*>(&Wk[i]), g_Wkh, g_Wkl, i);
    hsplit4(*reinterpret_cast<const float4*>(&Wv[i]), g_Wvh, g_Wvl, i);
    hsplit4(*reinterpret_cast<const float4*>(&Wo[i]), g_Woh, g_Wol, i);
}

struct LoraSrc { const float* s1[4]; const float* s2[4]; };
__constant__ int c_D[4] = {96, 96, 64, 128};

__global__ void lsplit_kernel(LoraSrc ls)
{
    int id = blockIdx.y;
    int i = blockIdx.x * 256 + threadIdx.x;
    if (id < 4) {
        int D = c_D[id];
        int n = i >> 11, kcol = i & 2047;
        float v = (n < D) ? ls.s1[id][(size_t)kcol * D + n] : 0.f;
        hsplit1(v, g_l1h[id], g_l1l[id], i);
    } else {
        int p = id - 4;
        int D = c_D[p];
        int n = i >> 7, kcol = i & 127;
        float v = (kcol < D) ? ls.s2[p][(size_t)kcol * Cc + n] : 0.f;
        hsplit1(v, g_l2h[p], g_l2l[p], i);
    }
}

// ---------------- GEMM: 2-term fp16 (A single, B split), 4-stage pipeline -------
// MODE 0: batched fp32 out [*,2048] (grid (16*P,64), path=x>>4).
// MODE 1: batched LoRA stage1 (grid (4,64)), fp16 out [*,128], tanh(p0)/sigmoid(p3).
// MODE 2: batched LoRA stage2 (grid (16*P,64)), fused elementwise by etype.
#define ATILE_B 16384
#define STAGE3_B (3*ATILE_B)        // 48KB
#define GEMM_SMEM (4*STAGE3_B)      // 192KB

struct GemmB {
    const uint16_t *Aa[4], *Bh[4], *Bl[4];
    uint16_t *Oh[4];
    float *Of[4];
    const float *bias[4];
    int etype[4];                   // MODE2: 0=wdec 1=asig 2=vupd 3=copy
    const float *vf, *mask;
};

template<int MODE>
__global__ __launch_bounds__(256, 1)
void mma_gemm(GemmB bp, int K)
{
    extern __shared__ char smem[];
    const uint32_t sb = smem_u32(smem);
    const int tid = threadIdx.x, lane = tid & 31, warp = tid >> 5;
    const int warpM = warp >> 1, warpN = warp & 1;
    const int m0 = blockIdx.y * 128;
    int n0, path;
    if (MODE == 1) { path = blockIdx.x;      n0 = 0; }
    else           { path = blockIdx.x >> 4; n0 = (blockIdx.x & 15) * 128; }
    const uint16_t* Aa  = bp.Aa[path];
    const uint16_t* Bhi = bp.Bh[path];
    const uint16_t* Blo = bp.Bl[path];
    const int kc = K >> 6;

    float acc[2][8][4];
#pragma unroll
    for (int mt = 0; mt < 2; mt++)
#pragma unroll
        for (int nt = 0; nt < 8; nt++)
#pragma unroll
            for (int e = 0; e < 4; e++) acc[mt][nt][e] = 0.f;

    auto load_chunk = [&](int c) {
        const uint32_t stb = sb + (uint32_t)(c & 3) * STAGE3_B;
        const int k0 = c << 6;
        const uint16_t* srcs[3] = {Aa, Bhi, Blo};
#pragma unroll
        for (int a3 = 0; a3 < 3; a3++) {
            const uint16_t* src = srcs[a3];
            const int rb = (a3 == 0) ? m0 : n0;
            const uint32_t ab = stb + a3 * ATILE_B;
#pragma unroll
            for (int jj = 0; jj < 4; jj++) {
                int T = tid + jj * 256;
                int row = T >> 3, seg = T & 7;
                cpa16(ab + SWZ128(row * 128 + seg * 16),
                      src + (size_t)(rb + row) * K + k0 + seg * 8);
            }
        }
    };

    load_chunk(0);
    asm volatile("cp.async.commit_group;" ::: "memory");
    if (1 < kc) load_chunk(1);
    asm volatile("cp.async.commit_group;" ::: "memory");
    if (2 < kc) load_chunk(2);
    asm volatile("cp.async.commit_group;" ::: "memory");

    const int aRowOff = warpM * 32 + (lane & 15);
    const int aKbase  = (lane >> 4) << 4;
    const int bRowOff = warpN * 64 + (lane & 7) + ((lane >> 1) & 8);
    const int bKbase  = ((lane >> 3) & 1) * 16;

    for (int c = 0; c < kc; c++) {
        asm volatile("cp.async.wait_group 2;" ::: "memory");
        __syncthreads();
        if (c + 3 < kc) load_chunk(c + 3);
        asm volatile("cp.async.commit_group;" ::: "memory");

        const uint32_t stb = sb + (uint32_t)(c & 3) * STAGE3_B;
        const uint32_t sA = stb, sBh = stb + ATILE_B, sBl = stb + 2u * ATILE_B;
#pragma unroll
        for (int s = 0; s < 4; s++) {
            const int akb = s * 32 + aKbase;
            const int bkb = s * 32 + bKbase;
            uint32_t a[2][4];
#pragma unroll
            for (int mt = 0; mt < 2; mt++) {
                int ro = (aRowOff + mt * 16) * 128;
                ldsm4(a[mt][0], a[mt][1], a[mt][2], a[mt][3], sA + SWZ128(ro + akb));
            }
            uint32_t bh[8][2], bl[8][2];
#pragma unroll
            for (int p = 0; p < 4; p++) {
                int ro = (bRowOff + p * 16) * 128;
                uint32_t r0, r1, r2, r3;
                ldsm4(r0, r1, r2, r3, sBh + SWZ128(ro + bkb));
                bh[p*2][0] = r0; bh[p*2][1] = r1; bh[p*2+1][0] = r2; bh[p*2+1][1] = r3;
                ldsm4(r0, r1, r2, r3, sBl + SWZ128(ro + bkb));
                bl[p*2][0] = r0; bl[p*2][1] = r1; bl[p*2+1][0] = r2; bl[p*2+1][1] = r3;
            }
#pragma unroll
            for (int mt = 0; mt < 2; mt++)
#pragma unroll
                for (int nt = 0; nt < 8; nt++)
                    mma16816(acc[mt][nt], a[mt], bh[nt]);
#pragma unroll
            for (int mt = 0; mt < 2; mt++)
#pragma unroll
                for (int nt = 0; nt < 8; nt++)
                    mma16816(acc[mt][nt], a[mt], bl[nt]);
        }
    }

    // epilogue
    const int row0 = m0 + warpM * 32 + (lane >> 2);
    const int col0 = n0 + warpN * 64 + (lane & 3) * 2;
    const int et = (MODE == 2) ? bp.etype[path] : 0;
#pragma unroll
    for (int mt = 0; mt < 2; mt++) {
#pragma unroll
        for (int nt = 0; nt < 8; nt++) {
            int r1 = row0 + mt * 16;
            int c1 = col0 + nt * 8;
            float v0 = acc[mt][nt][0], v1 = acc[mt][nt][1];
            float v2 = acc[mt][nt][2], v3 = acc[mt][nt][3];
            if (MODE == 0) {
                float* Cf = bp.Of[path];
                *reinterpret_cast<float2*>(&Cf[(size_t)r1 * Cc + c1]) = make_float2(v0, v1);
                *reinterpret_cast<float2*>(&Cf[(size_t)(r1 + 8) * Cc + c1]) = make_float2(v2, v3);
            } else if (MODE == 1) {
                if (path == 0) { v0 = tanhf(v0); v1 = tanhf(v1); v2 = tanhf(v2); v3 = tanhf(v3); }
                else if (path == 3) {
                    v0 = 1.f/(1.f+expf(-v0)); v1 = 1.f/(1.f+expf(-v1));
                    v2 = 1.f/(1.f+expf(-v2)); v3 = 1.f/(1.f+expf(-v3));
                }
                uint16_t* oh = bp.Oh[path];
                h1store(v0, oh, (size_t)r1 * LORA_PAD + c1);
                h1store(v1, oh, (size_t)r1 * LORA_PAD + c1 + 1);
                h1store(v2, oh, (size_t)(r1 + 8) * LORA_PAD + c1);
                h1store(v3, oh, (size_t)(r1 + 8) * LORA_PAD + c1 + 1);
            } else {
                float* Of = bp.Of[path];
                const float* bias = bp.bias[path];
                auto ep = [&](float z, int rr_, int cc_) {
                    size_t idx = (size_t)rr_ * Cc + cc_;
                    if (et == 0) {
                        float zz = bias[cc_] + z;
                        float nz = -zz;
                        float sp = (nz > 20.f) ? nz : log1pf(expf(nz));
                        Of[idx] = expf(-expf(-sp - 0.5f));
                    } else if (et == 1) {
                        Of[idx] = 1.f / (1.f + expf(-(bias[cc_] + z)));
                    } else if (et == 2) {
                        float s = 1.f / (1.f + expf(-(bias[cc_] + z)));
                        float vv = Of[idx];
                        Of[idx] = (vv + (bp.vf[idx] - vv) * s) * bp.mask[rr_];
                    } else {
                        Of[idx] = z;
                    }
                };
                ep(v0, r1, c1); ep(v1, r1, c1 + 1);
                ep(v2, r1 + 8, c1); ep(v3, r1 + 8, c1 + 1);
            }
        }
    }
}

// ---------------- kk normalize + k rescale ----------------
__global__ void kk_kernel(const float* __restrict__ kkp, const float* __restrict__ kap,
                          const float* __restrict__ asig,
                          float* __restrict__ k, float* __restrict__ kk)
{
    int gid = blockIdx.x * 8 + (threadIdx.x >> 5);
    int lane = threadIdx.x & 31;
    int h = gid % Hh;
    size_t bt = gid / Hh;
    size_t base = bt * Cc + (size_t)h * Nn;
    int c0 = h * Nn + lane, c1 = c0 + 32;
    float k0v = k[base + lane], k1v = k[base + lane + 32];
    float kk0 = k0v * kkp[c0], kk1 = k1v * kkp[c1];
    float ss = kk0 * kk0 + kk1 * kk1;
#pragma unroll
    for (int o = 16; o > 0; o >>= 1) ss += __shfl_xor_sync(0xffffffffu, ss, o);
    float inv = 1.f / fmaxf(sqrtf(ss), 1e-12f);
    kk[base + lane]      = kk0 * inv;
    kk[base + lane + 32] = kk1 * inv;
    float a0v = asig[base + lane], a1v = asig[base + lane + 32];
    k[base + lane]      = k0v * (1.f + (a0v - 1.f) * kap[c0]);
    k[base + lane + 32] = k1v * (1.f + (a1v - 1.f) * kap[c1]);
}

// ---------------- RWKV-7 scan ----------------
__global__ __launch_bounds__(128)
void scan_kernel(const float* __restrict__ r, const float* __restrict__ wdec,
                 const float* __restrict__ k, const float* __restrict__ v,
                 const float* __restrict__ kk, const float* __restrict__ asig,
                 float* __restrict__ y)
{
    int bh = blockIdx.x;
    int b = bh >> 5, h = bh & 31;
    int tid = threadIdx.x;
    int j = tid >> 1, half = tid & 1;
    __shared__ float4 sWB[2][32];
    __shared__ float4 sKR[2][32];
    __shared__ float2 sA2[2][32];
    u64t S[16];
#pragma unroll
    for (int i = 0; i < 16; i++) S[i] = 0ull;
    size_t base0 = ((size_t)b * Tt) * Cc + (size_t)h * Nn;

    float pw = 0.f, pb = 0.f, pkv = 0.f, prv = 0.f, pa = 0.f;
    if (tid < 64) {
        size_t ba = base0 + tid;
        float kkv = kk[ba];
        pw = wdec[ba]; pb = kkv * asig[ba]; pkv = k[ba]; prv = r[ba]; pa = -kkv;
    }
    float pvj = v[base0 + j];

    for (int t = 0; t < Tt; t++) {
        int buf = t & 1;
        if (tid < 64) {
            int hi_ = tid >> 1, par = tid & 1;
            float* pWB = reinterpret_cast<float*>(&sWB[buf][hi_]);
            pWB[par] = pw; pWB[2 + par] = pb;
            float* pKR = reinterpret_cast<float*>(&sKR[buf][hi_]);
            pKR[par] = pkv; pKR[2 + par] = prv;
            reinterpret_cast<float*>(&sA2[buf][hi_])[par] = pa;
        }
        float vj = pvj;
        __syncthreads();
        if (t + 1 < Tt) {
            if (tid < 64) {
                size_t ba = base0 + (size_t)(t + 1) * Cc + tid;
                float kkv = kk[ba];
                pw = wdec[ba]; pb = kkv * asig[ba]; pkv = k[ba]; prv = r[ba]; pa = -kkv;
            }
            pvj = v[base0 + (size_t)(t + 1) * Cc + j];
        }
        int i0 = half * 16;
        u64t a0 = 0ull, a1 = 0ull, a2 = 0ull, a3 = 0ull;
#pragma unroll
        for (int ii = 0; ii < 16; ii += 4) {
            a0 = fma2(S[ii + 0], *reinterpret_cast<u64t*>(&sA2[buf][i0 + ii + 0]), a0);
            a1 = fma2(S[ii + 1], *reinterpret_cast<u64t*>(&sA2[buf][i0 + ii + 1]), a1);
            a2 = fma2(S[ii + 2], *reinterpret_cast<u64t*>(&sA2[buf][i0 + ii + 2]), a2);
            a3 = fma2(S[ii + 3], *reinterpret_cast<u64t*>(&sA2[buf][i0 + ii + 3]), a3);
        }
        float ax, ay, bx, by, cx, cy, dx, dy;
        upk2(a0, ax, ay); upk2(a1, bx, by); upk2(a2, cx, cy); upk2(a3, dx, dy);
        float sacc = ((ax + ay) + (bx + by)) + ((cx + cy) + (dx + dy));
        sacc += __shfl_xor_sync(0xffffffffu, sacc, 1);
        u64t sacc2 = pk2(sacc, sacc);
        u64t vj2 = pk2(vj, vj);
        u64t ya = 0ull, yb = 0ull;
#pragma unroll
        for (int ii = 0; ii < 16; ii += 2) {
            float4 wb0 = sWB[buf][i0 + ii], kr0 = sKR[buf][i0 + ii];
            u64t s0 = fma2(S[ii], pk2(wb0.x, wb0.y),
                           fma2(sacc2, pk2(wb0.z, wb0.w), mul2(vj2, pk2(kr0.x, kr0.y))));
            S[ii] = s0;
            ya = fma2(s0, pk2(kr0.z, kr0.w), ya);
            float4 wb1 = sWB[buf][i0 + ii + 1], kr1 = sKR[buf][i0 + ii + 1];
            u64t s1 = fma2(S[ii + 1], pk2(wb1.x, wb1.y),
                           fma2(sacc2, pk2(wb1.z, wb1.w), mul2(vj2, pk2(kr1.x, kr1.y))));
            S[ii + 1] = s1;
            yb = fma2(s1, pk2(kr1.z, kr1.w), yb);
        }
        float y0x, y0y, y1x, y1y;
        upk2(ya, y0x, y0y); upk2(yb, y1x, y1y);
        float yv = (y0x + y0y) + (y1x + y1y);
        yv += __shfl_xor_sync(0xffffffffu, yv, 1);
        if (half == 0) y[base0 + (size_t)t * Cc + j] = yv;
    }
}

// ---------------- groupnorm + rk*v + gate -> fp16 ----------------
__global__ void post_kernel(const float* __restrict__ y, const float* __restrict__ r,
                            const float* __restrict__ k, const float* __restrict__ v,
                            const float* __restrict__ g, const float* __restrict__ r_k,
                            const float* __restrict__ ln_w, const float* __restrict__ ln_b,
                            uint16_t* __restrict__ oh)
{
    int gid = blockIdx.x * 8 + (threadIdx.x >> 5);
    int lane = threadIdx.x & 31;
    int h = gid % Hh;
    size_t bt = gid / Hh;
    size_t base = bt * Cc + (size_t)h * Nn;
    int c0 = h * Nn + lane, c1 = c0 + 32;
    float y0 = y[base + lane], y1 = y[base + lane + 32];
    float sum = y0 + y1;
#pragma unroll
    for (int o = 16; o > 0; o >>= 1) sum += __shfl_xor_sync(0xffffffffu, sum, o);
    float mean = sum * (1.f / 64.f);
    float d0 = y0 - mean, d1 = y1 - mean;
    float var = d0 * d0 + d1 * d1;
#pragma unroll
    for (int o = 16; o > 0; o >>= 1) var += __shfl_xor_sync(0xffffffffu, var, o);
    var *= (1.f / 64.f);
    float inv = rsqrtf(var + LN_EPS);
    float yn0 = d0 * inv * ln_w[c0] + ln_b[c0];
    float yn1 = d1 * inv * ln_w[c1] + ln_b[c1];
    float rk = r[base + lane] * k[base + lane] * r_k[c0]
             + r[base + lane + 32] * k[base + lane + 32] * r_k[c1];
#pragma unroll
    for (int o = 16; o > 0; o >>= 1) rk += __shfl_xor_sync(0xffffffffu, rk, o);
    float o0 = (yn0 + rk * v[base + lane]) * g[base + lane];
    float o1 = (yn1 + rk * v[base + lane + 32]) * g[base + lane + 32];
    h1store(o0, oh, base + lane);
    h1store(o1, oh, base + lane + 32);
}

// ---------------- launch ----------------
#define GETSYM(var, sym) do { void* _p; cudaGetSymbolAddress(&_p, sym); var = (decltype(var))_p; } while (0)

extern "C" void kernel_launch(void* const* d_in, const int* in_sizes, int n_in,
                              void* d_out, int out_size)
{
    const float* x       = (const float*)d_in[0];
    const float* mask    = (const float*)d_in[1];
    const float* v_first = (const float*)d_in[2];
    const float* x_r = (const float*)d_in[3];
    const float* x_w = (const float*)d_in[4];
    const float* x_k = (const float*)d_in[5];
    const float* x_v = (const float*)d_in[6];
    const float* x_a = (const float*)d_in[7];
    const float* x_g = (const float*)d_in[8];
    const float* w0 = (const float*)d_in[9];
    const float* w1 = (const float*)d_in[10];
    const float* w2 = (const float*)d_in[11];
    const float* a0 = (const float*)d_in[12];
    const float* a1 = (const float*)d_in[13];
    const float* a2 = (const float*)d_in[14];
    const float* v0 = (const float*)d_in[15];
    const float* v1 = (const float*)d_in[16];
    const float* v2 = (const float*)d_in[17];
    const float* g1 = (const float*)d_in[18];
    const float* g2 = (const float*)d_in[19];
    const float* k_k = (const float*)d_in[20];
    const float* k_a = (const float*)d_in[21];
    const float* r_k = (const float*)d_in[22];
    const float* W_r = (const float*)d_in[23];
    const float* W_k = (const float*)d_in[24];
    const float* W_v = (const float*)d_in[25];
    const float* W_o = (const float*)d_in[26];
    const float* ln_w = (const float*)d_in[27];
    const float* ln_b = (const float*)d_in[28];
    float* out = (float*)d_out;

    float *rr, *kb, *vb, *wd, *as, *gg, *kkb, *yb;
    GETSYM(rr, g_r); GETSYM(kb, g_k); GETSYM(vb, g_v);
    GETSYM(wd, g_wdec); GETSYM(as, g_asig); GETSYM(gg, g_g);
    GETSYM(kkb, g_kk); GETSYM(yb, g_y);
    uint16_t *xr,*xw,*xk,*xv,*xa,*xg,*yg;
    GETSYM(xr, g_xr); GETSYM(xw, g_xw); GETSYM(xk, g_xk);
    GETSYM(xv, g_xv); GETSYM(xa, g_xa); GETSYM(xg, g_xg);
    GETSYM(yg, g_yg);
    uint16_t *Wrh,*Wrl,*Wkh,*Wkl,*Wvh,*Wvl,*Woh,*Wol;
    GETSYM(Wrh, g_Wrh); GETSYM(Wrl, g_Wrl); GETSYM(Wkh, g_Wkh); GETSYM(Wkl, g_Wkl);
    GETSYM(Wvh, g_Wvh); GETSYM(Wvl, g_Wvl); GETSYM(Woh, g_Woh); GETSYM(Wol, g_Wol);
    uint16_t *l1h, *l1l, *l2h, *l2l, *ts;
    GETSYM(l1h, g_l1h); GETSYM(l1l, g_l1l); GETSYM(l2h, g_l2h); GETSYM(l2l, g_l2l);
    GETSYM(ts, g_ts);

    cudaFuncSetAttribute(mma_gemm<0>, cudaFuncAttributeMaxDynamicSharedMemorySize, GEMM_SMEM);
    cudaFuncSetAttribute(mma_gemm<1>, cudaFuncAttributeMaxDynamicSharedMemorySize, GEMM_SMEM);
    cudaFuncSetAttribute(mma_gemm<2>, cudaFuncAttributeMaxDynamicSharedMemorySize, GEMM_SMEM);

    // side stream + events for graph-capture fork/join (host resources only)
    static cudaStream_t s1 = nullptr;
    static cudaEvent_t eFork = nullptr, eJoin = nullptr;
    if (s1 == nullptr) {
        cudaStreamCreateWithFlags(&s1, cudaStreamNonBlocking);
        cudaEventCreateWithFlags(&eFork, cudaEventDisableTiming);
        cudaEventCreateWithFlags(&eJoin, cudaEventDisableTiming);
    }

    // conversions
    prep_kernel<<<dim3(BT, 2), 256>>>(x, mask, x_r, x_w, x_k, x_v, x_a, x_g);
    wsplit_kernel<<<(Cc * Cc) / 1024, 256>>>(W_r, W_k, W_v, W_o);
    LoraSrc ls;
    ls.s1[0] = w1; ls.s1[1] = a1; ls.s1[2] = v1; ls.s1[3] = g1;
    ls.s2[0] = w2; ls.s2[1] = a2; ls.s2[2] = v2; ls.s2[3] = g2;
    lsplit_kernel<<<dim3(1024, 8), 256>>>(ls);

    cudaEventRecord(eFork, 0);
    cudaStreamWaitEvent(s1, eFork, 0);

    const size_t L1 = (size_t)LORA_PAD * Cc, L2 = (size_t)Cc * LORA_PAD;
    const size_t TS = (size_t)BT * LORA_PAD;

    // side stream: v_first passthrough + LoRA stage1 + v-independent stage2 paths
    if ((size_t)out_size >= 2 * BTC) {
        cudaMemcpyAsync(out + BTC, v_first, BTC * sizeof(float),
                        cudaMemcpyDeviceToDevice, s1);
    }
    GemmB b1 = {};
    b1.Aa[0] = xw; b1.Aa[1] = xa; b1.Aa[2] = xv; b1.Aa[3] = xg;
    for (int p = 0; p < 4; p++) {
        b1.Bh[p] = l1h + p * L1; b1.Bl[p] = l1l + p * L1;
        b1.Oh[p] = ts + p * TS;
    }
    mma_gemm<1><<<dim3(4, 64), 256, GEMM_SMEM, s1>>>(b1, Cc);

    GemmB b2a = {};   // stage2: w, a, g (independent of v projection)
    b2a.Aa[0] = ts + 0 * TS; b2a.Bh[0] = l2h + 0 * L2; b2a.Bl[0] = l2l + 0 * L2;
    b2a.Of[0] = wd; b2a.bias[0] = w0; b2a.etype[0] = 0;
    b2a.Aa[1] = ts + 1 * TS; b2a.Bh[1] = l2h + 1 * L2; b2a.Bl[1] = l2l + 1 * L2;
    b2a.Of[1] = as; b2a.bias[1] = a0; b2a.etype[1] = 1;
    b2a.Aa[2] = ts + 3 * TS; b2a.Bh[2] = l2h + 3 * L2; b2a.Bl[2] = l2l + 3 * L2;
    b2a.Of[2] = gg; b2a.bias[2] = w0; b2a.etype[2] = 3;
    mma_gemm<2><<<dim3(48, 64), 256, GEMM_SMEM, s1>>>(b2a, LORA_PAD);
    cudaEventRecord(eJoin, s1);

    // main stream: batched r,k,v projections (overlaps with side stream)
    GemmB b0 = {};
    b0.Aa[0] = xr; b0.Bh[0] = Wrh; b0.Bl[0] = Wrl; b0.Of[0] = rr;
    b0.Aa[1] = xk; b0.Bh[1] = Wkh; b0.Bl[1] = Wkl; b0.Of[1] = kb;
    b0.Aa[2] = xv; b0.Bh[2] = Wvh; b0.Bl[2] = Wvl; b0.Of[2] = vb;
    mma_gemm<0><<<dim3(48, 64), 256, GEMM_SMEM>>>(b0, Cc);

    cudaStreamWaitEvent(0, eJoin, 0);

    // stage2 v path (needs vb from rkv GEMM + ts from lora1)
    GemmB b2b = {};
    b2b.Aa[0] = ts + 2 * TS; b2b.Bh[0] = l2h + 2 * L2; b2b.Bl[0] = l2l + 2 * L2;
    b2b.Of[0] = vb; b2b.bias[0] = v0; b2b.etype[0] = 2;
    b2b.vf = v_first; b2b.mask = mask;
    mma_gemm<2><<<dim3(16, 64), 256, GEMM_SMEM>>>(b2b, LORA_PAD);

    // kk, scan, post
    kk_kernel<<<(BT * Hh) / 8, 256>>>(k_k, k_a, as, kb, kkb);
    scan_kernel<<<Bb * Hh, 128>>>(rr, wd, kb, vb, kkb, as, yb);
    post_kernel<<<(BT * Hh) / 8, 256>>>(yb, rr, kb, vb, gg, r_k, ln_w, ln_b, yg);

    // output projection
    GemmB bo = {};
    bo.Aa[0] = yg; bo.Bh[0] = Woh; bo.Bl[0] = Wol; bo.Of[0] = out;
    mma_gemm<0><<<dim3(16, 64), 256, GEMM_SMEM>>>(bo, Cc);
}

// round 9
// speedup vs baseline: 4.3940x; 1.3142x over previous
#include <cuda_runtime.h>
#include <cuda_bf16.h>
#include <cuda_fp16.h>
#include <cstdint>

// ---------------- problem constants ----------------
#define Bb 8
#define Tt 1024
#define Cc 2048
#define Hh 32
#define Nn 64
#define BT (Bb*Tt)                  // 8192
#define BTC ((size_t)BT*Cc)         // 16.7M
#define LORA_PAD 128
#define LN_EPS (1e-5f*64.0f)

// ---------------- scratch (device globals) ----------------
__device__ float g_r[BTC], g_k[BTC], g_v[BTC];
__device__ float g_wdec[BTC], g_asig[BTC], g_g[BTC], g_y[BTC];
// packed scan inputs: per (bt,h): 384 floats = [WB 128][KR 128][A2 64][V 64]
__device__ float g_pack[(size_t)BT*Hh*384];

// fp16 activations (A operands)
__device__ uint16_t g_xr[BTC], g_xw[BTC], g_xk[BTC], g_xv[BTC], g_xa[BTC], g_xg[BTC];
__device__ uint16_t g_yg[BTC];
// fp16 split weights (B operands)
__device__ uint16_t g_Wrh[Cc*Cc], g_Wrl[Cc*Cc], g_Wkh[Cc*Cc], g_Wkl[Cc*Cc];
__device__ uint16_t g_Wvh[Cc*Cc], g_Wvl[Cc*Cc], g_Woh[Cc*Cc], g_Wol[Cc*Cc];
// LoRA weights
__device__ uint16_t g_l1h[4][LORA_PAD*Cc], g_l1l[4][LORA_PAD*Cc];
__device__ uint16_t g_l2h[4][Cc*LORA_PAD], g_l2l[4][Cc*LORA_PAD];
__device__ uint16_t g_ts[4][(size_t)BT*LORA_PAD];

// ---------------- helpers ----------------
__device__ __forceinline__ void h1store(float v, uint16_t* dst, size_t i) {
    reinterpret_cast<__half*>(dst)[i] = __float2half_rn(v);
}
__device__ __forceinline__ void h4store(float4 v, uint16_t* dst, size_t i) {
    __half2 a = __floats2half2_rn(v.x, v.y);
    __half2 b = __floats2half2_rn(v.z, v.w);
    *reinterpret_cast<uint2*>(dst + i) =
        make_uint2(*reinterpret_cast<uint32_t*>(&a), *reinterpret_cast<uint32_t*>(&b));
}
__device__ __forceinline__ void hsplit1(float v, uint16_t* hi, uint16_t* lo, size_t i) {
    __half h = __float2half_rn(v);
    float hf = __half2float(h);
    __half l = __float2half_rn(v - hf);
    reinterpret_cast<__half*>(hi)[i] = h;
    reinterpret_cast<__half*>(lo)[i] = l;
}
__device__ __forceinline__ void hsplit4(float4 v, uint16_t* hi, uint16_t* lo, size_t i) {
    __half2 h0 = __floats2half2_rn(v.x, v.y), h1 = __floats2half2_rn(v.z, v.w);
    float2 f0 = __half22float2(h0), f1 = __half22float2(h1);
    __half2 l0 = __floats2half2_rn(v.x - f0.x, v.y - f0.y);
    __half2 l1 = __floats2half2_rn(v.z - f1.x, v.w - f1.y);
    *reinterpret_cast<uint2*>(hi + i) =
        make_uint2(*reinterpret_cast<uint32_t*>(&h0), *reinterpret_cast<uint32_t*>(&h1));
    *reinterpret_cast<uint2*>(lo + i) =
        make_uint2(*reinterpret_cast<uint32_t*>(&l0), *reinterpret_cast<uint32_t*>(&l1));
}

__device__ __forceinline__ uint32_t smem_u32(const void* p) {
    uint32_t a;
    asm("{ .reg .u64 t; cvta.to.shared.u64 t, %1; cvt.u32.u64 %0, t; }" : "=r"(a) : "l"(p));
    return a;
}
#define SWZ128(o) ((o) ^ (((o) >> 3) & 0x70))

__device__ __forceinline__ void cpa16(uint32_t daddr, const void* g)
{
    asm volatile("cp.async.cg.shared.global [%0], [%1], 16;"
                 :: "r"(daddr), "l"(__cvta_generic_to_global(g)) : "memory");
}

__device__ __forceinline__ void ldsm4(uint32_t& r0, uint32_t& r1, uint32_t& r2, uint32_t& r3,
                                      uint32_t addr)
{
    asm volatile("ldmatrix.sync.aligned.m8n8.x4.shared.b16 {%0,%1,%2,%3}, [%4];"
                 : "=r"(r0), "=r"(r1), "=r"(r2), "=r"(r3) : "r"(addr));
}

__device__ __forceinline__ void mma16816(float* c, const uint32_t* a, const uint32_t* b)
{
    asm volatile("mma.sync.aligned.m16n8k16.row.col.f32.f16.f16.f32 "
                 "{%0,%1,%2,%3}, {%4,%5,%6,%7}, {%8,%9}, {%0,%1,%2,%3};"
                 : "+f"(c[0]), "+f"(c[1]), "+f"(c[2]), "+f"(c[3])
                 : "r"(a[0]), "r"(a[1]), "r"(a[2]), "r"(a[3]), "r"(b[0]), "r"(b[1]));
}

// packed f32x2 (sm_100+)
typedef unsigned long long u64t;
__device__ __forceinline__ u64t pk2(float x, float y){ u64t d; asm("mov.b64 %0, {%1,%2};" : "=l"(d) : "f"(x), "f"(y)); return d; }
__device__ __forceinline__ void upk2(u64t d, float& x, float& y){ asm("mov.b64 {%0,%1}, %2;" : "=f"(x), "=f"(y) : "l"(d)); }
__device__ __forceinline__ u64t fma2(u64t a, u64t b, u64t c){ u64t d; asm("fma.rn.f32x2 %0, %1, %2, %3;" : "=l"(d) : "l"(a), "l"(b), "l"(c)); return d; }
__device__ __forceinline__ u64t mul2(u64t a, u64t b){ u64t d; asm("mul.rn.f32x2 %0, %1, %2;" : "=l"(d) : "l"(a), "l"(b)); return d; }

// ---------------- prep: mask + time-shift mixes -> fp16 ----------------
__global__ void prep_kernel(const float* __restrict__ x, const float* __restrict__ mask,
                            const float* __restrict__ mr, const float* __restrict__ mw,
                            const float* __restrict__ mk, const float* __restrict__ mv,
                            const float* __restrict__ ma, const float* __restrict__ mg)
{
    int bt = blockIdx.x;
    int c  = blockIdx.y * 1024 + threadIdx.x * 4;
    int t  = bt & (Tt - 1);
    float m  = mask[bt];
    float mp = (t > 0) ? mask[bt - 1] : 0.f;
    size_t idx = (size_t)bt * Cc + c;
    float4 xv = *reinterpret_cast<const float4*>(&x[idx]);
    float4 xp = make_float4(0.f, 0.f, 0.f, 0.f);
    if (t > 0) xp = *reinterpret_cast<const float4*>(&x[idx - Cc]);
    float4 xm = make_float4(xv.x*m, xv.y*m, xv.z*m, xv.w*m);
    float4 xx = make_float4(xp.x*mp - xm.x, xp.y*mp - xm.y, xp.z*mp - xm.z, xp.w*mp - xm.w);
#define MIX(MM, DD) { \
    float4 mm = *reinterpret_cast<const float4*>(&MM[c]); \
    float4 vv = make_float4(xm.x + xx.x*mm.x, xm.y + xx.y*mm.y, xm.z + xx.z*mm.z, xm.w + xx.w*mm.w); \
    h4store(vv, DD, idx); }
    MIX(mr, g_xr); MIX(mw, g_xw); MIX(mk, g_xk);
    MIX(mv, g_xv); MIX(ma, g_xa); MIX(mg, g_xg);
#undef MIX
}

__global__ void wsplit_kernel(const float* __restrict__ Wr, const float* __restrict__ Wk,
                              const float* __restrict__ Wv, const float* __restrict__ Wo)
{
    size_t i = ((size_t)blockIdx.x * 256 + threadIdx.x) * 4;
    hsplit4(*reinterpret_cast<const float4*>(&Wr[i]), g_Wrh, g_Wrl, i);
    hsplit4(*reinterpret_cast<const float4*>(&Wk[i]), g_Wkh, g_Wkl, i);
    hsplit4(*reinterpret_cast<const float4*>(&Wv[i]), g_Wvh, g_Wvl, i);
    hsplit4(*reinterpret_cast<const float4*>(&Wo[i]), g_Woh, g_Wol, i);
}

struct LoraSrc { const float* s1[4]; const float* s2[4]; };
__constant__ int c_D[4] = {96, 96, 64, 128};

__global__ void lsplit_kernel(LoraSrc ls)
{
    int id = blockIdx.y;
    int i = blockIdx.x * 256 + threadIdx.x;
    if (id < 4) {
        int D = c_D[id];
        int n = i >> 11, kcol = i & 2047;
        float v = (n < D) ? ls.s1[id][(size_t)kcol * D + n] : 0.f;
        hsplit1(v, g_l1h[id], g_l1l[id], i);
    } else {
        int p = id - 4;
        int D = c_D[p];
        int n = i >> 7, kcol = i & 127;
        float v = (kcol < D) ? ls.s2[p][(size_t)kcol * Cc + n] : 0.f;
        hsplit1(v, g_l2h[p], g_l2l[p], i);
    }
}

// ---------------- GEMM: 2-term fp16, 2-stage smem, 2 CTAs/SM -----------------
#define ATILE_B 16384
#define STAGE3_B (3*ATILE_B)        // 48KB
#define GEMM_SMEM (2*STAGE3_B)      // 96KB

struct GemmB {
    const uint16_t *Aa[4], *Bh[4], *Bl[4];
    uint16_t *Oh[4];
    float *Of[4];
    const float *bias[4];
    int etype[4];                   // MODE2: 0=wdec 1=asig 2=vupd 3=copy
    const float *vf, *mask;
};

template<int MODE>
__global__ __launch_bounds__(256, 2)
void mma_gemm(GemmB bp, int K)
{
    extern __shared__ char smem[];
    const uint32_t sb = smem_u32(smem);
    const int tid = threadIdx.x, lane = tid & 31, warp = tid >> 5;
    const int warpM = warp >> 1, warpN = warp & 1;
    const int m0 = blockIdx.y * 128;
    int n0, path;
    if (MODE == 1) { path = blockIdx.x;      n0 = 0; }
    else           { path = blockIdx.x >> 4; n0 = (blockIdx.x & 15) * 128; }
    const uint16_t* Aa  = bp.Aa[path];
    const uint16_t* Bhi = bp.Bh[path];
    const uint16_t* Blo = bp.Bl[path];
    const int kc = K >> 6;

    float acc[2][8][4];
#pragma unroll
    for (int mt = 0; mt < 2; mt++)
#pragma unroll
        for (int nt = 0; nt < 8; nt++)
#pragma unroll
            for (int e = 0; e < 4; e++) acc[mt][nt][e] = 0.f;

    auto load_chunk = [&](int c) {
        const uint32_t stb = sb + (uint32_t)(c & 1) * STAGE3_B;
        const int k0 = c << 6;
        const uint16_t* srcs[3] = {Aa, Bhi, Blo};
#pragma unroll
        for (int a3 = 0; a3 < 3; a3++) {
            const uint16_t* src = srcs[a3];
            const int rb = (a3 == 0) ? m0 : n0;
            const uint32_t ab = stb + a3 * ATILE_B;
#pragma unroll
            for (int jj = 0; jj < 4; jj++) {
                int T = tid + jj * 256;
                int row = T >> 3, seg = T & 7;
                cpa16(ab + SWZ128(row * 128 + seg * 16),
                      src + (size_t)(rb + row) * K + k0 + seg * 8);
            }
        }
    };

    load_chunk(0);
    asm volatile("cp.async.commit_group;" ::: "memory");

    const int aRowOff = warpM * 32 + (lane & 15);
    const int aKbase  = (lane >> 4) << 4;
    const int bRowOff = warpN * 64 + (lane & 7) + ((lane >> 1) & 8);
    const int bKbase  = ((lane >> 3) & 1) * 16;

    for (int c = 0; c < kc; c++) {
        __syncthreads();                       // all warps done reading stage (c+1)&1
        if (c + 1 < kc) load_chunk(c + 1);
        asm volatile("cp.async.commit_group;" ::: "memory");
        asm volatile("cp.async.wait_group 1;" ::: "memory");
        __syncthreads();                       // chunk c visible to all

        const uint32_t stb = sb + (uint32_t)(c & 1) * STAGE3_B;
        const uint32_t sA = stb, sBh = stb + ATILE_B, sBl = stb + 2u * ATILE_B;
#pragma unroll
        for (int s = 0; s < 4; s++) {
            const int akb = s * 32 + aKbase;
            const int bkb = s * 32 + bKbase;
            uint32_t a[2][4];
#pragma unroll
            for (int mt = 0; mt < 2; mt++) {
                int ro = (aRowOff + mt * 16) * 128;
                ldsm4(a[mt][0], a[mt][1], a[mt][2], a[mt][3], sA + SWZ128(ro + akb));
            }
            uint32_t b[8][2];
#pragma unroll
            for (int p = 0; p < 4; p++) {
                int ro = (bRowOff + p * 16) * 128;
                uint32_t r0, r1, r2, r3;
                ldsm4(r0, r1, r2, r3, sBh + SWZ128(ro + bkb));
                b[p*2][0] = r0; b[p*2][1] = r1; b[p*2+1][0] = r2; b[p*2+1][1] = r3;
            }
#pragma unroll
            for (int mt = 0; mt < 2; mt++)
#pragma unroll
                for (int nt = 0; nt < 8; nt++)
                    mma16816(acc[mt][nt], a[mt], b[nt]);
#pragma unroll
            for (int p = 0; p < 4; p++) {
                int ro = (bRowOff + p * 16) * 128;
                uint32_t r0, r1, r2, r3;
                ldsm4(r0, r1, r2, r3, sBl + SWZ128(ro + bkb));
                b[p*2][0] = r0; b[p*2][1] = r1; b[p*2+1][0] = r2; b[p*2+1][1] = r3;
            }
#pragma unroll
            for (int mt = 0; mt < 2; mt++)
#pragma unroll
                for (int nt = 0; nt < 8; nt++)
                    mma16816(acc[mt][nt], a[mt], b[nt]);
        }
    }

    // epilogue
    const int row0 = m0 + warpM * 32 + (lane >> 2);
    const int col0 = n0 + warpN * 64 + (lane & 3) * 2;
    const int et = (MODE == 2) ? bp.etype[path] : 0;
#pragma unroll
    for (int mt = 0; mt < 2; mt++) {
#pragma unroll
        for (int nt = 0; nt < 8; nt++) {
            int r1 = row0 + mt * 16;
            int c1 = col0 + nt * 8;
            float v0 = acc[mt][nt][0], v1 = acc[mt][nt][1];
            float v2 = acc[mt][nt][2], v3 = acc[mt][nt][3];
            if (MODE == 0) {
                float* Cf = bp.Of[path];
                *reinterpret_cast<float2*>(&Cf[(size_t)r1 * Cc + c1]) = make_float2(v0, v1);
                *reinterpret_cast<float2*>(&Cf[(size_t)(r1 + 8) * Cc + c1]) = make_float2(v2, v3);
            } else if (MODE == 1) {
                if (path == 0) { v0 = tanhf(v0); v1 = tanhf(v1); v2 = tanhf(v2); v3 = tanhf(v3); }
                else if (path == 3) {
                    v0 = 1.f/(1.f+expf(-v0)); v1 = 1.f/(1.f+expf(-v1));
                    v2 = 1.f/(1.f+expf(-v2)); v3 = 1.f/(1.f+expf(-v3));
                }
                uint16_t* oh = bp.Oh[path];
                h1store(v0, oh, (size_t)r1 * LORA_PAD + c1);
                h1store(v1, oh, (size_t)r1 * LORA_PAD + c1 + 1);
                h1store(v2, oh, (size_t)(r1 + 8) * LORA_PAD + c1);
                h1store(v3, oh, (size_t)(r1 + 8) * LORA_PAD + c1 + 1);
            } else {
                float* Of = bp.Of[path];
                const float* bias = bp.bias[path];
                auto ep = [&](float z, int rr_, int cc_) {
                    size_t idx = (size_t)rr_ * Cc + cc_;
                    if (et == 0) {
                        float zz = bias[cc_] + z;
                        float nz = -zz;
                        float sp = (nz > 20.f) ? nz : log1pf(expf(nz));
                        Of[idx] = expf(-expf(-sp - 0.5f));
                    } else if (et == 1) {
                        Of[idx] = 1.f / (1.f + expf(-(bias[cc_] + z)));
                    } else if (et == 2) {
                        float s = 1.f / (1.f + expf(-(bias[cc_] + z)));
                        float vv = Of[idx];
                        Of[idx] = (vv + (bp.vf[idx] - vv) * s) * bp.mask[rr_];
                    } else {
                        Of[idx] = z;
                    }
                };
                ep(v0, r1, c1); ep(v1, r1, c1 + 1);
                ep(v2, r1 + 8, c1); ep(v3, r1 + 8, c1 + 1);
            }
        }
    }
}

// ---------------- pack: kk-normalize + k-rescale + scan-input packing ----------
// record per (bt,h): [WB: (w0,w1,b0,b1)x32][KR: (k0,k1,r0,r1)x32][A2: (a0,a1)x32][V: 64]
__global__ void pack_kernel(const float* __restrict__ kkp, const float* __restrict__ kap,
                            const float* __restrict__ asig, const float* __restrict__ wd,
                            const float* __restrict__ r, const float* __restrict__ v,
                            float* __restrict__ k, float* __restrict__ pack)
{
    int gid = blockIdx.x * 8 + (threadIdx.x >> 5);   // bt*Hh + h
    int l = threadIdx.x & 31;
    int h = gid & (Hh - 1);
    size_t bt = (size_t)gid >> 5;
    size_t base = bt * Cc + (size_t)h * Nn + 2 * l;
    int c0 = h * Nn + 2 * l;
    float2 kv = *reinterpret_cast<const float2*>(&k[base]);
    float2 kp = *reinterpret_cast<const float2*>(&kkp[c0]);
    float kk0 = kv.x * kp.x, kk1 = kv.y * kp.y;
    float ss = kk0 * kk0 + kk1 * kk1;
#pragma unroll
    for (int o = 16; o > 0; o >>= 1) ss += __shfl_xor_sync(0xffffffffu, ss, o);
    float inv = 1.f / fmaxf(sqrtf(ss), 1e-12f);
    kk0 *= inv; kk1 *= inv;
    float2 as2 = *reinterpret_cast<const float2*>(&asig[base]);
    float2 ka2 = *reinterpret_cast<const float2*>(&kap[c0]);
    float kn0 = kv.x * (1.f + (as2.x - 1.f) * ka2.x);
    float kn1 = kv.y * (1.f + (as2.y - 1.f) * ka2.y);
    *reinterpret_cast<float2*>(&k[base]) = make_float2(kn0, kn1);
    float2 w2 = *reinterpret_cast<const float2*>(&wd[base]);
    float2 r2 = *reinterpret_cast<const float2*>(&r[base]);
    float2 v2 = *reinterpret_cast<const float2*>(&v[base]);
    float* pb = pack + (size_t)gid * 384;
    *reinterpret_cast<float4*>(&pb[l * 4])       = make_float4(w2.x, w2.y, kk0 * as2.x, kk1 * as2.y);
    *reinterpret_cast<float4*>(&pb[128 + l * 4]) = make_float4(kn0, kn1, r2.x, r2.y);
    *reinterpret_cast<float2*>(&pb[256 + l * 2]) = make_float2(-kk0, -kk1);
    *reinterpret_cast<float2*>(&pb[320 + l * 2]) = v2;
}

// ---------------- RWKV-7 scan: cp.async depth-4 pipeline -----------------------
__global__ __launch_bounds__(128)
void scan_kernel(const float* __restrict__ pack, float* __restrict__ y)
{
    int bh = blockIdx.x;
    int b = bh >> 5, h = bh & (Hh - 1);
    int tid = threadIdx.x;
    int j = tid >> 1, half = tid & 1;
    __shared__ __align__(16) char buf[4][1536];
    const char* src = reinterpret_cast<const char*>(
        pack + ((size_t)b * Tt * Hh + h) * 384);
    const size_t stepB = (size_t)Hh * 1536;
    const uint32_t sbase = smem_u32(buf);
    u64t S[16];
#pragma unroll
    for (int i = 0; i < 16; i++) S[i] = 0ull;

#pragma unroll
    for (int pt = 0; pt < 3; pt++) {
        if (tid < 96) cpa16(sbase + pt * 1536 + tid * 16, src + pt * stepB + tid * 16);
        asm volatile("cp.async.commit_group;" ::: "memory");
    }

    size_t ybase = ((size_t)b * Tt) * Cc + (size_t)h * Nn + j;
    for (int t = 0; t < Tt; t++) {
        asm volatile("cp.async.wait_group 2;" ::: "memory");
        __syncthreads();
        if (t + 3 < Tt && tid < 96)
            cpa16(sbase + ((t + 3) & 3) * 1536 + tid * 16, src + (t + 3) * stepB + tid * 16);
        asm volatile("cp.async.commit_group;" ::: "memory");

        const float* W = reinterpret_cast<const float*>(buf[t & 3]);
        float vj = W[320 + j];
        // pass 1: sacc over own pairs
        u64t q0 = 0ull, q1 = 0ull, q2 = 0ull, q3 = 0ull;
#pragma unroll
        for (int ii = 0; ii < 16; ii += 4) {
            q0 = fma2(S[ii + 0], *reinterpret_cast<const u64t*>(W + 256 + (2*(ii+0)+half)*2), q0);
            q1 = fma2(S[ii + 1], *reinterpret_cast<const u64t*>(W + 256 + (2*(ii+1)+half)*2), q1);
            q2 = fma2(S[ii + 2], *reinterpret_cast<const u64t*>(W + 256 + (2*(ii+2)+half)*2), q2);
            q3 = fma2(S[ii + 3], *reinterpret_cast<const u64t*>(W + 256 + (2*(ii+3)+half)*2), q3);
        }
        float ax, ay, bx, by, cx, cy, dx, dy;
        upk2(q0, ax, ay); upk2(q1, bx, by); upk2(q2, cx, cy); upk2(q3, dx, dy);
        float sacc = ((ax + ay) + (bx + by)) + ((cx + cy) + (dx + dy));
        sacc += __shfl_xor_sync(0xffffffffu, sacc, 1);
        u64t sacc2 = pk2(sacc, sacc);
        u64t vj2 = pk2(vj, vj);
        // pass 2: state update + y
        u64t ya = 0ull, yb = 0ull;
#pragma unroll
        for (int ii = 0; ii < 16; ii++) {
            int p = 2 * ii + half;
            float4 wb = *reinterpret_cast<const float4*>(W + p * 4);
            float4 kr = *reinterpret_cast<const float4*>(W + 128 + p * 4);
            u64t s = fma2(S[ii], pk2(wb.x, wb.y),
                          fma2(sacc2, pk2(wb.z, wb.w), mul2(vj2, pk2(kr.x, kr.y))));
            S[ii] = s;
            if (ii & 1) yb = fma2(s, pk2(kr.z, kr.w), yb);
            else        ya = fma2(s, pk2(kr.z, kr.w), ya);
        }
        float y0x, y0y, y1x, y1y;
        upk2(ya, y0x, y0y); upk2(yb, y1x, y1y);
        float yv = (y0x + y0y) + (y1x + y1y);
        yv += __shfl_xor_sync(0xffffffffu, yv, 1);
        if (half == 0) y[ybase + (size_t)t * Cc] = yv;
    }
}

// ---------------- groupnorm + rk*v + gate -> fp16 ----------------
__global__ void post_kernel(const float* __restrict__ y, const float* __restrict__ r,
                            const float* __restrict__ k, const float* __restrict__ v,
                            const float* __restrict__ g, const float* __restrict__ r_k,
                            const float* __restrict__ ln_w, const float* __restrict__ ln_b,
                            uint16_t* __restrict__ oh)
{
    int gid = blockIdx.x * 8 + (threadIdx.x >> 5);
    int lane = threadIdx.x & 31;
    int h = gid % Hh;
    size_t bt = gid / Hh;
    size_t base = bt * Cc + (size_t)h * Nn;
    int c0 = h * Nn + lane, c1 = c0 + 32;
    float y0 = y[base + lane], y1 = y[base + lane + 32];
    float sum = y0 + y1;
#pragma unroll
    for (int o = 16; o > 0; o >>= 1) sum += __shfl_xor_sync(0xffffffffu, sum, o);
    float mean = sum * (1.f / 64.f);
    float d0 = y0 - mean, d1 = y1 - mean;
    float var = d0 * d0 + d1 * d1;
#pragma unroll
    for (int o = 16; o > 0; o >>= 1) var += __shfl_xor_sync(0xffffffffu, var, o);
    var *= (1.f / 64.f);
    float inv = rsqrtf(var + LN_EPS);
    float yn0 = d0 * inv * ln_w[c0] + ln_b[c0];
    float yn1 = d1 * inv * ln_w[c1] + ln_b[c1];
    float rk = r[base + lane] * k[base + lane] * r_k[c0]
             + r[base + lane + 32] * k[base + lane + 32] * r_k[c1];
#pragma unroll
    for (int o = 16; o > 0; o >>= 1) rk += __shfl_xor_sync(0xffffffffu, rk, o);
    float o0 = (yn0 + rk * v[base + lane]) * g[base + lane];
    float o1 = (yn1 + rk * v[base + lane + 32]) * g[base + lane + 32];
    h1store(o0, oh, base + lane);
    h1store(o1, oh, base + lane + 32);
}

// ---------------- launch ----------------
#define GETSYM(var, sym) do { void* _p; cudaGetSymbolAddress(&_p, sym); var = (decltype(var))_p; } while (0)

extern "C" void kernel_launch(void* const* d_in, const int* in_sizes, int n_in,
                              void* d_out, int out_size)
{
    const float* x       = (const float*)d_in[0];
    const float* mask    = (const float*)d_in[1];
    const float* v_first = (const float*)d_in[2];
    const float* x_r = (const float*)d_in[3];
    const float* x_w = (const float*)d_in[4];
    const float* x_k = (const float*)d_in[5];
    const float* x_v = (const float*)d_in[6];
    const float* x_a = (const float*)d_in[7];
    const float* x_g = (const float*)d_in[8];
    const float* w0 = (const float*)d_in[9];
    const float* w1 = (const float*)d_in[10];
    const float* w2 = (const float*)d_in[11];
    const float* a0 = (const float*)d_in[12];
    const float* a1 = (const float*)d_in[13];
    const float* a2 = (const float*)d_in[14];
    const float* v0 = (const float*)d_in[15];
    const float* v1 = (const float*)d_in[16];
    const float* v2 = (const float*)d_in[17];
    const float* g1 = (const float*)d_in[18];
    const float* g2 = (const float*)d_in[19];
    const float* k_k = (const float*)d_in[20];
    const float* k_a = (const float*)d_in[21];
    const float* r_k = (const float*)d_in[22];
    const float* W_r = (const float*)d_in[23];
    const float* W_k = (const float*)d_in[24];
    const float* W_v = (const float*)d_in[25];
    const float* W_o = (const float*)d_in[26];
    const float* ln_w = (const float*)d_in[27];
    const float* ln_b = (const float*)d_in[28];
    float* out = (float*)d_out;

    float *rr, *kb, *vb, *wd, *as, *gg, *yb, *pk;
    GETSYM(rr, g_r); GETSYM(kb, g_k); GETSYM(vb, g_v);
    GETSYM(wd, g_wdec); GETSYM(as, g_asig); GETSYM(gg, g_g);
    GETSYM(yb, g_y); GETSYM(pk, g_pack);
    uint16_t *xr,*xw,*xk,*xv,*xa,*xg,*yg;
    GETSYM(xr, g_xr); GETSYM(xw, g_xw); GETSYM(xk, g_xk);
    GETSYM(xv, g_xv); GETSYM(xa, g_xa); GETSYM(xg, g_xg);
    GETSYM(yg, g_yg);
    uint16_t *Wrh,*Wrl,*Wkh,*Wkl,*Wvh,*Wvl,*Woh,*Wol;
    GETSYM(Wrh, g_Wrh); GETSYM(Wrl, g_Wrl); GETSYM(Wkh, g_Wkh); GETSYM(Wkl, g_Wkl);
    GETSYM(Wvh, g_Wvh); GETSYM(Wvl, g_Wvl); GETSYM(Woh, g_Woh); GETSYM(Wol, g_Wol);
    uint16_t *l1h, *l1l, *l2h, *l2l, *ts;
    GETSYM(l1h, g_l1h); GETSYM(l1l, g_l1l); GETSYM(l2h, g_l2h); GETSYM(l2l, g_l2l);
    GETSYM(ts, g_ts);

    cudaFuncSetAttribute(mma_gemm<0>, cudaFuncAttributeMaxDynamicSharedMemorySize, GEMM_SMEM);
    cudaFuncSetAttribute(mma_gemm<1>, cudaFuncAttributeMaxDynamicSharedMemorySize, GEMM_SMEM);
    cudaFuncSetAttribute(mma_gemm<2>, cudaFuncAttributeMaxDynamicSharedMemorySize, GEMM_SMEM);

    static cudaStream_t s1 = nullptr;
    static cudaEvent_t eFork = nullptr, eJoin = nullptr;
    if (s1 == nullptr) {
        cudaStreamCreateWithFlags(&s1, cudaStreamNonBlocking);
        cudaEventCreateWithFlags(&eFork, cudaEventDisableTiming);
        cudaEventCreateWithFlags(&eJoin, cudaEventDisableTiming);
    }

    // conversions
    prep_kernel<<<dim3(BT, 2), 256>>>(x, mask, x_r, x_w, x_k, x_v, x_a, x_g);
    wsplit_kernel<<<(Cc * Cc) / 1024, 256>>>(W_r, W_k, W_v, W_o);
    LoraSrc ls;
    ls.s1[0] = w1; ls.s1[1] = a1; ls.s1[2] = v1; ls.s1[3] = g1;
    ls.s2[0] = w2; ls.s2[1] = a2; ls.s2[2] = v2; ls.s2[3] = g2;
    lsplit_kernel<<<dim3(1024, 8), 256>>>(ls);

    cudaEventRecord(eFork, 0);
    cudaStreamWaitEvent(s1, eFork, 0);

    const size_t L1 = (size_t)LORA_PAD * Cc, L2 = (size_t)Cc * LORA_PAD;
    const size_t TS = (size_t)BT * LORA_PAD;

    // side stream: v_first passthrough + LoRA stage1 + v-independent stage2 paths
    if ((size_t)out_size >= 2 * BTC) {
        cudaMemcpyAsync(out + BTC, v_first, BTC * sizeof(float),
                        cudaMemcpyDeviceToDevice, s1);
    }
    GemmB b1 = {};
    b1.Aa[0] = xw; b1.Aa[1] = xa; b1.Aa[2] = xv; b1.Aa[3] = xg;
    for (int p = 0; p < 4; p++) {
        b1.Bh[p] = l1h + p * L1; b1.Bl[p] = l1l + p * L1;
        b1.Oh[p] = ts + p * TS;
    }
    mma_gemm<1><<<dim3(4, 64), 256, GEMM_SMEM, s1>>>(b1, Cc);

    GemmB b2a = {};
    b2a.Aa[0] = ts + 0 * TS; b2a.Bh[0] = l2h + 0 * L2; b2a.Bl[0] = l2l + 0 * L2;
    b2a.Of[0] = wd; b2a.bias[0] = w0; b2a.etype[0] = 0;
    b2a.Aa[1] = ts + 1 * TS; b2a.Bh[1] = l2h + 1 * L2; b2a.Bl[1] = l2l + 1 * L2;
    b2a.Of[1] = as; b2a.bias[1] = a0; b2a.etype[1] = 1;
    b2a.Aa[2] = ts + 3 * TS; b2a.Bh[2] = l2h + 3 * L2; b2a.Bl[2] = l2l + 3 * L2;
    b2a.Of[2] = gg; b2a.bias[2] = w0; b2a.etype[2] = 3;
    mma_gemm<2><<<dim3(48, 64), 256, GEMM_SMEM, s1>>>(b2a, LORA_PAD);
    cudaEventRecord(eJoin, s1);

    // main stream: batched r,k,v projections
    GemmB b0 = {};
    b0.Aa[0] = xr; b0.Bh[0] = Wrh; b0.Bl[0] = Wrl; b0.Of[0] = rr;
    b0.Aa[1] = xk; b0.Bh[1] = Wkh; b0.Bl[1] = Wkl; b0.Of[1] = kb;
    b0.Aa[2] = xv; b0.Bh[2] = Wvh; b0.Bl[2] = Wvl; b0.Of[2] = vb;
    mma_gemm<0><<<dim3(48, 64), 256, GEMM_SMEM>>>(b0, Cc);

    cudaStreamWaitEvent(0, eJoin, 0);

    // stage2 v path
    GemmB b2b = {};
    b2b.Aa[0] = ts + 2 * TS; b2b.Bh[0] = l2h + 2 * L2; b2b.Bl[0] = l2l + 2 * L2;
    b2b.Of[0] = vb; b2b.bias[0] = v0; b2b.etype[0] = 2;
    b2b.vf = v_first; b2b.mask = mask;
    mma_gemm<2><<<dim3(16, 64), 256, GEMM_SMEM>>>(b2b, LORA_PAD);

    // pack, scan, post
    pack_kernel<<<(BT * Hh) / 8, 256>>>(k_k, k_a, as, wd, rr, vb, kb, pk);
    scan_kernel<<<Bb * Hh, 128>>>(pk, yb);
    post_kernel<<<(BT * Hh) / 8, 256>>>(yb, rr, kb, vb, gg, r_k, ln_w, ln_b, yg);

    // output projection
    GemmB bo = {};
    bo.Aa[0] = yg; bo.Bh[0] = Woh; bo.Bl[0] = Wol; bo.Of[0] = out;
    mma_gemm<0><<<dim3(16, 64), 256, GEMM_SMEM>>>(bo, Cc);
}

// round 10
// speedup vs baseline: 5.6157x; 1.2780x over previous
#include <cuda_runtime.h>
#include <cuda_bf16.h>
#include <cuda_fp16.h>
#include <cstdint>

// ---------------- problem constants ----------------
#define Bb 8
#define Tt 1024
#define Cc 2048
#define Hh 32
#define Nn 64
#define BT (Bb*Tt)                  // 8192
#define BTC ((size_t)BT*Cc)         // 16.7M
#define LORA_PAD 128
#define LN_EPS (1e-5f*64.0f)

// ---------------- scratch (device globals) ----------------
__device__ float g_r[BTC], g_k[BTC], g_v[BTC];
__device__ float g_wdec[BTC], g_asig[BTC], g_g[BTC], g_y[BTC];
// packed scan inputs: per (bt,h): 384 floats = [WB 128][KR 128][A2 64][V 64]
__device__ float g_pack[(size_t)BT*Hh*384];

// fp16 activations (A operands)
__device__ uint16_t g_xr[BTC], g_xw[BTC], g_xk[BTC], g_xv[BTC], g_xa[BTC], g_xg[BTC];
__device__ uint16_t g_yg[BTC];
// fp16 big weights (single term)
__device__ uint16_t g_Wr[Cc*Cc], g_Wk[Cc*Cc], g_Wv[Cc*Cc], g_Wo[Cc*Cc];
// LoRA weights (2-term split)
__device__ uint16_t g_l1h[4][LORA_PAD*Cc], g_l1l[4][LORA_PAD*Cc];
__device__ uint16_t g_l2h[4][Cc*LORA_PAD], g_l2l[4][Cc*LORA_PAD];
__device__ uint16_t g_ts[4][(size_t)BT*LORA_PAD];

// ---------------- helpers ----------------
__device__ __forceinline__ void h1store(float v, uint16_t* dst, size_t i) {
    reinterpret_cast<__half*>(dst)[i] = __float2half_rn(v);
}
__device__ __forceinline__ void h4store(float4 v, uint16_t* dst, size_t i) {
    __half2 a = __floats2half2_rn(v.x, v.y);
    __half2 b = __floats2half2_rn(v.z, v.w);
    *reinterpret_cast<uint2*>(dst + i) =
        make_uint2(*reinterpret_cast<uint32_t*>(&a), *reinterpret_cast<uint32_t*>(&b));
}
__device__ __forceinline__ void hsplit1(float v, uint16_t* hi, uint16_t* lo, size_t i) {
    __half h = __float2half_rn(v);
    float hf = __half2float(h);
    __half l = __float2half_rn(v - hf);
    reinterpret_cast<__half*>(hi)[i] = h;
    reinterpret_cast<__half*>(lo)[i] = l;
}

__device__ __forceinline__ uint32_t smem_u32(const void* p) {
    uint32_t a;
    asm("{ .reg .u64 t; cvta.to.shared.u64 t, %1; cvt.u32.u64 %0, t; }" : "=r"(a) : "l"(p));
    return a;
}
#define SWZ128(o) ((o) ^ (((o) >> 3) & 0x70))

__device__ __forceinline__ void cpa16(uint32_t daddr, const void* g)
{
    asm volatile("cp.async.cg.shared.global [%0], [%1], 16;"
                 :: "r"(daddr), "l"(__cvta_generic_to_global(g)) : "memory");
}

__device__ __forceinline__ void ldsm4(uint32_t& r0, uint32_t& r1, uint32_t& r2, uint32_t& r3,
                                      uint32_t addr)
{
    asm volatile("ldmatrix.sync.aligned.m8n8.x4.shared.b16 {%0,%1,%2,%3}, [%4];"
                 : "=r"(r0), "=r"(r1), "=r"(r2), "=r"(r3) : "r"(addr));
}

__device__ __forceinline__ void mma16816(float* c, const uint32_t* a, const uint32_t* b)
{
    asm volatile("mma.sync.aligned.m16n8k16.row.col.f32.f16.f16.f32 "
                 "{%0,%1,%2,%3}, {%4,%5,%6,%7}, {%8,%9}, {%0,%1,%2,%3};"
                 : "+f"(c[0]), "+f"(c[1]), "+f"(c[2]), "+f"(c[3])
                 : "r"(a[0]), "r"(a[1]), "r"(a[2]), "r"(a[3]), "r"(b[0]), "r"(b[1]));
}

// packed f32x2 (sm_100+)
typedef unsigned long long u64t;
__device__ __forceinline__ u64t pk2(float x, float y){ u64t d; asm("mov.b64 %0, {%1,%2};" : "=l"(d) : "f"(x), "f"(y)); return d; }
__device__ __forceinline__ void upk2(u64t d, float& x, float& y){ asm("mov.b64 {%0,%1}, %2;" : "=f"(x), "=f"(y) : "l"(d)); }
__device__ __forceinline__ u64t fma2(u64t a, u64t b, u64t c){ u64t d; asm("fma.rn.f32x2 %0, %1, %2, %3;" : "=l"(d) : "l"(a), "l"(b), "l"(c)); return d; }
__device__ __forceinline__ u64t mul2(u64t a, u64t b){ u64t d; asm("mul.rn.f32x2 %0, %1, %2;" : "=l"(d) : "l"(a), "l"(b)); return d; }

// ---------------- prep: mask + time-shift mixes -> fp16 ----------------
__global__ void prep_kernel(const float* __restrict__ x, const float* __restrict__ mask,
                            const float* __restrict__ mr, const float* __restrict__ mw,
                            const float* __restrict__ mk, const float* __restrict__ mv,
                            const float* __restrict__ ma, const float* __restrict__ mg)
{
    int bt = blockIdx.x;
    int c  = blockIdx.y * 1024 + threadIdx.x * 4;
    int t  = bt & (Tt - 1);
    float m  = mask[bt];
    float mp = (t > 0) ? mask[bt - 1] : 0.f;
    size_t idx = (size_t)bt * Cc + c;
    float4 xv = *reinterpret_cast<const float4*>(&x[idx]);
    float4 xp = make_float4(0.f, 0.f, 0.f, 0.f);
    if (t > 0) xp = *reinterpret_cast<const float4*>(&x[idx - Cc]);
    float4 xm = make_float4(xv.x*m, xv.y*m, xv.z*m, xv.w*m);
    float4 xx = make_float4(xp.x*mp - xm.x, xp.y*mp - xm.y, xp.z*mp - xm.z, xp.w*mp - xm.w);
#define MIX(MM, DD) { \
    float4 mm = *reinterpret_cast<const float4*>(&MM[c]); \
    float4 vv = make_float4(xm.x + xx.x*mm.x, xm.y + xx.y*mm.y, xm.z + xx.z*mm.z, xm.w + xx.w*mm.w); \
    h4store(vv, DD, idx); }
    MIX(mr, g_xr); MIX(mw, g_xw); MIX(mk, g_xk);
    MIX(mv, g_xv); MIX(ma, g_xa); MIX(mg, g_xg);
#undef MIX
}

__global__ void wconv_kernel(const float* __restrict__ Wr, const float* __restrict__ Wk,
                             const float* __restrict__ Wv, const float* __restrict__ Wo)
{
    size_t i = ((size_t)blockIdx.x * 256 + threadIdx.x) * 4;
    h4store(*reinterpret_cast<const float4*>(&Wr[i]), g_Wr, i);
    h4store(*reinterpret_cast<const float4*>(&Wk[i]), g_Wk, i);
    h4store(*reinterpret_cast<const float4*>(&Wv[i]), g_Wv, i);
    h4store(*reinterpret_cast<const float4*>(&Wo[i]), g_Wo, i);
}

struct LoraSrc { const float* s1[4]; const float* s2[4]; };
__constant__ int c_D[4] = {96, 96, 64, 128};

__global__ void lsplit_kernel(LoraSrc ls)
{
    int id = blockIdx.y;
    int i = blockIdx.x * 256 + threadIdx.x;
    if (id < 4) {
        int D = c_D[id];
        int n = i >> 11, kcol = i & 2047;
        float v = (n < D) ? ls.s1[id][(size_t)kcol * D + n] : 0.f;
        hsplit1(v, g_l1h[id], g_l1l[id], i);
    } else {
        int p = id - 4;
        int D = c_D[p];
        int n = i >> 7, kcol = i & 127;
        float v = (kcol < D) ? ls.s2[p][(size_t)kcol * Cc + n] : 0.f;
        hsplit1(v, g_l2h[p], g_l2l[p], i);
    }
}

// ---------------- GEMM ----------------
// NB=1: single-term B (big GEMMs), 3-stage 32KB pipeline.
// NB=2: B split hi/lo (LoRA), 2-stage 48KB pipeline.
// MODE 0: batched fp32 out [*,2048].  MODE 1: LoRA stage1, fp16 out [*,128].
// MODE 2: LoRA stage2, fused elementwise by etype.
#define ATILE_B 16384
#define GEMM_SMEM 98304

struct GemmB {
    const uint16_t *Aa[4], *Bh[4], *Bl[4];
    uint16_t *Oh[4];
    float *Of[4];
    const float *bias[4];
    int etype[4];                   // MODE2: 0=wdec 1=asig 2=vupd 3=copy
    const float *vf, *mask;
};

template<int MODE, int NB>
__global__ __launch_bounds__(256, 2)
void mma_gemm(GemmB bp, int K)
{
    extern __shared__ char smem[];
    constexpr uint32_t STB = (uint32_t)(1 + NB) * ATILE_B;
    constexpr int NSTAGE = (NB == 1) ? 3 : 2;
    const uint32_t sb = smem_u32(smem);
    const int tid = threadIdx.x, lane = tid & 31, warp = tid >> 5;
    const int warpM = warp >> 1, warpN = warp & 1;
    const int m0 = blockIdx.y * 128;
    int n0, path;
    if (MODE == 1) { path = blockIdx.x;      n0 = 0; }
    else           { path = blockIdx.x >> 4; n0 = (blockIdx.x & 15) * 128; }
    const uint16_t* Aa  = bp.Aa[path];
    const uint16_t* Bhi = bp.Bh[path];
    const uint16_t* Blo = bp.Bl[path];
    const int kc = K >> 6;

    float acc[2][8][4];
#pragma unroll
    for (int mt = 0; mt < 2; mt++)
#pragma unroll
        for (int nt = 0; nt < 8; nt++)
#pragma unroll
            for (int e = 0; e < 4; e++) acc[mt][nt][e] = 0.f;

    auto load_chunk = [&](int c) {
        const uint32_t stb = sb + (uint32_t)(c % NSTAGE) * STB;
        const int k0 = c << 6;
#pragma unroll
        for (int a3 = 0; a3 < 1 + NB; a3++) {
            const uint16_t* src = (a3 == 0) ? Aa : ((a3 == 1) ? Bhi : Blo);
            const int rb = (a3 == 0) ? m0 : n0;
            const uint32_t ab = stb + a3 * ATILE_B;
#pragma unroll
            for (int jj = 0; jj < 4; jj++) {
                int T = tid + jj * 256;
                int row = T >> 3, seg = T & 7;
                cpa16(ab + SWZ128(row * 128 + seg * 16),
                      src + (size_t)(rb + row) * K + k0 + seg * 8);
            }
        }
    };

    if (NB == 1) {
        load_chunk(0);
        asm volatile("cp.async.commit_group;" ::: "memory");
        if (1 < kc) load_chunk(1);
        asm volatile("cp.async.commit_group;" ::: "memory");
    } else {
        load_chunk(0);
        asm volatile("cp.async.commit_group;" ::: "memory");
    }

    const int aRowOff = warpM * 32 + (lane & 15);
    const int aKbase  = (lane >> 4) << 4;
    const int bRowOff = warpN * 64 + (lane & 7) + ((lane >> 1) & 8);
    const int bKbase  = ((lane >> 3) & 1) * 16;

    for (int c = 0; c < kc; c++) {
        if (NB == 1) {
            asm volatile("cp.async.wait_group 1;" ::: "memory");
            __syncthreads();
            if (c + 2 < kc) load_chunk(c + 2);
            asm volatile("cp.async.commit_group;" ::: "memory");
        } else {
            __syncthreads();
            if (c + 1 < kc) load_chunk(c + 1);
            asm volatile("cp.async.commit_group;" ::: "memory");
            asm volatile("cp.async.wait_group 1;" ::: "memory");
            __syncthreads();
        }

        const uint32_t stb = sb + (uint32_t)(c % NSTAGE) * STB;
        const uint32_t sA = stb, sBh = stb + ATILE_B, sBl = stb + 2u * ATILE_B;
#pragma unroll
        for (int s = 0; s < 4; s++) {
            const int akb = s * 32 + aKbase;
            const int bkb = s * 32 + bKbase;
            uint32_t a[2][4];
#pragma unroll
            for (int mt = 0; mt < 2; mt++) {
                int ro = (aRowOff + mt * 16) * 128;
                ldsm4(a[mt][0], a[mt][1], a[mt][2], a[mt][3], sA + SWZ128(ro + akb));
            }
            uint32_t b[8][2];
#pragma unroll
            for (int p = 0; p < 4; p++) {
                int ro = (bRowOff + p * 16) * 128;
                uint32_t r0, r1, r2, r3;
                ldsm4(r0, r1, r2, r3, sBh + SWZ128(ro + bkb));
                b[p*2][0] = r0; b[p*2][1] = r1; b[p*2+1][0] = r2; b[p*2+1][1] = r3;
            }
#pragma unroll
            for (int mt = 0; mt < 2; mt++)
#pragma unroll
                for (int nt = 0; nt < 8; nt++)
                    mma16816(acc[mt][nt], a[mt], b[nt]);
            if (NB == 2) {
#pragma unroll
                for (int p = 0; p < 4; p++) {
                    int ro = (bRowOff + p * 16) * 128;
                    uint32_t r0, r1, r2, r3;
                    ldsm4(r0, r1, r2, r3, sBl + SWZ128(ro + bkb));
                    b[p*2][0] = r0; b[p*2][1] = r1; b[p*2+1][0] = r2; b[p*2+1][1] = r3;
                }
#pragma unroll
                for (int mt = 0; mt < 2; mt++)
#pragma unroll
                    for (int nt = 0; nt < 8; nt++)
                        mma16816(acc[mt][nt], a[mt], b[nt]);
            }
        }
    }

    // epilogue
    const int row0 = m0 + warpM * 32 + (lane >> 2);
    const int col0 = n0 + warpN * 64 + (lane & 3) * 2;
    const int et = (MODE == 2) ? bp.etype[path] : 0;
#pragma unroll
    for (int mt = 0; mt < 2; mt++) {
#pragma unroll
        for (int nt = 0; nt < 8; nt++) {
            int r1 = row0 + mt * 16;
            int c1 = col0 + nt * 8;
            float v0 = acc[mt][nt][0], v1 = acc[mt][nt][1];
            float v2 = acc[mt][nt][2], v3 = acc[mt][nt][3];
            if (MODE == 0) {
                float* Cf = bp.Of[path];
                *reinterpret_cast<float2*>(&Cf[(size_t)r1 * Cc + c1]) = make_float2(v0, v1);
                *reinterpret_cast<float2*>(&Cf[(size_t)(r1 + 8) * Cc + c1]) = make_float2(v2, v3);
            } else if (MODE == 1) {
                if (path == 0) { v0 = tanhf(v0); v1 = tanhf(v1); v2 = tanhf(v2); v3 = tanhf(v3); }
                else if (path == 3) {
                    v0 = 1.f/(1.f+expf(-v0)); v1 = 1.f/(1.f+expf(-v1));
                    v2 = 1.f/(1.f+expf(-v2)); v3 = 1.f/(1.f+expf(-v3));
                }
                uint16_t* oh = bp.Oh[path];
                h1store(v0, oh, (size_t)r1 * LORA_PAD + c1);
                h1store(v1, oh, (size_t)r1 * LORA_PAD + c1 + 1);
                h1store(v2, oh, (size_t)(r1 + 8) * LORA_PAD + c1);
                h1store(v3, oh, (size_t)(r1 + 8) * LORA_PAD + c1 + 1);
            } else {
                float* Of = bp.Of[path];
                const float* bias = bp.bias[path];
                auto ep = [&](float z, int rr_, int cc_) {
                    size_t idx = (size_t)rr_ * Cc + cc_;
                    if (et == 0) {
                        float zz = bias[cc_] + z;
                        float nz = -zz;
                        float sp = (nz > 20.f) ? nz : log1pf(expf(nz));
                        Of[idx] = expf(-expf(-sp - 0.5f));
                    } else if (et == 1) {
                        Of[idx] = 1.f / (1.f + expf(-(bias[cc_] + z)));
                    } else if (et == 2) {
                        float s = 1.f / (1.f + expf(-(bias[cc_] + z)));
                        float vv = Of[idx];
                        Of[idx] = (vv + (bp.vf[idx] - vv) * s) * bp.mask[rr_];
                    } else {
                        Of[idx] = z;
                    }
                };
                ep(v0, r1, c1); ep(v1, r1, c1 + 1);
                ep(v2, r1 + 8, c1); ep(v3, r1 + 8, c1 + 1);
            }
        }
    }
}

// ---------------- pack: kk-normalize + k-rescale + scan-input packing ----------
__global__ void pack_kernel(const float* __restrict__ kkp, const float* __restrict__ kap,
                            const float* __restrict__ asig, const float* __restrict__ wd,
                            const float* __restrict__ r, const float* __restrict__ v,
                            float* __restrict__ k, float* __restrict__ pack)
{
    int gid = blockIdx.x * 8 + (threadIdx.x >> 5);   // bt*Hh + h
    int l = threadIdx.x & 31;
    int h = gid & (Hh - 1);
    size_t bt = (size_t)gid >> 5;
    size_t base = bt * Cc + (size_t)h * Nn + 2 * l;
    int c0 = h * Nn + 2 * l;
    float2 kv = *reinterpret_cast<const float2*>(&k[base]);
    float2 kp = *reinterpret_cast<const float2*>(&kkp[c0]);
    float kk0 = kv.x * kp.x, kk1 = kv.y * kp.y;
    float ss = kk0 * kk0 + kk1 * kk1;
#pragma unroll
    for (int o = 16; o > 0; o >>= 1) ss += __shfl_xor_sync(0xffffffffu, ss, o);
    float inv = 1.f / fmaxf(sqrtf(ss), 1e-12f);
    kk0 *= inv; kk1 *= inv;
    float2 as2 = *reinterpret_cast<const float2*>(&asig[base]);
    float2 ka2 = *reinterpret_cast<const float2*>(&kap[c0]);
    float kn0 = kv.x * (1.f + (as2.x - 1.f) * ka2.x);
    float kn1 = kv.y * (1.f + (as2.y - 1.f) * ka2.y);
    *reinterpret_cast<float2*>(&k[base]) = make_float2(kn0, kn1);
    float2 w2 = *reinterpret_cast<const float2*>(&wd[base]);
    float2 r2 = *reinterpret_cast<const float2*>(&r[base]);
    float2 v2 = *reinterpret_cast<const float2*>(&v[base]);
    float* pb = pack + (size_t)gid * 384;
    *reinterpret_cast<float4*>(&pb[l * 4])       = make_float4(w2.x, w2.y, kk0 * as2.x, kk1 * as2.y);
    *reinterpret_cast<float4*>(&pb[128 + l * 4]) = make_float4(kn0, kn1, r2.x, r2.y);
    *reinterpret_cast<float2*>(&pb[256 + l * 2]) = make_float2(-kk0, -kk1);
    *reinterpret_cast<float2*>(&pb[320 + l * 2]) = v2;
}

// ---------------- RWKV-7 scan: cp.async depth-4 pipeline -----------------------
__global__ __launch_bounds__(128)
void scan_kernel(const float* __restrict__ pack, float* __restrict__ y)
{
    int bh = blockIdx.x;
    int b = bh >> 5, h = bh & (Hh - 1);
    int tid = threadIdx.x;
    int j = tid >> 1, half = tid & 1;
    __shared__ __align__(16) char buf[4][1536];
    const char* src = reinterpret_cast<const char*>(
        pack + ((size_t)b * Tt * Hh + h) * 384);
    const size_t stepB = (size_t)Hh * 1536;
    const uint32_t sbase = smem_u32(buf);
    u64t S[16];
#pragma unroll
    for (int i = 0; i < 16; i++) S[i] = 0ull;

#pragma unroll
    for (int pt = 0; pt < 3; pt++) {
        if (tid < 96) cpa16(sbase + pt * 1536 + tid * 16, src + pt * stepB + tid * 16);
        asm volatile("cp.async.commit_group;" ::: "memory");
    }

    size_t ybase = ((size_t)b * Tt) * Cc + (size_t)h * Nn + j;
    for (int t = 0; t < Tt; t++) {
        asm volatile("cp.async.wait_group 2;" ::: "memory");
        __syncthreads();
        if (t + 3 < Tt && tid < 96)
            cpa16(sbase + ((t + 3) & 3) * 1536 + tid * 16, src + (t + 3) * stepB + tid * 16);
        asm volatile("cp.async.commit_group;" ::: "memory");

        const float* W = reinterpret_cast<const float*>(buf[t & 3]);
        float vj = W[320 + j];
        u64t q0 = 0ull, q1 = 0ull, q2 = 0ull, q3 = 0ull;
#pragma unroll
        for (int ii = 0; ii < 16; ii += 4) {
            q0 = fma2(S[ii + 0], *reinterpret_cast<const u64t*>(W + 256 + (2*(ii+0)+half)*2), q0);
            q1 = fma2(S[ii + 1], *reinterpret_cast<const u64t*>(W + 256 + (2*(ii+1)+half)*2), q1);
            q2 = fma2(S[ii + 2], *reinterpret_cast<const u64t*>(W + 256 + (2*(ii+2)+half)*2), q2);
            q3 = fma2(S[ii + 3], *reinterpret_cast<const u64t*>(W + 256 + (2*(ii+3)+half)*2), q3);
        }
        float ax, ay, bx, by, cx, cy, dx, dy;
        upk2(q0, ax, ay); upk2(q1, bx, by); upk2(q2, cx, cy); upk2(q3, dx, dy);
        float sacc = ((ax + ay) + (bx + by)) + ((cx + cy) + (dx + dy));
        sacc += __shfl_xor_sync(0xffffffffu, sacc, 1);
        u64t sacc2 = pk2(sacc, sacc);
        u64t vj2 = pk2(vj, vj);
        u64t ya = 0ull, yb = 0ull;
#pragma unroll
        for (int ii = 0; ii < 16; ii++) {
            int p = 2 * ii + half;
            float4 wb = *reinterpret_cast<const float4*>(W + p * 4);
            float4 kr = *reinterpret_cast<const float4*>(W + 128 + p * 4);
            u64t s = fma2(S[ii], pk2(wb.x, wb.y),
                          fma2(sacc2, pk2(wb.z, wb.w), mul2(vj2, pk2(kr.x, kr.y))));
            S[ii] = s;
            if (ii & 1) yb = fma2(s, pk2(kr.z, kr.w), yb);
            else        ya = fma2(s, pk2(kr.z, kr.w), ya);
        }
        float y0x, y0y, y1x, y1y;
        upk2(ya, y0x, y0y); upk2(yb, y1x, y1y);
        float yv = (y0x + y0y) + (y1x + y1y);
        yv += __shfl_xor_sync(0xffffffffu, yv, 1);
        if (half == 0) y[ybase + (size_t)t * Cc] = yv;
    }
}

// ---------------- groupnorm + rk*v + gate -> fp16 ----------------
__global__ void post_kernel(const float* __restrict__ y, const float* __restrict__ r,
                            const float* __restrict__ k, const float* __restrict__ v,
                            const float* __restrict__ g, const float* __restrict__ r_k,
                            const float* __restrict__ ln_w, const float* __restrict__ ln_b,
                            uint16_t* __restrict__ oh)
{
    int gid = blockIdx.x * 8 + (threadIdx.x >> 5);
    int lane = threadIdx.x & 31;
    int h = gid % Hh;
    size_t bt = gid / Hh;
    size_t base = bt * Cc + (size_t)h * Nn;
    int c0 = h * Nn + lane, c1 = c0 + 32;
    float y0 = y[base + lane], y1 = y[base + lane + 32];
    float sum = y0 + y1;
#pragma unroll
    for (int o = 16; o > 0; o >>= 1) sum += __shfl_xor_sync(0xffffffffu, sum, o);
    float mean = sum * (1.f / 64.f);
    float d0 = y0 - mean, d1 = y1 - mean;
    float var = d0 * d0 + d1 * d1;
#pragma unroll
    for (int o = 16; o > 0; o >>= 1) var += __shfl_xor_sync(0xffffffffu, var, o);
    var *= (1.f / 64.f);
    float inv = rsqrtf(var + LN_EPS);
    float yn0 = d0 * inv * ln_w[c0] + ln_b[c0];
    float yn1 = d1 * inv * ln_w[c1] + ln_b[c1];
    float rk = r[base + lane] * k[base + lane] * r_k[c0]
             + r[base + lane + 32] * k[base + lane + 32] * r_k[c1];
#pragma unroll
    for (int o = 16; o > 0; o >>= 1) rk += __shfl_xor_sync(0xffffffffu, rk, o);
    float o0 = (yn0 + rk * v[base + lane]) * g[base + lane];
    float o1 = (yn1 + rk * v[base + lane + 32]) * g[base + lane + 32];
    h1store(o0, oh, base + lane);
    h1store(o1, oh, base + lane + 32);
}

// ---------------- launch ----------------
#define GETSYM(var, sym) do { void* _p; cudaGetSymbolAddress(&_p, sym); var = (decltype(var))_p; } while (0)

extern "C" void kernel_launch(void* const* d_in, const int* in_sizes, int n_in,
                              void* d_out, int out_size)
{
    const float* x       = (const float*)d_in[0];
    const float* mask    = (const float*)d_in[1];
    const float* v_first = (const float*)d_in[2];
    const float* x_r = (const float*)d_in[3];
    const float* x_w = (const float*)d_in[4];
    const float* x_k = (const float*)d_in[5];
    const float* x_v = (const float*)d_in[6];
    const float* x_a = (const float*)d_in[7];
    const float* x_g = (const float*)d_in[8];
    const float* w0 = (const float*)d_in[9];
    const float* w1 = (const float*)d_in[10];
    const float* w2 = (const float*)d_in[11];
    const float* a0 = (const float*)d_in[12];
    const float* a1 = (const float*)d_in[13];
    const float* a2 = (const float*)d_in[14];
    const float* v0 = (const float*)d_in[15];
    const float* v1 = (const float*)d_in[16];
    const float* v2 = (const float*)d_in[17];
    const float* g1 = (const float*)d_in[18];
    const float* g2 = (const float*)d_in[19];
    const float* k_k = (const float*)d_in[20];
    const float* k_a = (const float*)d_in[21];
    const float* r_k = (const float*)d_in[22];
    const float* W_r = (const float*)d_in[23];
    const float* W_k = (const float*)d_in[24];
    const float* W_v = (const float*)d_in[25];
    const float* W_o = (const float*)d_in[26];
    const float* ln_w = (const float*)d_in[27];
    const float* ln_b = (const float*)d_in[28];
    float* out = (float*)d_out;

    float *rr, *kb, *vb, *wd, *as, *gg, *yb, *pk;
    GETSYM(rr, g_r); GETSYM(kb, g_k); GETSYM(vb, g_v);
    GETSYM(wd, g_wdec); GETSYM(as, g_asig); GETSYM(gg, g_g);
    GETSYM(yb, g_y); GETSYM(pk, g_pack);
    uint16_t *xr,*xw,*xk,*xv,*xa,*xg,*yg;
    GETSYM(xr, g_xr); GETSYM(xw, g_xw); GETSYM(xk, g_xk);
    GETSYM(xv, g_xv); GETSYM(xa, g_xa); GETSYM(xg, g_xg);
    GETSYM(yg, g_yg);
    uint16_t *Wr,*Wk,*Wv,*Wo;
    GETSYM(Wr, g_Wr); GETSYM(Wk, g_Wk); GETSYM(Wv, g_Wv); GETSYM(Wo, g_Wo);
    uint16_t *l1h, *l1l, *l2h, *l2l, *ts;
    GETSYM(l1h, g_l1h); GETSYM(l1l, g_l1l); GETSYM(l2h, g_l2h); GETSYM(l2l, g_l2l);
    GETSYM(ts, g_ts);

    cudaFuncSetAttribute(mma_gemm<0,1>, cudaFuncAttributeMaxDynamicSharedMemorySize, GEMM_SMEM);
    cudaFuncSetAttribute(mma_gemm<1,2>, cudaFuncAttributeMaxDynamicSharedMemorySize, GEMM_SMEM);
    cudaFuncSetAttribute(mma_gemm<2,2>, cudaFuncAttributeMaxDynamicSharedMemorySize, GEMM_SMEM);

    static cudaStream_t s1 = nullptr;
    static cudaEvent_t ePrep = nullptr, eW = nullptr, eJoin = nullptr;
    if (s1 == nullptr) {
        cudaStreamCreateWithFlags(&s1, cudaStreamNonBlocking);
        cudaEventCreateWithFlags(&ePrep, cudaEventDisableTiming);
        cudaEventCreateWithFlags(&eW, cudaEventDisableTiming);
        cudaEventCreateWithFlags(&eJoin, cudaEventDisableTiming);
    }
    static cudaEvent_t eStart = nullptr;
    if (eStart == nullptr) cudaEventCreateWithFlags(&eStart, cudaEventDisableTiming);

    // fork side stream at the very start
    cudaEventRecord(eStart, 0);
    cudaStreamWaitEvent(s1, eStart, 0);

    // main: prep (activations)
    prep_kernel<<<dim3(BT, 2), 256>>>(x, mask, x_r, x_w, x_k, x_v, x_a, x_g);
    cudaEventRecord(ePrep, 0);

    // side: weight conversions + v_first copy (independent of prep)
    if ((size_t)out_size >= 2 * BTC) {
        cudaMemcpyAsync(out + BTC, v_first, BTC * sizeof(float),
                        cudaMemcpyDeviceToDevice, s1);
    }
    wconv_kernel<<<(Cc * Cc) / 1024, 256, 0, s1>>>(W_r, W_k, W_v, W_o);
    LoraSrc ls;
    ls.s1[0] = w1; ls.s1[1] = a1; ls.s1[2] = v1; ls.s1[3] = g1;
    ls.s2[0] = w2; ls.s2[1] = a2; ls.s2[2] = v2; ls.s2[3] = g2;
    lsplit_kernel<<<dim3(1024, 8), 256, 0, s1>>>(ls);
    cudaEventRecord(eW, s1);

    const size_t L1 = (size_t)LORA_PAD * Cc, L2 = (size_t)Cc * LORA_PAD;
    const size_t TS = (size_t)BT * LORA_PAD;

    // side: LoRA stage1 (needs prep outputs) + v-independent stage2 paths
    cudaStreamWaitEvent(s1, ePrep, 0);
    GemmB b1 = {};
    b1.Aa[0] = xw; b1.Aa[1] = xa; b1.Aa[2] = xv; b1.Aa[3] = xg;
    for (int p = 0; p < 4; p++) {
        b1.Bh[p] = l1h + p * L1; b1.Bl[p] = l1l + p * L1;
        b1.Oh[p] = ts + p * TS;
    }
    mma_gemm<1,2><<<dim3(4, 64), 256, GEMM_SMEM, s1>>>(b1, Cc);

    GemmB b2a = {};
    b2a.Aa[0] = ts + 0 * TS; b2a.Bh[0] = l2h + 0 * L2; b2a.Bl[0] = l2l + 0 * L2;
    b2a.Of[0] = wd; b2a.bias[0] = w0; b2a.etype[0] = 0;
    b2a.Aa[1] = ts + 1 * TS; b2a.Bh[1] = l2h + 1 * L2; b2a.Bl[1] = l2l + 1 * L2;
    b2a.Of[1] = as; b2a.bias[1] = a0; b2a.etype[1] = 1;
    b2a.Aa[2] = ts + 3 * TS; b2a.Bh[2] = l2h + 3 * L2; b2a.Bl[2] = l2l + 3 * L2;
    b2a.Of[2] = gg; b2a.bias[2] = w0; b2a.etype[2] = 3;
    mma_gemm<2,2><<<dim3(48, 64), 256, GEMM_SMEM, s1>>>(b2a, LORA_PAD);
    cudaEventRecord(eJoin, s1);

    // main: batched r,k,v projections (needs weights from side stream)
    cudaStreamWaitEvent(0, eW, 0);
    GemmB b0 = {};
    b0.Aa[0] = xr; b0.Bh[0] = Wr; b0.Of[0] = rr;
    b0.Aa[1] = xk; b0.Bh[1] = Wk; b0.Of[1] = kb;
    b0.Aa[2] = xv; b0.Bh[2] = Wv; b0.Of[2] = vb;
    mma_gemm<0,1><<<dim3(48, 64), 256, GEMM_SMEM>>>(b0, Cc);

    cudaStreamWaitEvent(0, eJoin, 0);

    // stage2 v path
    GemmB b2b = {};
    b2b.Aa[0] = ts + 2 * TS; b2b.Bh[0] = l2h + 2 * L2; b2b.Bl[0] = l2l + 2 * L2;
    b2b.Of[0] = vb; b2b.bias[0] = v0; b2b.etype[0] = 2;
    b2b.vf = v_first; b2b.mask = mask;
    mma_gemm<2,2><<<dim3(16, 64), 256, GEMM_SMEM>>>(b2b, LORA_PAD);

    // pack, scan, post
    pack_kernel<<<(BT * Hh) / 8, 256>>>(k_k, k_a, as, wd, rr, vb, kb, pk);
    scan_kernel<<<Bb * Hh, 128>>>(pk, yb);
    post_kernel<<<(BT * Hh) / 8, 256>>>(yb, rr, kb, vb, gg, r_k, ln_w, ln_b, yg);

    // output projection
    GemmB bo = {};
    bo.Aa[0] = yg; bo.Bh[0] = Wo; bo.Of[0] = out;
    mma_gemm<0,1><<<dim3(16, 64), 256, GEMM_SMEM>>>(bo, Cc);
}

// round 12
// speedup vs baseline: 5.6701x; 1.0097x over previous
#include <cuda_runtime.h>
#include <cuda_bf16.h>
#include <cuda_fp16.h>
#include <cstdint>

// ---------------- problem constants ----------------
#define Bb 8
#define Tt 1024
#define Cc 2048
#define Hh 32
#define Nn 64
#define BT (Bb*Tt)                  // 8192
#define BTC ((size_t)BT*Cc)         // 16.7M
#define LORA_PAD 128
#define LN_EPS (1e-5f*64.0f)

// ---------------- scratch (device globals) ----------------
__device__ float g_r[BTC], g_k[BTC], g_v[BTC];
__device__ float g_wdec[BTC], g_asig[BTC], g_g[BTC], g_y[BTC];
// packed scan inputs: per (bt,h): 384 floats = [WB 128][KR 128][A2 64][V 64]
__device__ float g_pack[(size_t)BT*Hh*384];

// fp16 activations (A operands)
__device__ uint16_t g_xr[BTC], g_xw[BTC], g_xk[BTC], g_xv[BTC], g_xa[BTC], g_xg[BTC];
__device__ uint16_t g_yg[BTC];
// fp16 big weights (single term)
__device__ uint16_t g_Wr[Cc*Cc], g_Wk[Cc*Cc], g_Wv[Cc*Cc], g_Wo[Cc*Cc];
// LoRA weights (2-term split)
__device__ uint16_t g_l1h[4][LORA_PAD*Cc], g_l1l[4][LORA_PAD*Cc];
__device__ uint16_t g_l2h[4][Cc*LORA_PAD], g_l2l[4][Cc*LORA_PAD];
__device__ uint16_t g_ts[4][(size_t)BT*LORA_PAD];

// ---------------- helpers ----------------
__device__ __forceinline__ void h1store(float v, uint16_t* dst, size_t i) {
    reinterpret_cast<__half*>(dst)[i] = __float2half_rn(v);
}
__device__ __forceinline__ void h4store(float4 v, uint16_t* dst, size_t i) {
    __half2 a = __floats2half2_rn(v.x, v.y);
    __half2 b = __floats2half2_rn(v.z, v.w);
    *reinterpret_cast<uint2*>(dst + i) =
        make_uint2(*reinterpret_cast<uint32_t*>(&a), *reinterpret_cast<uint32_t*>(&b));
}
__device__ __forceinline__ void hsplit1(float v, uint16_t* hi, uint16_t* lo, size_t i) {
    __half h = __float2half_rn(v);
    float hf = __half2float(h);
    __half l = __float2half_rn(v - hf);
    reinterpret_cast<__half*>(hi)[i] = h;
    reinterpret_cast<__half*>(lo)[i] = l;
}

__device__ __forceinline__ uint32_t smem_u32(const void* p) {
    uint32_t a;
    asm("{ .reg .u64 t; cvta.to.shared.u64 t, %1; cvt.u32.u64 %0, t; }" : "=r"(a) : "l"(p));
    return a;
}
#define SWZ128(o) ((o) ^ (((o) >> 3) & 0x70))

__device__ __forceinline__ void cpa16(uint32_t daddr, const void* g)
{
    asm volatile("cp.async.cg.shared.global [%0], [%1], 16;"
                 :: "r"(daddr), "l"(__cvta_generic_to_global(g)) : "memory");
}

__device__ __forceinline__ void ldsm4(uint32_t& r0, uint32_t& r1, uint32_t& r2, uint32_t& r3,
                                      uint32_t addr)
{
    asm volatile("ldmatrix.sync.aligned.m8n8.x4.shared.b16 {%0,%1,%2,%3}, [%4];"
                 : "=r"(r0), "=r"(r1), "=r"(r2), "=r"(r3) : "r"(addr));
}

__device__ __forceinline__ void mma16816(float* c, const uint32_t* a, const uint32_t* b)
{
    asm volatile("mma.sync.aligned.m16n8k16.row.col.f32.f16.f16.f32 "
                 "{%0,%1,%2,%3}, {%4,%5,%6,%7}, {%8,%9}, {%0,%1,%2,%3};"
                 : "+f"(c[0]), "+f"(c[1]), "+f"(c[2]), "+f"(c[3])
                 : "r"(a[0]), "r"(a[1]), "r"(a[2]), "r"(a[3]), "r"(b[0]), "r"(b[1]));
}

// packed f32x2 (sm_100+)
typedef unsigned long long u64t;
__device__ __forceinline__ u64t pk2(float x, float y){ u64t d; asm("mov.b64 %0, {%1,%2};" : "=l"(d) : "f"(x), "f"(y)); return d; }
__device__ __forceinline__ void upk2(u64t d, float& x, float& y){ asm("mov.b64 {%0,%1}, %2;" : "=f"(x), "=f"(y) : "l"(d)); }
__device__ __forceinline__ u64t fma2(u64t a, u64t b, u64t c){ u64t d; asm("fma.rn.f32x2 %0, %1, %2, %3;" : "=l"(d) : "l"(a), "l"(b), "l"(c)); return d; }
__device__ __forceinline__ u64t mul2(u64t a, u64t b){ u64t d; asm("mul.rn.f32x2 %0, %1, %2;" : "=l"(d) : "l"(a), "l"(b)); return d; }

// ---------------- prep: mask + time-shift mixes -> fp16 ----------------
__global__ void prep_kernel(const float* __restrict__ x, const float* __restrict__ mask,
                            const float* __restrict__ mr, const float* __restrict__ mw,
                            const float* __restrict__ mk, const float* __restrict__ mv,
                            const float* __restrict__ ma, const float* __restrict__ mg)
{
    int bt = blockIdx.x;
    int c  = blockIdx.y * 1024 + threadIdx.x * 4;
    int t  = bt & (Tt - 1);
    float m  = mask[bt];
    float mp = (t > 0) ? mask[bt - 1] : 0.f;
    size_t idx = (size_t)bt * Cc + c;
    float4 xv = *reinterpret_cast<const float4*>(&x[idx]);
    float4 xp = make_float4(0.f, 0.f, 0.f, 0.f);
    if (t > 0) xp = *reinterpret_cast<const float4*>(&x[idx - Cc]);
    float4 xm = make_float4(xv.x*m, xv.y*m, xv.z*m, xv.w*m);
    float4 xx = make_float4(xp.x*mp - xm.x, xp.y*mp - xm.y, xp.z*mp - xm.z, xp.w*mp - xm.w);
#define MIX(MM, DD) { \
    float4 mm = *reinterpret_cast<const float4*>(&MM[c]); \
    float4 vv = make_float4(xm.x + xx.x*mm.x, xm.y + xx.y*mm.y, xm.z + xx.z*mm.z, xm.w + xx.w*mm.w); \
    h4store(vv, DD, idx); }
    MIX(mr, g_xr); MIX(mw, g_xw); MIX(mk, g_xk);
    MIX(mv, g_xv); MIX(ma, g_xa); MIX(mg, g_xg);
#undef MIX
}

__global__ void wconv_kernel(const float* __restrict__ Wr, const float* __restrict__ Wk,
                             const float* __restrict__ Wv, const float* __restrict__ Wo)
{
    size_t i = ((size_t)blockIdx.x * 256 + threadIdx.x) * 4;
    h4store(*reinterpret_cast<const float4*>(&Wr[i]), g_Wr, i);
    h4store(*reinterpret_cast<const float4*>(&Wk[i]), g_Wk, i);
    h4store(*reinterpret_cast<const float4*>(&Wv[i]), g_Wv, i);
    h4store(*reinterpret_cast<const float4*>(&Wo[i]), g_Wo, i);
}

struct LoraSrc { const float* s1[4]; const float* s2[4]; };
__constant__ int c_D[4] = {96, 96, 64, 128};

__global__ void lsplit_kernel(LoraSrc ls)
{
    int id = blockIdx.y;
    int i = blockIdx.x * 256 + threadIdx.x;
    if (id < 4) {
        int D = c_D[id];
        int n = i >> 11, kcol = i & 2047;
        float v = (n < D) ? ls.s1[id][(size_t)kcol * D + n] : 0.f;
        hsplit1(v, g_l1h[id], g_l1l[id], i);
    } else {
        int p = id - 4;
        int D = c_D[p];
        int n = i >> 7, kcol = i & 127;
        float v = (kcol < D) ? ls.s2[p][(size_t)kcol * Cc + n] : 0.f;
        hsplit1(v, g_l2h[p], g_l2l[p], i);
    }
}

// ---------------- GEMM ----------------
#define ATILE_B 16384
#define GEMM_SMEM 98304

struct GemmB {
    const uint16_t *Aa[4], *Bh[4], *Bl[4];
    uint16_t *Oh[4];
    float *Of[4];
    const float *bias[4];
    int etype[4];                   // MODE2: 0=wdec 1=asig 2=vupd 3=copy
    const float *vf, *mask;
};

template<int MODE, int NB>
__global__ __launch_bounds__(256, 2)
void mma_gemm(GemmB bp, int K)
{
    extern __shared__ char smem[];
    constexpr uint32_t STB = (uint32_t)(1 + NB) * ATILE_B;
    constexpr int NSTAGE = (NB == 1) ? 3 : 2;
    const uint32_t sb = smem_u32(smem);
    const int tid = threadIdx.x, lane = tid & 31, warp = tid >> 5;
    const int warpM = warp >> 1, warpN = warp & 1;
    const int m0 = blockIdx.y * 128;
    int n0, path;
    if (MODE == 1) { path = blockIdx.x;      n0 = 0; }
    else           { path = blockIdx.x >> 4; n0 = (blockIdx.x & 15) * 128; }
    const uint16_t* Aa  = bp.Aa[path];
    const uint16_t* Bhi = bp.Bh[path];
    const uint16_t* Blo = bp.Bl[path];
    const int kc = K >> 6;

    float acc[2][8][4];
#pragma unroll
    for (int mt = 0; mt < 2; mt++)
#pragma unroll
        for (int nt = 0; nt < 8; nt++)
#pragma unroll
            for (int e = 0; e < 4; e++) acc[mt][nt][e] = 0.f;

    auto load_chunk = [&](int c) {
        const uint32_t stb = sb + (uint32_t)(c % NSTAGE) * STB;
        const int k0 = c << 6;
#pragma unroll
        for (int a3 = 0; a3 < 1 + NB; a3++) {
            const uint16_t* src = (a3 == 0) ? Aa : ((a3 == 1) ? Bhi : Blo);
            const int rb = (a3 == 0) ? m0 : n0;
            const uint32_t ab = stb + a3 * ATILE_B;
#pragma unroll
            for (int jj = 0; jj < 4; jj++) {
                int T = tid + jj * 256;
                int row = T >> 3, seg = T & 7;
                cpa16(ab + SWZ128(row * 128 + seg * 16),
                      src + (size_t)(rb + row) * K + k0 + seg * 8);
            }
        }
    };

    if (NB == 1) {
        load_chunk(0);
        asm volatile("cp.async.commit_group;" ::: "memory");
        if (1 < kc) load_chunk(1);
        asm volatile("cp.async.commit_group;" ::: "memory");
    } else {
        load_chunk(0);
        asm volatile("cp.async.commit_group;" ::: "memory");
    }

    const int aRowOff = warpM * 32 + (lane & 15);
    const int aKbase  = (lane >> 4) << 4;
    const int bRowOff = warpN * 64 + (lane & 7) + ((lane >> 1) & 8);
    const int bKbase  = ((lane >> 3) & 1) * 16;

    for (int c = 0; c < kc; c++) {
        if (NB == 1) {
            asm volatile("cp.async.wait_group 1;" ::: "memory");
            __syncthreads();
            if (c + 2 < kc) load_chunk(c + 2);
            asm volatile("cp.async.commit_group;" ::: "memory");
        } else {
            __syncthreads();
            if (c + 1 < kc) load_chunk(c + 1);
            asm volatile("cp.async.commit_group;" ::: "memory");
            asm volatile("cp.async.wait_group 1;" ::: "memory");
            __syncthreads();
        }

        const uint32_t stb = sb + (uint32_t)(c % NSTAGE) * STB;
        const uint32_t sA = stb, sBh = stb + ATILE_B, sBl = stb + 2u * ATILE_B;
#pragma unroll
        for (int s = 0; s < 4; s++) {
            const int akb = s * 32 + aKbase;
            const int bkb = s * 32 + bKbase;
            uint32_t a[2][4];
#pragma unroll
            for (int mt = 0; mt < 2; mt++) {
                int ro = (aRowOff + mt * 16) * 128;
                ldsm4(a[mt][0], a[mt][1], a[mt][2], a[mt][3], sA + SWZ128(ro + akb));
            }
            uint32_t b[8][2];
#pragma unroll
            for (int p = 0; p < 4; p++) {
                int ro = (bRowOff + p * 16) * 128;
                uint32_t r0, r1, r2, r3;
                ldsm4(r0, r1, r2, r3, sBh + SWZ128(ro + bkb));
                b[p*2][0] = r0; b[p*2][1] = r1; b[p*2+1][0] = r2; b[p*2+1][1] = r3;
            }
#pragma unroll
            for (int mt = 0; mt < 2; mt++)
#pragma unroll
                for (int nt = 0; nt < 8; nt++)
                    mma16816(acc[mt][nt], a[mt], b[nt]);
            if (NB == 2) {
#pragma unroll
                for (int p = 0; p < 4; p++) {
                    int ro = (bRowOff + p * 16) * 128;
                    uint32_t r0, r1, r2, r3;
                    ldsm4(r0, r1, r2, r3, sBl + SWZ128(ro + bkb));
                    b[p*2][0] = r0; b[p*2][1] = r1; b[p*2+1][0] = r2; b[p*2+1][1] = r3;
                }
#pragma unroll
                for (int mt = 0; mt < 2; mt++)
#pragma unroll
                    for (int nt = 0; nt < 8; nt++)
                        mma16816(acc[mt][nt], a[mt], b[nt]);
            }
        }
    }

    // epilogue
    const int row0 = m0 + warpM * 32 + (lane >> 2);
    const int col0 = n0 + warpN * 64 + (lane & 3) * 2;
    const int et = (MODE == 2) ? bp.etype[path] : 0;
#pragma unroll
    for (int mt = 0; mt < 2; mt++) {
#pragma unroll
        for (int nt = 0; nt < 8; nt++) {
            int r1 = row0 + mt * 16;
            int c1 = col0 + nt * 8;
            float v0 = acc[mt][nt][0], v1 = acc[mt][nt][1];
            float v2 = acc[mt][nt][2], v3 = acc[mt][nt][3];
            if (MODE == 0) {
                float* Cf = bp.Of[path];
                *reinterpret_cast<float2*>(&Cf[(size_t)r1 * Cc + c1]) = make_float2(v0, v1);
                *reinterpret_cast<float2*>(&Cf[(size_t)(r1 + 8) * Cc + c1]) = make_float2(v2, v3);
            } else if (MODE == 1) {
                if (path == 0) { v0 = tanhf(v0); v1 = tanhf(v1); v2 = tanhf(v2); v3 = tanhf(v3); }
                else if (path == 3) {
                    v0 = 1.f/(1.f+expf(-v0)); v1 = 1.f/(1.f+expf(-v1));
                    v2 = 1.f/(1.f+expf(-v2)); v3 = 1.f/(1.f+expf(-v3));
                }
                uint16_t* oh = bp.Oh[path];
                h1store(v0, oh, (size_t)r1 * LORA_PAD + c1);
                h1store(v1, oh, (size_t)r1 * LORA_PAD + c1 + 1);
                h1store(v2, oh, (size_t)(r1 + 8) * LORA_PAD + c1);
                h1store(v3, oh, (size_t)(r1 + 8) * LORA_PAD + c1 + 1);
            } else {
                float* Of = bp.Of[path];
                const float* bias = bp.bias[path];
                auto ep = [&](float z, int rr_, int cc_) {
                    size_t idx = (size_t)rr_ * Cc + cc_;
                    if (et == 0) {
                        float zz = bias[cc_] + z;
                        float nz = -zz;
                        float sp = (nz > 20.f) ? nz : log1pf(expf(nz));
                        Of[idx] = expf(-expf(-sp - 0.5f));
                    } else if (et == 1) {
                        Of[idx] = 1.f / (1.f + expf(-(bias[cc_] + z)));
                    } else if (et == 2) {
                        float s = 1.f / (1.f + expf(-(bias[cc_] + z)));
                        float vv = Of[idx];
                        Of[idx] = (vv + (bp.vf[idx] - vv) * s) * bp.mask[rr_];
                    } else {
                        Of[idx] = z;
                    }
                };
                ep(v0, r1, c1); ep(v1, r1, c1 + 1);
                ep(v2, r1 + 8, c1); ep(v3, r1 + 8, c1 + 1);
            }
        }
    }
}

// ---------------- pack: kk-normalize + k-rescale + scan-input packing ----------
__global__ void pack_kernel(const float* __restrict__ kkp, const float* __restrict__ kap,
                            const float* __restrict__ asig, const float* __restrict__ wd,
                            const float* __restrict__ r, const float* __restrict__ v,
                            float* __restrict__ k, float* __restrict__ pack)
{
    int gid = blockIdx.x * 8 + (threadIdx.x >> 5);   // bt*Hh + h
    int l = threadIdx.x & 31;
    int h = gid & (Hh - 1);
    size_t bt = (size_t)gid >> 5;
    size_t base = bt * Cc + (size_t)h * Nn + 2 * l;
    int c0 = h * Nn + 2 * l;
    float2 kv = *reinterpret_cast<const float2*>(&k[base]);
    float2 kp = *reinterpret_cast<const float2*>(&kkp[c0]);
    float kk0 = kv.x * kp.x, kk1 = kv.y * kp.y;
    float ss = kk0 * kk0 + kk1 * kk1;
#pragma unroll
    for (int o = 16; o > 0; o >>= 1) ss += __shfl_xor_sync(0xffffffffu, ss, o);
    float inv = 1.f / fmaxf(sqrtf(ss), 1e-12f);
    kk0 *= inv; kk1 *= inv;
    float2 as2 = *reinterpret_cast<const float2*>(&asig[base]);
    float2 ka2 = *reinterpret_cast<const float2*>(&kap[c0]);
    float kn0 = kv.x * (1.f + (as2.x - 1.f) * ka2.x);
    float kn1 = kv.y * (1.f + (as2.y - 1.f) * ka2.y);
    *reinterpret_cast<float2*>(&k[base]) = make_float2(kn0, kn1);
    float2 w2 = *reinterpret_cast<const float2*>(&wd[base]);
    float2 r2 = *reinterpret_cast<const float2*>(&r[base]);
    float2 v2 = *reinterpret_cast<const float2*>(&v[base]);
    float* pb = pack + (size_t)gid * 384;
    *reinterpret_cast<float4*>(&pb[l * 4])       = make_float4(w2.x, w2.y, kk0 * as2.x, kk1 * as2.y);
    *reinterpret_cast<float4*>(&pb[128 + l * 4]) = make_float4(kn0, kn1, r2.x, r2.y);
    *reinterpret_cast<float2*>(&pb[256 + l * 2]) = make_float2(-kk0, -kk1);
    *reinterpret_cast<float2*>(&pb[320 + l * 2]) = v2;
}

// ---------------- RWKV-7 scan: cp.async depth-8 pipeline -----------------------
__global__ __launch_bounds__(128)
void scan_kernel(const float* __restrict__ pack, float* __restrict__ y)
{
    int bh = blockIdx.x;
    int b = bh >> 5, h = bh & (Hh - 1);
    int tid = threadIdx.x;
    int j = tid >> 1, half = tid & 1;
    __shared__ __align__(16) char buf[8][1536];   // 12KB, depth-8
    const char* src = reinterpret_cast<const char*>(
        pack + ((size_t)b * Tt * Hh + h) * 384);
    const size_t stepB = (size_t)Hh * 1536;
    const uint32_t sbase = smem_u32(buf);
    u64t S[16];
#pragma unroll
    for (int i = 0; i < 16; i++) S[i] = 0ull;

#pragma unroll
    for (int pt = 0; pt < 7; pt++) {
        if (tid < 96) cpa16(sbase + pt * 1536 + tid * 16, src + pt * stepB + tid * 16);
        asm volatile("cp.async.commit_group;" ::: "memory");
    }

    size_t ybase = ((size_t)b * Tt) * Cc + (size_t)h * Nn + j;
    for (int t = 0; t < Tt; t++) {
        asm volatile("cp.async.wait_group 6;" ::: "memory");
        __syncthreads();
        if (t + 7 < Tt && tid < 96)
            cpa16(sbase + ((t + 7) & 7) * 1536 + tid * 16, src + (t + 7) * stepB + tid * 16);
        asm volatile("cp.async.commit_group;" ::: "memory");

        const float* W = reinterpret_cast<const float*>(buf[t & 7]);
        float vj = W[320 + j];
        u64t q0 = 0ull, q1 = 0ull, q2 = 0ull, q3 = 0ull;
#pragma unroll
        for (int ii = 0; ii < 16; ii += 4) {
            q0 = fma2(S[ii + 0], *reinterpret_cast<const u64t*>(W + 256 + (2*(ii+0)+half)*2), q0);
            q1 = fma2(S[ii + 1], *reinterpret_cast<const u64t*>(W + 256 + (2*(ii+1)+half)*2), q1);
            q2 = fma2(S[ii + 2], *reinterpret_cast<const u64t*>(W + 256 + (2*(ii+2)+half)*2), q2);
            q3 = fma2(S[ii + 3], *reinterpret_cast<const u64t*>(W + 256 + (2*(ii+3)+half)*2), q3);
        }
        float ax, ay, bx, by, cx, cy, dx, dy;
        upk2(q0, ax, ay); upk2(q1, bx, by); upk2(q2, cx, cy); upk2(q3, dx, dy);
        float sacc = ((ax + ay) + (bx + by)) + ((cx + cy) + (dx + dy));
        sacc += __shfl_xor_sync(0xffffffffu, sacc, 1);
        u64t sacc2 = pk2(sacc, sacc);
        u64t vj2 = pk2(vj, vj);
        u64t ya = 0ull, yb = 0ull;
#pragma unroll
        for (int ii = 0; ii < 16; ii++) {
            int p = 2 * ii + half;
            float4 wb = *reinterpret_cast<const float4*>(W + p * 4);
            float4 kr = *reinterpret_cast<const float4*>(W + 128 + p * 4);
            u64t s = fma2(S[ii], pk2(wb.x, wb.y),
                          fma2(sacc2, pk2(wb.z, wb.w), mul2(vj2, pk2(kr.x, kr.y))));
            S[ii] = s;
            if (ii & 1) yb = fma2(s, pk2(kr.z, kr.w), yb);
            else        ya = fma2(s, pk2(kr.z, kr.w), ya);
        }
        float y0x, y0y, y1x, y1y;
        upk2(ya, y0x, y0y); upk2(yb, y1x, y1y);
        float yv = (y0x + y0y) + (y1x + y1y);
        yv += __shfl_xor_sync(0xffffffffu, yv, 1);
        if (half == 0) y[ybase + (size_t)t * Cc] = yv;
    }
}

// ---------------- groupnorm + rk*v + gate -> fp16 ----------------
__global__ void post_kernel(const float* __restrict__ y, const float* __restrict__ r,
                            const float* __restrict__ k, const float* __restrict__ v,
                            const float* __restrict__ g, const float* __restrict__ r_k,
                            const float* __restrict__ ln_w, const float* __restrict__ ln_b,
                            uint16_t* __restrict__ oh)
{
    int gid = blockIdx.x * 8 + (threadIdx.x >> 5);
    int lane = threadIdx.x & 31;
    int h = gid % Hh;
    size_t bt = gid / Hh;
    size_t base = bt * Cc + (size_t)h * Nn;
    int c0 = h * Nn + lane, c1 = c0 + 32;
    float y0 = y[base + lane], y1 = y[base + lane + 32];
    float sum = y0 + y1;
#pragma unroll
    for (int o = 16; o > 0; o >>= 1) sum += __shfl_xor_sync(0xffffffffu, sum, o);
    float mean = sum * (1.f / 64.f);
    float d0 = y0 - mean, d1 = y1 - mean;
    float var = d0 * d0 + d1 * d1;
#pragma unroll
    for (int o = 16; o > 0; o >>= 1) var += __shfl_xor_sync(0xffffffffu, var, o);
    var *= (1.f / 64.f);
    float inv = rsqrtf(var + LN_EPS);
    float yn0 = d0 * inv * ln_w[c0] + ln_b[c0];
    float yn1 = d1 * inv * ln_w[c1] + ln_b[c1];
    float rk = r[base + lane] * k[base + lane] * r_k[c0]
             + r[base + lane + 32] * k[base + lane + 32] * r_k[c1];
#pragma unroll
    for (int o = 16; o > 0; o >>= 1) rk += __shfl_xor_sync(0xffffffffu, rk, o);
    float o0 = (yn0 + rk * v[base + lane]) * g[base + lane];
    float o1 = (yn1 + rk * v[base + lane + 32]) * g[base + lane + 32];
    h1store(o0, oh, base + lane);
    h1store(o1, oh, base + lane + 32);
}

// ---------------- launch ----------------
#define GETSYM(var, sym) do { void* _p; cudaGetSymbolAddress(&_p, sym); var = (decltype(var))_p; } while (0)

extern "C" void kernel_launch(void* const* d_in, const int* in_sizes, int n_in,
                              void* d_out, int out_size)
{
    const float* x       = (const float*)d_in[0];
    const float* mask    = (const float*)d_in[1];
    const float* v_first = (const float*)d_in[2];
    const float* x_r = (const float*)d_in[3];
    const float* x_w = (const float*)d_in[4];
    const float* x_k = (const float*)d_in[5];
    const float* x_v = (const float*)d_in[6];
    const float* x_a = (const float*)d_in[7];
    const float* x_g = (const float*)d_in[8];
    const float* w0 = (const float*)d_in[9];
    const float* w1 = (const float*)d_in[10];
    const float* w2 = (const float*)d_in[11];
    const float* a0 = (const float*)d_in[12];
    const float* a1 = (const float*)d_in[13];
    const float* a2 = (const float*)d_in[14];
    const float* v0 = (const float*)d_in[15];
    const float* v1 = (const float*)d_in[16];
    const float* v2 = (const float*)d_in[17];
    const float* g1 = (const float*)d_in[18];
    const float* g2 = (const float*)d_in[19];
    const float* k_k = (const float*)d_in[20];
    const float* k_a = (const float*)d_in[21];
    const float* r_k = (const float*)d_in[22];
    const float* W_r = (const float*)d_in[23];
    const float* W_k = (const float*)d_in[24];
    const float* W_v = (const float*)d_in[25];
    const float* W_o = (const float*)d_in[26];
    const float* ln_w = (const float*)d_in[27];
    const float* ln_b = (const float*)d_in[28];
    float* out = (float*)d_out;

    float *rr, *kb, *vb, *wd, *as, *gg, *yb, *pk;
    GETSYM(rr, g_r); GETSYM(kb, g_k); GETSYM(vb, g_v);
    GETSYM(wd, g_wdec); GETSYM(as, g_asig); GETSYM(gg, g_g);
    GETSYM(yb, g_y); GETSYM(pk, g_pack);
    uint16_t *xr,*xw,*xk,*xv,*xa,*xg,*yg;
    GETSYM(xr, g_xr); GETSYM(xw, g_xw); GETSYM(xk, g_xk);
    GETSYM(xv, g_xv); GETSYM(xa, g_xa); GETSYM(xg, g_xg);
    GETSYM(yg, g_yg);
    uint16_t *Wr,*Wk,*Wv,*Wo;
    GETSYM(Wr, g_Wr); GETSYM(Wk, g_Wk); GETSYM(Wv, g_Wv); GETSYM(Wo, g_Wo);
    uint16_t *l1h, *l1l, *l2h, *l2l, *ts;
    GETSYM(l1h, g_l1h); GETSYM(l1l, g_l1l); GETSYM(l2h, g_l2h); GETSYM(l2l, g_l2l);
    GETSYM(ts, g_ts);

    cudaFuncSetAttribute(mma_gemm<0,1>, cudaFuncAttributeMaxDynamicSharedMemorySize, GEMM_SMEM);
    cudaFuncSetAttribute(mma_gemm<1,2>, cudaFuncAttributeMaxDynamicSharedMemorySize, GEMM_SMEM);
    cudaFuncSetAttribute(mma_gemm<2,2>, cudaFuncAttributeMaxDynamicSharedMemorySize, GEMM_SMEM);

    static cudaStream_t s1 = nullptr;
    static cudaEvent_t ePrep = nullptr, eW = nullptr, eL1 = nullptr, eJoin = nullptr, eStart = nullptr;
    if (s1 == nullptr) {
        cudaStreamCreateWithFlags(&s1, cudaStreamNonBlocking);
        cudaEventCreateWithFlags(&ePrep, cudaEventDisableTiming);
        cudaEventCreateWithFlags(&eW, cudaEventDisableTiming);
        cudaEventCreateWithFlags(&eL1, cudaEventDisableTiming);
        cudaEventCreateWithFlags(&eJoin, cudaEventDisableTiming);
        cudaEventCreateWithFlags(&eStart, cudaEventDisableTiming);
    }

    // fork side stream at the very start
    cudaEventRecord(eStart, 0);
    cudaStreamWaitEvent(s1, eStart, 0);

    // main: prep (activations)
    prep_kernel<<<dim3(BT, 2), 256>>>(x, mask, x_r, x_w, x_k, x_v, x_a, x_g);
    cudaEventRecord(ePrep, 0);

    // side: weight conversions + v_first copy (independent of prep)
    if ((size_t)out_size >= 2 * BTC) {
        cudaMemcpyAsync(out + BTC, v_first, BTC * sizeof(float),
                        cudaMemcpyDeviceToDevice, s1);
    }
    wconv_kernel<<<(Cc * Cc) / 1024, 256, 0, s1>>>(W_r, W_k, W_v, W_o);
    LoraSrc ls;
    ls.s1[0] = w1; ls.s1[1] = a1; ls.s1[2] = v1; ls.s1[3] = g1;
    ls.s2[0] = w2; ls.s2[1] = a2; ls.s2[2] = v2; ls.s2[3] = g2;
    lsplit_kernel<<<dim3(1024, 8), 256, 0, s1>>>(ls);
    cudaEventRecord(eW, s1);

    const size_t L1 = (size_t)LORA_PAD * Cc, L2 = (size_t)Cc * LORA_PAD;
    const size_t TS = (size_t)BT * LORA_PAD;

    // side: LoRA stage1 (needs prep outputs) + v-independent stage2 paths
    cudaStreamWaitEvent(s1, ePrep, 0);
    GemmB b1 = {};
    b1.Aa[0] = xw; b1.Aa[1] = xa; b1.Aa[2] = xv; b1.Aa[3] = xg;
    for (int p = 0; p < 4; p++) {
        b1.Bh[p] = l1h + p * L1; b1.Bl[p] = l1l + p * L1;
        b1.Oh[p] = ts + p * TS;
    }
    mma_gemm<1,2><<<dim3(4, 64), 256, GEMM_SMEM, s1>>>(b1, Cc);
    cudaEventRecord(eL1, s1);

    GemmB b2a = {};
    b2a.Aa[0] = ts + 0 * TS; b2a.Bh[0] = l2h + 0 * L2; b2a.Bl[0] = l2l + 0 * L2;
    b2a.Of[0] = wd; b2a.bias[0] = w0; b2a.etype[0] = 0;
    b2a.Aa[1] = ts + 1 * TS; b2a.Bh[1] = l2h + 1 * L2; b2a.Bl[1] = l2l + 1 * L2;
    b2a.Of[1] = as; b2a.bias[1] = a0; b2a.etype[1] = 1;
    b2a.Aa[2] = ts + 3 * TS; b2a.Bh[2] = l2h + 3 * L2; b2a.Bl[2] = l2l + 3 * L2;
    b2a.Of[2] = gg; b2a.bias[2] = w0; b2a.etype[2] = 3;
    mma_gemm<2,2><<<dim3(48, 64), 256, GEMM_SMEM, s1>>>(b2a, LORA_PAD);
    cudaEventRecord(eJoin, s1);

    // main: batched r,k,v projections (needs weights from side stream)
    cudaStreamWaitEvent(0, eW, 0);
    GemmB b0 = {};
    b0.Aa[0] = xr; b0.Bh[0] = Wr; b0.Of[0] = rr;
    b0.Aa[1] = xk; b0.Bh[1] = Wk; b0.Of[1] = kb;
    b0.Aa[2] = xv; b0.Bh[2] = Wv; b0.Of[2] = vb;
    mma_gemm<0,1><<<dim3(48, 64), 256, GEMM_SMEM>>>(b0, Cc);

    // stage2 v path: needs only lora1 output + vb (overlaps stage2a on side)
    cudaStreamWaitEvent(0, eL1, 0);
    GemmB b2b = {};
    b2b.Aa[0] = ts + 2 * TS; b2b.Bh[0] = l2h + 2 * L2; b2b.Bl[0] = l2l + 2 * L2;
    b2b.Of[0] = vb; b2b.bias[0] = v0; b2b.etype[0] = 2;
    b2b.vf = v_first; b2b.mask = mask;
    mma_gemm<2,2><<<dim3(16, 64), 256, GEMM_SMEM>>>(b2b, LORA_PAD);

    // pack needs wd/as from stage2a
    cudaStreamWaitEvent(0, eJoin, 0);
    pack_kernel<<<(BT * Hh) / 8, 256>>>(k_k, k_a, as, wd, rr, vb, kb, pk);
    scan_kernel<<<Bb * Hh, 128>>>(pk, yb);
    post_kernel<<<(BT * Hh) / 8, 256>>>(yb, rr, kb, vb, gg, r_k, ln_w, ln_b, yg);

    // output projection
    GemmB bo = {};
    bo.Aa[0] = yg; bo.Bh[0] = Wo; bo.Of[0] = out;
    mma_gemm<0,1><<<dim3(16, 64), 256, GEMM_SMEM>>>(bo, Cc);
}